// round 6
// baseline (speedup 1.0000x reference)
#include <cuda_runtime.h>
#include <cuda_bf16.h>
#include <math.h>
#include <stdint.h>

// ---------------- model constants ----------------
#define BATCH  8
#define SEQ    512
#define DMODEL 512
#define NHEAD  8
#define HEADD  64
#define FFDIM  2048
#define NLAYER 6
#define VOCAB  50257
#define VPAD   50432                  // 197*256
#define BS     (BATCH*SEQ)
#define QKVS   1536
static const long long NLOG = (long long)BS * VOCAB;

// converted-weight layout (bf16), per layer:
// [q_hi k_hi v_hi o_hi][q_lo k_lo v_lo o_lo][w1_hi w1_lo][w2_hi w2_lo]
#define DDSZ   (DMODEL*DMODEL)
#define DFSZ   (DMODEL*FFDIM)
#define QKVO_TOT (8*DDSZ)
#define WL_STRIDE (QKVO_TOT + 2*DFSZ + 2*DFSZ)

// ---------------- device scratch ----------------
__device__ float g_h[BS * DMODEL];
__device__ float g_rowloss[BS];
__device__ float g_bqkv[NLAYER * QKVS];
__device__ float g_logits_scratch[(size_t)BS * VOCAB];
__device__ __nv_bfloat16 g_xnh[BS * DMODEL];
__device__ __nv_bfloat16 g_xnl[BS * DMODEL];
__device__ __nv_bfloat16 g_qkvh[BS * QKVS];
__device__ __nv_bfloat16 g_qkvl[BS * QKVS];
__device__ __nv_bfloat16 g_ctxh[BS * DMODEL];
__device__ __nv_bfloat16 g_ctxl[BS * DMODEL];
__device__ __nv_bfloat16 g_ffh[BS * FFDIM];
__device__ __nv_bfloat16 g_ffl[BS * FFDIM];
__device__ __nv_bfloat16 g_wbuf[(size_t)WL_STRIDE * NLAYER];
__device__ __nv_bfloat16 g_emb[2 * (size_t)VPAD * DMODEL];

// ================= PTX helpers =================
__device__ __forceinline__ uint32_t smem_to_u32(const void* smem_ptr) {
    uint32_t addr;
    asm("{ .reg .u64 tmp; cvta.to.shared.u64 tmp, %1; cvt.u32.u64 %0, tmp; }"
        : "=r"(addr) : "l"(smem_ptr));
    return addr;
}
__device__ __forceinline__ void cp16(uint32_t d, const void* s, int sz) {
    asm volatile("cp.async.cg.shared.global [%0], [%1], 16, %2;\n"
                 :: "r"(d), "l"(s), "r"(sz) : "memory");
}
__device__ __forceinline__ void cp_commit() {
    asm volatile("cp.async.commit_group;\n" ::: "memory");
}
__device__ __forceinline__ void cp_wait0() {
    asm volatile("cp.async.wait_group 0;\n" ::: "memory");
}
__device__ __forceinline__ void cp_wait1() {
    asm volatile("cp.async.wait_group 1;\n" ::: "memory");
}
#define LDSM4(r, addr) \
    asm volatile("ldmatrix.sync.aligned.m8n8.x4.shared.b16 {%0,%1,%2,%3}, [%4];" \
        : "=r"((r)[0]), "=r"((r)[1]), "=r"((r)[2]), "=r"((r)[3]) : "r"(addr))
#define MMA16816(c, a, b0, b1) \
    asm volatile("mma.sync.aligned.m16n8k16.row.col.f32.bf16.bf16.f32 " \
        "{%0,%1,%2,%3}, {%4,%5,%6,%7}, {%8,%9}, {%0,%1,%2,%3};" \
        : "+f"((c)[0]), "+f"((c)[1]), "+f"((c)[2]), "+f"((c)[3]) \
        : "r"((a)[0]), "r"((a)[1]), "r"((a)[2]), "r"((a)[3]), "r"(b0), "r"(b1))

__device__ __forceinline__ void split4(float4 v, uint2& hi, uint2& lo) {
    __nv_bfloat162 h01 = __floats2bfloat162_rn(v.x, v.y);
    __nv_bfloat162 h23 = __floats2bfloat162_rn(v.z, v.w);
    float2 b01 = __bfloat1622float2(h01);
    float2 b23 = __bfloat1622float2(h23);
    __nv_bfloat162 l01 = __floats2bfloat162_rn(v.x - b01.x, v.y - b01.y);
    __nv_bfloat162 l23 = __floats2bfloat162_rn(v.z - b23.x, v.w - b23.y);
    hi.x = *reinterpret_cast<uint32_t*>(&h01);
    hi.y = *reinterpret_cast<uint32_t*>(&h23);
    lo.x = *reinterpret_cast<uint32_t*>(&l01);
    lo.y = *reinterpret_cast<uint32_t*>(&l23);
}

// epilogue: 0=bias->f32, 1=bias+res->f32, 2=bias+gelu->bf16 split, 3=plain f32, 4=bias->bf16 split
template <int EPI>
__device__ __forceinline__ void emit_one(float x, size_t off, int col,
        const float* __restrict__ bias, const float* __restrict__ res,
        float* __restrict__ C, __nv_bfloat16* __restrict__ Chi, __nv_bfloat16* __restrict__ Clo) {
    if (EPI == 0 || EPI == 1 || EPI == 2 || EPI == 4) x += __ldg(bias + col);
    if (EPI == 2) x = 0.5f * x * (1.0f + erff(x * 0.70710678118654752440f));
    if (EPI == 1) x += res[off];
    if (EPI == 2 || EPI == 4) {
        __nv_bfloat16 h = __float2bfloat16(x);
        Chi[off] = h;
        Clo[off] = __float2bfloat16(x - __bfloat162float(h));
    } else {
        C[off] = x;
    }
}

// ================= narrow GEMM (CTA 128x128) — used for N=512 =================
#define TB 16384
#define STAGE_BYTES (4*TB)
#define SMEM_OFF 1024
#define GEMM_SMEM (SMEM_OFF + 2*STAGE_BYTES)

__device__ __forceinline__ void copy_stage(uint32_t st,
        const __nv_bfloat16* __restrict__ Ahi, const __nv_bfloat16* __restrict__ Alo,
        const __nv_bfloat16* __restrict__ Bhi, const __nv_bfloat16* __restrict__ Blo,
        int bm, int bn, int k0, int K, int N, int tid) {
    #pragma unroll
    for (int it = 0; it < 4; it++) {
        int idx = tid + it * 256;
        int row = idx >> 3, c = idx & 7;
        uint32_t d = st + row * 128 + ((c ^ (row & 7)) << 4);
        size_t so = (size_t)(bm + row) * K + k0 + c * 8;
        cp16(d, Ahi + so, 16);
        cp16(d + TB, Alo + so, 16);
    }
    #pragma unroll
    for (int it = 0; it < 4; it++) {
        int idx = tid + it * 256;
        int row = idx >> 3, c = idx & 7;
        int n = bn + row;
        int sz = (n < N) ? 16 : 0;
        uint32_t d = st + 2 * TB + row * 128 + ((c ^ (row & 7)) << 4);
        size_t so = (size_t)n * K + k0 + c * 8;
        cp16(d, Bhi + so, sz);
        cp16(d + TB, Blo + so, sz);
    }
}

template <int EPI>
__global__ void __launch_bounds__(256, 1)
gemm_bf(const __nv_bfloat16* __restrict__ Ahi, const __nv_bfloat16* __restrict__ Alo,
        const __nv_bfloat16* __restrict__ Bhi, const __nv_bfloat16* __restrict__ Blo,
        const float* __restrict__ bias, const float* __restrict__ res,
        float* __restrict__ C, __nv_bfloat16* __restrict__ Chi, __nv_bfloat16* __restrict__ Clo,
        int M, int N, int K) {
    extern __shared__ char smem[];
    const int tid = threadIdx.x;
    const int bm = blockIdx.x * 128;
    const int bn = blockIdx.y * 128;
    const int nc = K >> 6;

    const uint32_t tiles = smem_to_u32(smem) + SMEM_OFF;
    const int lane = tid & 31;
    const int wid = tid >> 5;
    const int wm = (wid & 3) << 5;
    const int wn = (wid >> 2) << 6;
    const int mi = lane >> 3;
    const int lrow = lane & 7;

    float acc[2][8][4];
    #pragma unroll
    for (int i = 0; i < 2; i++)
        #pragma unroll
        for (int j = 0; j < 8; j++)
            #pragma unroll
            for (int t = 0; t < 4; t++) acc[i][j][t] = 0.0f;

    copy_stage(tiles, Ahi, Alo, Bhi, Blo, bm, bn, 0, K, N, tid);
    cp_commit();

    for (int c = 0; c < nc; c++) {
        if (c + 1 < nc) {
            copy_stage(tiles + ((c + 1) & 1) * STAGE_BYTES, Ahi, Alo, Bhi, Blo,
                       bm, bn, (c + 1) << 6, K, N, tid);
            cp_commit();
            cp_wait1();
        } else {
            cp_wait0();
        }
        __syncthreads();

        const uint32_t st = tiles + (c & 1) * STAGE_BYTES;
        #pragma unroll
        for (int s = 0; s < 4; s++) {
            const int cb = (s << 5) + ((mi >> 1) << 4);
            uint32_t ahi[2][4], alo[2][4], bhi[4][4], blo[4][4];
            #pragma unroll
            for (int i = 0; i < 2; i++) {
                int r = wm + (i << 4) + ((mi & 1) << 3) + lrow;
                uint32_t a = st + r * 128 + (cb ^ ((r & 7) << 4));
                LDSM4(ahi[i], a);
                LDSM4(alo[i], a + TB);
            }
            #pragma unroll
            for (int j2 = 0; j2 < 4; j2++) {
                int r = wn + (j2 << 4) + ((mi & 1) << 3) + lrow;
                uint32_t a = st + 2 * TB + r * 128 + (cb ^ ((r & 7) << 4));
                LDSM4(bhi[j2], a);
                LDSM4(blo[j2], a + TB);
            }
            #pragma unroll
            for (int i = 0; i < 2; i++)
                #pragma unroll
                for (int j2 = 0; j2 < 4; j2++) {
                    MMA16816(acc[i][2 * j2],     ahi[i], bhi[j2][0], bhi[j2][2]);
                    MMA16816(acc[i][2 * j2 + 1], ahi[i], bhi[j2][1], bhi[j2][3]);
                }
            #pragma unroll
            for (int i = 0; i < 2; i++)
                #pragma unroll
                for (int j2 = 0; j2 < 4; j2++) {
                    MMA16816(acc[i][2 * j2],     alo[i], bhi[j2][0], bhi[j2][2]);
                    MMA16816(acc[i][2 * j2 + 1], alo[i], bhi[j2][1], bhi[j2][3]);
                }
            #pragma unroll
            for (int i = 0; i < 2; i++)
                #pragma unroll
                for (int j2 = 0; j2 < 4; j2++) {
                    MMA16816(acc[i][2 * j2],     ahi[i], blo[j2][0], blo[j2][2]);
                    MMA16816(acc[i][2 * j2 + 1], ahi[i], blo[j2][1], blo[j2][3]);
                }
        }
        __syncthreads();
    }

    #pragma unroll
    for (int i = 0; i < 2; i++) {
        int row = bm + wm + (i << 4) + (lane >> 2);
        size_t base = (size_t)row * N;
        size_t base8 = base + (size_t)8 * N;
        #pragma unroll
        for (int j = 0; j < 8; j++) {
            int col = bn + wn + (j << 3) + ((lane & 3) << 1);
            if (col < N)     emit_one<EPI>(acc[i][j][0], base + col, col, bias, res, C, Chi, Clo);
            if (col + 1 < N) emit_one<EPI>(acc[i][j][1], base + col + 1, col + 1, bias, res, C, Chi, Clo);
            if (col < N)     emit_one<EPI>(acc[i][j][2], base8 + col, col, bias, res, C, Chi, Clo);
            if (col + 1 < N) emit_one<EPI>(acc[i][j][3], base8 + col + 1, col + 1, bias, res, C, Chi, Clo);
        }
    }
}

// ================= wide GEMM (CTA 128x256, warp 64x64) =================
// stage layout: [Ahi 16K][Alo 16K][Bhi 32K][Blo 32K] = 96KB, 2 stages
#define WSTAGE 98304
#define GEMM_SMEM_W (SMEM_OFF + 2*WSTAGE)   // 197632

__device__ __forceinline__ void copy_stage_w(uint32_t st,
        const __nv_bfloat16* __restrict__ Ahi, const __nv_bfloat16* __restrict__ Alo,
        const __nv_bfloat16* __restrict__ Bhi, const __nv_bfloat16* __restrict__ Blo,
        int bm, int bn, int k0, int K, int N, int tid) {
    #pragma unroll
    for (int it = 0; it < 4; it++) {
        int idx = tid + it * 256;
        int row = idx >> 3, c = idx & 7;
        uint32_t d = st + row * 128 + ((c ^ (row & 7)) << 4);
        size_t so = (size_t)(bm + row) * K + k0 + c * 8;
        cp16(d, Ahi + so, 16);
        cp16(d + 16384, Alo + so, 16);
    }
    #pragma unroll
    for (int it = 0; it < 8; it++) {
        int idx = tid + it * 256;
        int row = idx >> 3, c = idx & 7;   // row 0..255
        int n = bn + row;
        int sz = (n < N) ? 16 : 0;
        uint32_t d = st + 32768 + row * 128 + ((c ^ (row & 7)) << 4);
        size_t so = (size_t)n * K + k0 + c * 8;
        cp16(d, Bhi + so, sz);
        cp16(d + 32768, Blo + so, sz);
    }
}

template <int EPI>
__global__ void __launch_bounds__(256, 1)
gemm_w(const __nv_bfloat16* __restrict__ Ahi, const __nv_bfloat16* __restrict__ Alo,
       const __nv_bfloat16* __restrict__ Bhi, const __nv_bfloat16* __restrict__ Blo,
       const float* __restrict__ bias, const float* __restrict__ res,
       float* __restrict__ C, __nv_bfloat16* __restrict__ Chi, __nv_bfloat16* __restrict__ Clo,
       int M, int N, int K) {
    extern __shared__ char smem[];
    const int tid = threadIdx.x;
    const int bm = blockIdx.x * 128;
    const int bn = blockIdx.y * 256;
    const int nc = K >> 6;

    const uint32_t tiles = smem_to_u32(smem) + SMEM_OFF;
    const int lane = tid & 31;
    const int wid = tid >> 5;
    const int wm = (wid & 1) << 6;     // 0 or 64
    const int wn = (wid >> 1) << 6;    // 0,64,128,192
    const int mi = lane >> 3;
    const int lrow = lane & 7;
    const int rA = ((mi & 1) << 3) + lrow;

    float acc[4][8][4];
    #pragma unroll
    for (int i = 0; i < 4; i++)
        #pragma unroll
        for (int j = 0; j < 8; j++)
            #pragma unroll
            for (int t = 0; t < 4; t++) acc[i][j][t] = 0.0f;

    copy_stage_w(tiles, Ahi, Alo, Bhi, Blo, bm, bn, 0, K, N, tid);
    cp_commit();

    for (int c = 0; c < nc; c++) {
        if (c + 1 < nc) {
            copy_stage_w(tiles + ((c + 1) & 1) * WSTAGE, Ahi, Alo, Bhi, Blo,
                         bm, bn, (c + 1) << 6, K, N, tid);
            cp_commit();
            cp_wait1();
        } else {
            cp_wait0();
        }
        __syncthreads();

        const uint32_t st = tiles + (c & 1) * WSTAGE;
        #pragma unroll
        for (int s = 0; s < 4; s++) {
            const int cb = (s << 5) + ((mi >> 1) << 4);
            uint32_t ahi[4][4], alo[4][4], bhi[4][4], blo[4][4];
            #pragma unroll
            for (int i = 0; i < 4; i++) {
                int r = wm + (i << 4) + rA;
                uint32_t a = st + r * 128 + (cb ^ ((r & 7) << 4));
                LDSM4(ahi[i], a);
                LDSM4(alo[i], a + 16384);
            }
            #pragma unroll
            for (int j2 = 0; j2 < 4; j2++) {
                int r = wn + (j2 << 4) + rA;
                uint32_t a = st + 32768 + r * 128 + (cb ^ ((r & 7) << 4));
                LDSM4(bhi[j2], a);
                LDSM4(blo[j2], a + 32768);
            }
            #pragma unroll
            for (int i = 0; i < 4; i++)
                #pragma unroll
                for (int j2 = 0; j2 < 4; j2++) {
                    MMA16816(acc[i][2 * j2],     ahi[i], bhi[j2][0], bhi[j2][2]);
                    MMA16816(acc[i][2 * j2 + 1], ahi[i], bhi[j2][1], bhi[j2][3]);
                }
            #pragma unroll
            for (int i = 0; i < 4; i++)
                #pragma unroll
                for (int j2 = 0; j2 < 4; j2++) {
                    MMA16816(acc[i][2 * j2],     alo[i], bhi[j2][0], bhi[j2][2]);
                    MMA16816(acc[i][2 * j2 + 1], alo[i], bhi[j2][1], bhi[j2][3]);
                }
            #pragma unroll
            for (int i = 0; i < 4; i++)
                #pragma unroll
                for (int j2 = 0; j2 < 4; j2++) {
                    MMA16816(acc[i][2 * j2],     ahi[i], blo[j2][0], blo[j2][2]);
                    MMA16816(acc[i][2 * j2 + 1], ahi[i], blo[j2][1], blo[j2][3]);
                }
        }
        __syncthreads();
    }

    #pragma unroll
    for (int i = 0; i < 4; i++) {
        int row = bm + wm + (i << 4) + (lane >> 2);
        size_t base = (size_t)row * N;
        size_t base8 = base + (size_t)8 * N;
        #pragma unroll
        for (int j = 0; j < 8; j++) {
            int col = bn + wn + (j << 3) + ((lane & 3) << 1);
            if (col < N)     emit_one<EPI>(acc[i][j][0], base + col, col, bias, res, C, Chi, Clo);
            if (col + 1 < N) emit_one<EPI>(acc[i][j][1], base + col + 1, col + 1, bias, res, C, Chi, Clo);
            if (col < N)     emit_one<EPI>(acc[i][j][2], base8 + col, col, bias, res, C, Chi, Clo);
            if (col + 1 < N) emit_one<EPI>(acc[i][j][3], base8 + col + 1, col + 1, bias, res, C, Chi, Clo);
        }
    }
}

// ---------------- flash attention (mma.sync, split-compensated) ----------------
#define ATT_SMEM (6*16384)
__global__ void __launch_bounds__(256, 1)
fattn_k(const __nv_bfloat16* __restrict__ qkvh, const __nv_bfloat16* __restrict__ qkvl,
        __nv_bfloat16* __restrict__ ch, __nv_bfloat16* __restrict__ cl) {
    extern __shared__ char smx[];
    const uint32_t sQ = smem_to_u32(smx);
    const uint32_t sK = sQ + 2 * 16384;
    const uint32_t sV = sQ + 4 * 16384;
    const int tid = threadIdx.x;
    const int lane = tid & 31, wid = tid >> 5;
    const int qt = blockIdx.x;
    const int bh = blockIdx.y;
    const int b = bh >> 3, h = bh & 7;
    const int tokQ = b * SEQ + qt * 128;
    const int ho = h * HEADD;
    const int mi = lane >> 3, lrow = lane & 7;
    const int wm = wid * 16;
    const int rB = ((mi & 1) << 3) + lrow;

    #pragma unroll
    for (int it = 0; it < 4; it++) {
        int idx = tid + it * 256;
        int r = idx >> 3, c = idx & 7;
        uint32_t d = sQ + r * 128 + ((c ^ (r & 7)) << 4);
        size_t so = (size_t)(tokQ + r) * QKVS + ho + c * 8;
        cp16(d, qkvh + so, 16);
        cp16(d + 16384, qkvl + so, 16);
    }
    cp_commit();
    cp_wait0();
    __syncthreads();

    uint32_t aq[4][4], aql[4][4];
    {
        int r = wm + rB;
        #pragma unroll
        for (int s = 0; s < 4; s++) {
            uint32_t addr = sQ + r * 128 + ((((s << 5) + ((mi >> 1) << 4))) ^ ((r & 7) << 4));
            LDSM4(aq[s], addr);
            LDSM4(aql[s], addr + 16384);
        }
    }

    float oacc[8][4];
    #pragma unroll
    for (int f = 0; f < 8; f++)
        #pragma unroll
        for (int t = 0; t < 4; t++) oacc[f][t] = 0.0f;
    float mr0 = -1e30f, mr1 = -1e30f, lr0 = 0.0f, lr1 = 0.0f;
    const int myr0 = wm + (lane >> 2);
    const int myr1 = myr0 + 8;

    for (int jt = 0; jt <= qt; jt++) {
        __syncthreads();
        const int tokJ = b * SEQ + jt * 128;
        #pragma unroll
        for (int it = 0; it < 4; it++) {
            int idx = tid + it * 256;
            int r = idx >> 3, c = idx & 7;
            uint32_t d = sK + r * 128 + ((c ^ (r & 7)) << 4);
            size_t so = (size_t)(tokJ + r) * QKVS + 512 + ho + c * 8;
            cp16(d, qkvh + so, 16);
            cp16(d + 16384, qkvl + so, 16);
        }
        #pragma unroll
        for (int it = 0; it < 4; it++) {
            int task = tid + it * 256;
            int j = task >> 3, c = task & 7;
            size_t so = (size_t)(tokJ + j) * QKVS + 1024 + ho + c * 8;
            uint4 v4h = *reinterpret_cast<const uint4*>(qkvh + so);
            uint4 v4l = *reinterpret_cast<const uint4*>(qkvl + so);
            const uint32_t* wh = &v4h.x;
            const uint32_t* wl = &v4l.x;
            #pragma unroll
            for (int i = 0; i < 8; i++) {
                int dd = c * 8 + i;
                uint32_t off = dd * 256 + ((((uint32_t)(j >> 3) ^ (uint32_t)(dd & 7)) << 4)) + (j & 7) * 2;
                uint16_t hv = (uint16_t)(wh[i >> 1] >> ((i & 1) * 16));
                uint16_t lv = (uint16_t)(wl[i >> 1] >> ((i & 1) * 16));
                asm volatile("st.shared.u16 [%0], %1;" :: "r"(sV + off), "h"(hv));
                asm volatile("st.shared.u16 [%0], %1;" :: "r"(sV + 16384 + off), "h"(lv));
            }
        }
        cp_commit();
        cp_wait0();
        __syncthreads();

        float facc[16][4];
        #pragma unroll
        for (int f = 0; f < 16; f++)
            #pragma unroll
            for (int t = 0; t < 4; t++) facc[f][t] = 0.0f;
        #pragma unroll
        for (int g = 0; g < 8; g++) {
            int r = g * 16 + rB;
            #pragma unroll
            for (int s = 0; s < 4; s++) {
                uint32_t kb[4], kbl[4];
                uint32_t addr = sK + r * 128 + ((((s << 5) + ((mi >> 1) << 4))) ^ ((r & 7) << 4));
                LDSM4(kb, addr);
                LDSM4(kbl, addr + 16384);
                MMA16816(facc[2 * g],     aq[s],  kb[0],  kb[2]);
                MMA16816(facc[2 * g + 1], aq[s],  kb[1],  kb[3]);
                MMA16816(facc[2 * g],     aql[s], kb[0],  kb[2]);
                MMA16816(facc[2 * g + 1], aql[s], kb[1],  kb[3]);
                MMA16816(facc[2 * g],     aq[s],  kbl[0], kbl[2]);
                MMA16816(facc[2 * g + 1], aq[s],  kbl[1], kbl[3]);
            }
        }
        const float scl = 0.125f;
        #pragma unroll
        for (int f = 0; f < 16; f++) {
            int c0 = f * 8 + 2 * (lane & 3);
            facc[f][0] *= scl; facc[f][1] *= scl;
            facc[f][2] *= scl; facc[f][3] *= scl;
            if (jt == qt) {
                if (c0     > myr0) facc[f][0] = -1e30f;
                if (c0 + 1 > myr0) facc[f][1] = -1e30f;
                if (c0     > myr1) facc[f][2] = -1e30f;
                if (c0 + 1 > myr1) facc[f][3] = -1e30f;
            }
        }
        float m0 = -1e30f, m1 = -1e30f;
        #pragma unroll
        for (int f = 0; f < 16; f++) {
            m0 = fmaxf(m0, fmaxf(facc[f][0], facc[f][1]));
            m1 = fmaxf(m1, fmaxf(facc[f][2], facc[f][3]));
        }
        m0 = fmaxf(m0, __shfl_xor_sync(0xffffffffu, m0, 1));
        m0 = fmaxf(m0, __shfl_xor_sync(0xffffffffu, m0, 2));
        m1 = fmaxf(m1, __shfl_xor_sync(0xffffffffu, m1, 1));
        m1 = fmaxf(m1, __shfl_xor_sync(0xffffffffu, m1, 2));
        float nm0 = fmaxf(mr0, m0), nm1 = fmaxf(mr1, m1);
        float al0 = __expf(mr0 - nm0), al1 = __expf(mr1 - nm1);
        mr0 = nm0; mr1 = nm1;
        #pragma unroll
        for (int f = 0; f < 8; f++) {
            oacc[f][0] *= al0; oacc[f][1] *= al0;
            oacc[f][2] *= al1; oacc[f][3] *= al1;
        }
        float s0 = 0.0f, s1 = 0.0f;
        uint32_t pah[8][4], pal[8][4];
        #pragma unroll
        for (int f = 0; f < 16; f++) {
            float p0 = __expf(facc[f][0] - nm0);
            float p1 = __expf(facc[f][1] - nm0);
            float p2 = __expf(facc[f][2] - nm1);
            float p3 = __expf(facc[f][3] - nm1);
            s0 += p0 + p1;
            s1 += p2 + p3;
            __nv_bfloat162 hp = __floats2bfloat162_rn(p0, p1);
            float2 hf = __bfloat1622float2(hp);
            __nv_bfloat162 lp = __floats2bfloat162_rn(p0 - hf.x, p1 - hf.y);
            __nv_bfloat162 hq = __floats2bfloat162_rn(p2, p3);
            float2 hg = __bfloat1622float2(hq);
            __nv_bfloat162 lq = __floats2bfloat162_rn(p2 - hg.x, p3 - hg.y);
            int ks = f >> 1, half = f & 1;
            pah[ks][2 * half]     = *reinterpret_cast<uint32_t*>(&hp);
            pah[ks][2 * half + 1] = *reinterpret_cast<uint32_t*>(&hq);
            pal[ks][2 * half]     = *reinterpret_cast<uint32_t*>(&lp);
            pal[ks][2 * half + 1] = *reinterpret_cast<uint32_t*>(&lq);
        }
        s0 += __shfl_xor_sync(0xffffffffu, s0, 1);
        s0 += __shfl_xor_sync(0xffffffffu, s0, 2);
        s1 += __shfl_xor_sync(0xffffffffu, s1, 1);
        s1 += __shfl_xor_sync(0xffffffffu, s1, 2);
        lr0 = lr0 * al0 + s0;
        lr1 = lr1 * al1 + s1;
        #pragma unroll
        for (int ks = 0; ks < 8; ks++) {
            #pragma unroll
            for (int g2 = 0; g2 < 4; g2++) {
                uint32_t vb[4], vbl[4];
                int r = g2 * 16 + rB;
                uint32_t addr = sV + r * 256 + ((((ks << 5) + ((mi >> 1) << 4))) ^ ((r & 7) << 4));
                LDSM4(vb, addr);
                LDSM4(vbl, addr + 16384);
                MMA16816(oacc[2 * g2],     pah[ks], vb[0],  vb[2]);
                MMA16816(oacc[2 * g2 + 1], pah[ks], vb[1],  vb[3]);
                MMA16816(oacc[2 * g2],     pal[ks], vb[0],  vb[2]);
                MMA16816(oacc[2 * g2 + 1], pal[ks], vb[1],  vb[3]);
                MMA16816(oacc[2 * g2],     pah[ks], vbl[0], vbl[2]);
                MMA16816(oacc[2 * g2 + 1], pah[ks], vbl[1], vbl[3]);
            }
        }
    }

    float inv0 = 1.0f / lr0, inv1 = 1.0f / lr1;
    size_t t0 = (size_t)(tokQ + myr0) * DMODEL + ho;
    size_t t1 = t0 + (size_t)8 * DMODEL;
    #pragma unroll
    for (int f = 0; f < 8; f++) {
        int dc = f * 8 + 2 * (lane & 3);
        float x0 = oacc[f][0] * inv0, x1 = oacc[f][1] * inv0;
        float x2 = oacc[f][2] * inv1, x3 = oacc[f][3] * inv1;
        __nv_bfloat162 h01 = __floats2bfloat162_rn(x0, x1);
        float2 hf = __bfloat1622float2(h01);
        __nv_bfloat162 l01 = __floats2bfloat162_rn(x0 - hf.x, x1 - hf.y);
        __nv_bfloat162 h23 = __floats2bfloat162_rn(x2, x3);
        float2 hg = __bfloat1622float2(h23);
        __nv_bfloat162 l23 = __floats2bfloat162_rn(x2 - hg.x, x3 - hg.y);
        *reinterpret_cast<uint32_t*>(ch + t0 + dc) = *reinterpret_cast<uint32_t*>(&h01);
        *reinterpret_cast<uint32_t*>(cl + t0 + dc) = *reinterpret_cast<uint32_t*>(&l01);
        *reinterpret_cast<uint32_t*>(ch + t1 + dc) = *reinterpret_cast<uint32_t*>(&h23);
        *reinterpret_cast<uint32_t*>(cl + t1 + dc) = *reinterpret_cast<uint32_t*>(&l23);
    }
}

// ---------------- weight transpose + split ----------------
__device__ __forceinline__ void transpose_split(const float* __restrict__ in,
        __nv_bfloat16* __restrict__ hi, __nv_bfloat16* __restrict__ lo, int K, int N) {
    __shared__ float t[32][33];
    int n0 = blockIdx.x << 5, k0 = blockIdx.y << 5;
    int tx = threadIdx.x, ty = threadIdx.y;
    #pragma unroll
    for (int r = 0; r < 4; r++)
        t[ty + 8 * r][tx] = in[(size_t)(k0 + ty + 8 * r) * N + n0 + tx];
    __syncthreads();
    #pragma unroll
    for (int r = 0; r < 4; r++) {
        float v = t[tx][ty + 8 * r];
        size_t o = (size_t)(n0 + ty + 8 * r) * K + k0 + tx;
        __nv_bfloat16 h = __float2bfloat16(v);
        hi[o] = h;
        lo[o] = __float2bfloat16(v - __bfloat162float(h));
    }
}
__global__ void wsplit_qkvo_k(const float* __restrict__ Wq, const float* __restrict__ Wk,
                              const float* __restrict__ Wv, const float* __restrict__ Wo,
                              __nv_bfloat16* __restrict__ wbuf) {
    int z = blockIdx.z, l = z >> 2, m = z & 3;
    const float* W = (m == 0 ? Wq : m == 1 ? Wk : m == 2 ? Wv : Wo) + (size_t)l * DDSZ;
    __nv_bfloat16* base = wbuf + (size_t)l * WL_STRIDE;
    transpose_split(W, base + (size_t)m * DDSZ, base + (size_t)(4 + m) * DDSZ, DMODEL, DMODEL);
}
__global__ void wsplit_w1_k(const float* __restrict__ W1, __nv_bfloat16* __restrict__ wbuf) {
    int l = blockIdx.z;
    __nv_bfloat16* hi = wbuf + (size_t)l * WL_STRIDE + QKVO_TOT;
    transpose_split(W1 + (size_t)l * DFSZ, hi, hi + DFSZ, DMODEL, FFDIM);
}
__global__ void wsplit_w2_k(const float* __restrict__ W2, __nv_bfloat16* __restrict__ wbuf) {
    int l = blockIdx.z;
    __nv_bfloat16* hi = wbuf + (size_t)l * WL_STRIDE + QKVO_TOT + 2 * (size_t)DFSZ;
    transpose_split(W2 + (size_t)l * DFSZ, hi, hi + DFSZ, FFDIM, DMODEL);
}
__global__ __launch_bounds__(256) void embsplit_k(const float* __restrict__ te,
        __nv_bfloat16* __restrict__ hi, __nv_bfloat16* __restrict__ lo) {
    size_t n4 = (size_t)VOCAB * DMODEL / 4;
    for (size_t i = (size_t)blockIdx.x * blockDim.x + threadIdx.x; i < n4;
         i += (size_t)gridDim.x * blockDim.x) {
        float4 v = reinterpret_cast<const float4*>(te)[i];
        uint2 h, l;
        split4(v, h, l);
        reinterpret_cast<uint2*>(hi)[i] = h;
        reinterpret_cast<uint2*>(lo)[i] = l;
    }
}
__global__ void biascat_k(const float* __restrict__ bq, const float* __restrict__ bk,
                          const float* __restrict__ bv, float* __restrict__ o) {
    int l = blockIdx.x, t = threadIdx.x;
    o[l * QKVS + t]        = bq[l * DMODEL + t];
    o[l * QKVS + 512 + t]  = bk[l * DMODEL + t];
    o[l * QKVS + 1024 + t] = bv[l * DMODEL + t];
}

// ---------------- helpers ----------------
__device__ __forceinline__ int detect_i64(const void* p, int n) {
    const long long* x = (const long long*)p;
    int c = n < 32 ? n : 32;
    for (int i = 0; i < c; i++) {
        long long v = x[i];
        if (v < 0 || v >= VOCAB) return 0;
    }
    return 1;
}
__device__ __forceinline__ long long load_index(const void* p, int i, int is64) {
    return is64 ? ((const long long*)p)[i] : (long long)((const int*)p)[i];
}

// ---------------- embedding ----------------
__global__ __launch_bounds__(256) void embed_k(const void* __restrict__ xr,
                                               const float* __restrict__ te,
                                               const float* __restrict__ pe,
                                               float* __restrict__ h) {
    __shared__ int mode;
    if (threadIdx.x == 0) mode = detect_i64(xr, BS);
    __syncthreads();
    int pos = blockIdx.x;
    int tid = threadIdx.x;
    long long idx = load_index(xr, pos, mode);
    int s = pos & (SEQ - 1);
    const float* t = te + idx * DMODEL;
    const float* p = pe + (long long)s * DMODEL;
    float* o = h + (long long)pos * DMODEL;
    o[tid]       = t[tid]       + p[tid];
    o[tid + 256] = t[tid + 256] + p[tid + 256];
}

// ---------------- layernorm -> bf16 split ----------------
__global__ __launch_bounds__(256) void ln_k(const float* __restrict__ in,
                                            const float* __restrict__ g,
                                            const float* __restrict__ b,
                                            __nv_bfloat16* __restrict__ oh,
                                            __nv_bfloat16* __restrict__ ol) {
    int row = blockIdx.x;
    int tid = threadIdx.x;
    int lane = tid & 31, wid = tid >> 5;
    const float* x = in + (long long)row * DMODEL;
    float v0 = x[tid], v1 = x[tid + 256];
    __shared__ float wr[16];
    float s = v0 + v1;
    #pragma unroll
    for (int o = 16; o; o >>= 1) s += __shfl_xor_sync(0xffffffffu, s, o);
    if (lane == 0) wr[wid] = s;
    __syncthreads();
    float mu = (wr[0] + wr[1] + wr[2] + wr[3] + wr[4] + wr[5] + wr[6] + wr[7]) * (1.0f / DMODEL);
    float d0 = v0 - mu, d1 = v1 - mu;
    float q = d0 * d0 + d1 * d1;
    #pragma unroll
    for (int o = 16; o; o >>= 1) q += __shfl_xor_sync(0xffffffffu, q, o);
    if (lane == 0) wr[8 + wid] = q;
    __syncthreads();
    float var = (wr[8] + wr[9] + wr[10] + wr[11] + wr[12] + wr[13] + wr[14] + wr[15]) * (1.0f / DMODEL);
    float rstd = rsqrtf(var + 1e-5f);
    long long base = (long long)row * DMODEL;
    float y0 = d0 * rstd * g[tid] + b[tid];
    float y1 = d1 * rstd * g[tid + 256] + b[tid + 256];
    __nv_bfloat16 h0 = __float2bfloat16(y0);
    __nv_bfloat16 h1 = __float2bfloat16(y1);
    oh[base + tid] = h0;
    ol[base + tid] = __float2bfloat16(y0 - __bfloat162float(h0));
    oh[base + tid + 256] = h1;
    ol[base + tid + 256] = __float2bfloat16(y1 - __bfloat162float(h1));
}

// ---------------- single-pass cross-entropy ----------------
__global__ __launch_bounds__(256) void loss_row_k(const float* __restrict__ logits,
                                                  const void* __restrict__ tr,
                                                  float* __restrict__ rowloss) {
    __shared__ int mode;
    __shared__ float rm[256], rs[256];
    int row = blockIdx.x, tid = threadIdx.x;
    if (tid == 0) mode = detect_i64(tr, BS);
    __syncthreads();
    const float* lr = logits + (long long)row * VOCAB;
    float m = -1e30f, s = 0.0f;
    for (int j = tid; j < VOCAB; j += 256) {
        float v = lr[j];
        float nm = fmaxf(m, v);
        s = s * __expf(m - nm) + __expf(v - nm);
        m = nm;
    }
    rm[tid] = m;
    rs[tid] = s;
    __syncthreads();
    #pragma unroll
    for (int st = 128; st > 0; st >>= 1) {
        if (tid < st) {
            float ma = rm[tid], mb = rm[tid + st];
            float nm = fmaxf(ma, mb);
            rs[tid] = rs[tid] * __expf(ma - nm) + rs[tid + st] * __expf(mb - nm);
            rm[tid] = nm;
        }
        __syncthreads();
    }
    if (tid == 0) {
        long long t = load_index(tr, row, mode);
        rowloss[row] = -(lr[t] - rm[0] - logf(rs[0]));
    }
}

__global__ __launch_bounds__(1024) void loss_reduce_k(const float* __restrict__ rowloss,
                                                      float* __restrict__ out) {
    __shared__ float red[1024];
    int tid = threadIdx.x;
    red[tid] = rowloss[tid] + rowloss[tid + 1024] + rowloss[tid + 2048] + rowloss[tid + 3072];
    __syncthreads();
    #pragma unroll
    for (int s = 512; s > 0; s >>= 1) {
        if (tid < s) red[tid] += red[tid + s];
        __syncthreads();
    }
    if (tid == 0) out[0] = red[0] * (1.0f / BS);
}

// ---------------- host launcher ----------------
extern "C" void kernel_launch(void* const* d_in, const int* in_sizes, int n_in,
                              void* d_out, int out_size) {
    (void)in_sizes; (void)n_in;
    const void*  x       = d_in[0];
    const void*  targets = d_in[1];
    const float* te   = (const float*)d_in[2];
    const float* pe   = (const float*)d_in[3];
    const float* ln1g = (const float*)d_in[4];
    const float* ln1b = (const float*)d_in[5];
    const float* Wq   = (const float*)d_in[6];
    const float* bq   = (const float*)d_in[7];
    const float* Wk   = (const float*)d_in[8];
    const float* bk   = (const float*)d_in[9];
    const float* Wv   = (const float*)d_in[10];
    const float* bv   = (const float*)d_in[11];
    const float* Wo   = (const float*)d_in[12];
    const float* bo   = (const float*)d_in[13];
    const float* ln2g = (const float*)d_in[14];
    const float* ln2b = (const float*)d_in[15];
    const float* W1   = (const float*)d_in[16];
    const float* b1   = (const float*)d_in[17];
    const float* W2   = (const float*)d_in[18];
    const float* b2   = (const float*)d_in[19];
    const float* lnfg = (const float*)d_in[20];
    const float* lnfb = (const float*)d_in[21];
    float* out = (float*)d_out;

    float *p_h, *p_rowloss, *p_logits, *p_bqkv;
    __nv_bfloat16 *p_xnh, *p_xnl, *p_qkvh, *p_qkvl;
    __nv_bfloat16 *p_ctxh, *p_ctxl, *p_ffh, *p_ffl, *p_wbuf, *p_emb;
    cudaGetSymbolAddress((void**)&p_h, g_h);
    cudaGetSymbolAddress((void**)&p_rowloss, g_rowloss);
    cudaGetSymbolAddress((void**)&p_logits, g_logits_scratch);
    cudaGetSymbolAddress((void**)&p_bqkv, g_bqkv);
    cudaGetSymbolAddress((void**)&p_xnh, g_xnh);
    cudaGetSymbolAddress((void**)&p_xnl, g_xnl);
    cudaGetSymbolAddress((void**)&p_qkvh, g_qkvh);
    cudaGetSymbolAddress((void**)&p_qkvl, g_qkvl);
    cudaGetSymbolAddress((void**)&p_ctxh, g_ctxh);
    cudaGetSymbolAddress((void**)&p_ctxl, g_ctxl);
    cudaGetSymbolAddress((void**)&p_ffh, g_ffh);
    cudaGetSymbolAddress((void**)&p_ffl, g_ffl);
    cudaGetSymbolAddress((void**)&p_wbuf, g_wbuf);
    cudaGetSymbolAddress((void**)&p_emb, g_emb);
    __nv_bfloat16* p_embh = p_emb;
    __nv_bfloat16* p_embl = p_emb + (size_t)VPAD * DMODEL;

    cudaFuncSetAttribute(gemm_bf<1>, cudaFuncAttributeMaxDynamicSharedMemorySize, GEMM_SMEM);
    cudaFuncSetAttribute(gemm_w<2>,  cudaFuncAttributeMaxDynamicSharedMemorySize, GEMM_SMEM_W);
    cudaFuncSetAttribute(gemm_w<3>,  cudaFuncAttributeMaxDynamicSharedMemorySize, GEMM_SMEM_W);
    cudaFuncSetAttribute(gemm_w<4>,  cudaFuncAttributeMaxDynamicSharedMemorySize, GEMM_SMEM_W);
    cudaFuncSetAttribute(fattn_k, cudaFuncAttributeMaxDynamicSharedMemorySize, ATT_SMEM);

    wsplit_qkvo_k<<<dim3(16, 16, 24), dim3(32, 8)>>>(Wq, Wk, Wv, Wo, p_wbuf);
    wsplit_w1_k<<<dim3(64, 16, 6), dim3(32, 8)>>>(W1, p_wbuf);
    wsplit_w2_k<<<dim3(16, 64, 6), dim3(32, 8)>>>(W2, p_wbuf);
    embsplit_k<<<2048, 256>>>(te, p_embh, p_embl);
    biascat_k<<<NLAYER, 512>>>(bq, bk, bv, p_bqkv);

    embed_k<<<BS, 256>>>(x, te, pe, p_h);

    dim3 gDD(BS / 128, DMODEL / 128);     // 32 x 4  (narrow, N=512)
    dim3 gQKV(BS / 128, QKVS / 256);      // 32 x 6  (wide)
    dim3 gDF(BS / 128, FFDIM / 256);      // 32 x 8  (wide)
    dim3 gATT(SEQ / 128, BATCH * NHEAD);

    for (int l = 0; l < NLAYER; l++) {
        __nv_bfloat16* wl = p_wbuf + (size_t)l * WL_STRIDE;
        __nv_bfloat16* w1h = wl + QKVO_TOT;
        __nv_bfloat16* w2h = wl + QKVO_TOT + 2 * (size_t)DFSZ;

        ln_k<<<BS, 256>>>(p_h, ln1g + l * DMODEL, ln1b + l * DMODEL, p_xnh, p_xnl);
        gemm_w<4><<<gQKV, 256, GEMM_SMEM_W>>>(p_xnh, p_xnl, wl, wl + 4 * (size_t)DDSZ,
                                              p_bqkv + l * QKVS, nullptr, nullptr,
                                              p_qkvh, p_qkvl, BS, QKVS, DMODEL);
        fattn_k<<<gATT, 256, ATT_SMEM>>>(p_qkvh, p_qkvl, p_ctxh, p_ctxl);
        gemm_bf<1><<<gDD, 256, GEMM_SMEM>>>(p_ctxh, p_ctxl, wl + 3 * (size_t)DDSZ,
                                            wl + 7 * (size_t)DDSZ, bo + l * DMODEL,
                                            p_h, p_h, nullptr, nullptr, BS, DMODEL, DMODEL);
        ln_k<<<BS, 256>>>(p_h, ln2g + l * DMODEL, ln2b + l * DMODEL, p_xnh, p_xnl);
        gemm_w<2><<<gDF, 256, GEMM_SMEM_W>>>(p_xnh, p_xnl, w1h, w1h + DFSZ, b1 + l * FFDIM,
                                             nullptr, nullptr, p_ffh, p_ffl, BS, FFDIM, DMODEL);
        gemm_bf<1><<<gDD, 256, GEMM_SMEM>>>(p_ffh, p_ffl, w2h, w2h + DFSZ, b2 + l * DMODEL,
                                            p_h, p_h, nullptr, nullptr, BS, DMODEL, FFDIM);
    }

    ln_k<<<BS, 256>>>(p_h, lnfg, lnfb, p_xnh, p_xnl);

    float* logits = ((long long)out_size >= NLOG) ? out : p_logits;
    dim3 gLOG(BS / 128, VPAD / 256);      // 32 x 197
    gemm_w<3><<<gLOG, 256, GEMM_SMEM_W>>>(p_xnh, p_xnl, p_embh, p_embl, nullptr,
                                          nullptr, logits, nullptr, nullptr, BS, VOCAB, DMODEL);

    loss_row_k<<<BS, 256>>>(logits, targets, p_rowloss);
    if ((long long)out_size > NLOG) {
        loss_reduce_k<<<1, 1024>>>(p_rowloss, out + NLOG);
    } else if ((long long)out_size < NLOG && out_size >= 1) {
        loss_reduce_k<<<1, 1024>>>(p_rowloss, out + (out_size - 1));
    }
}

// round 7
// speedup vs baseline: 1.3000x; 1.3000x over previous
#include <cuda_runtime.h>
#include <cuda_bf16.h>
#include <cuda_fp16.h>
#include <math.h>
#include <stdint.h>

// ---------------- model constants ----------------
#define BATCH  8
#define SEQ    512
#define DMODEL 512
#define NHEAD  8
#define HEADD  64
#define FFDIM  2048
#define NLAYER 6
#define VOCAB  50257
#define VPAD   50304                  // 393*128
#define BS     (BATCH*SEQ)
#define QKVS   1536
static const long long NLOG = (long long)BS * VOCAB;

// converted-weight layout (bf16), per layer:
// [q_hi k_hi v_hi o_hi][q_lo k_lo v_lo o_lo][w1_hi w1_lo][w2_hi w2_lo]
#define DDSZ   (DMODEL*DMODEL)
#define DFSZ   (DMODEL*FFDIM)
#define QKVO_TOT (8*DDSZ)
#define WL_STRIDE (QKVO_TOT + 2*DFSZ + 2*DFSZ)

// ---------------- device scratch ----------------
__device__ float g_h[BS * DMODEL];
__device__ float g_rowloss[BS];
__device__ float g_bqkv[NLAYER * QKVS];
__device__ float g_logits_scratch[(size_t)BS * VOCAB];
__device__ __nv_bfloat16 g_xnh[BS * DMODEL];
__device__ __nv_bfloat16 g_xnl[BS * DMODEL];
__device__ __half g_xnf[BS * DMODEL];
__device__ __nv_bfloat16 g_qkvh[BS * QKVS];
__device__ __nv_bfloat16 g_qkvl[BS * QKVS];
__device__ __nv_bfloat16 g_ctxh[BS * DMODEL];
__device__ __nv_bfloat16 g_ctxl[BS * DMODEL];
__device__ __nv_bfloat16 g_ffh[BS * FFDIM];
__device__ __nv_bfloat16 g_ffl[BS * FFDIM];
__device__ __nv_bfloat16 g_wbuf[(size_t)WL_STRIDE * NLAYER];
__device__ __half g_embf[(size_t)VPAD * DMODEL];

// ================= PTX helpers =================
__device__ __forceinline__ uint32_t smem_to_u32(const void* smem_ptr) {
    uint32_t addr;
    asm("{ .reg .u64 tmp; cvta.to.shared.u64 tmp, %1; cvt.u32.u64 %0, tmp; }"
        : "=r"(addr) : "l"(smem_ptr));
    return addr;
}
__device__ __forceinline__ void cp16(uint32_t d, const void* s, int sz) {
    asm volatile("cp.async.cg.shared.global [%0], [%1], 16, %2;\n"
                 :: "r"(d), "l"(s), "r"(sz) : "memory");
}
__device__ __forceinline__ void cp_commit() {
    asm volatile("cp.async.commit_group;\n" ::: "memory");
}
__device__ __forceinline__ void cp_wait0() {
    asm volatile("cp.async.wait_group 0;\n" ::: "memory");
}
__device__ __forceinline__ void cp_wait1() {
    asm volatile("cp.async.wait_group 1;\n" ::: "memory");
}
#define LDSM4(r, addr) \
    asm volatile("ldmatrix.sync.aligned.m8n8.x4.shared.b16 {%0,%1,%2,%3}, [%4];" \
        : "=r"((r)[0]), "=r"((r)[1]), "=r"((r)[2]), "=r"((r)[3]) : "r"(addr))
#define MMA16816(c, a, b0, b1) \
    asm volatile("mma.sync.aligned.m16n8k16.row.col.f32.bf16.bf16.f32 " \
        "{%0,%1,%2,%3}, {%4,%5,%6,%7}, {%8,%9}, {%0,%1,%2,%3};" \
        : "+f"((c)[0]), "+f"((c)[1]), "+f"((c)[2]), "+f"((c)[3]) \
        : "r"((a)[0]), "r"((a)[1]), "r"((a)[2]), "r"((a)[3]), "r"(b0), "r"(b1))
#define MMAF16(c, a, b0, b1) \
    asm volatile("mma.sync.aligned.m16n8k16.row.col.f32.f16.f16.f32 " \
        "{%0,%1,%2,%3}, {%4,%5,%6,%7}, {%8,%9}, {%0,%1,%2,%3};" \
        : "+f"((c)[0]), "+f"((c)[1]), "+f"((c)[2]), "+f"((c)[3]) \
        : "r"((a)[0]), "r"((a)[1]), "r"((a)[2]), "r"((a)[3]), "r"(b0), "r"(b1))

__device__ __forceinline__ void split4(float4 v, uint2& hi, uint2& lo) {
    __nv_bfloat162 h01 = __floats2bfloat162_rn(v.x, v.y);
    __nv_bfloat162 h23 = __floats2bfloat162_rn(v.z, v.w);
    float2 b01 = __bfloat1622float2(h01);
    float2 b23 = __bfloat1622float2(h23);
    __nv_bfloat162 l01 = __floats2bfloat162_rn(v.x - b01.x, v.y - b01.y);
    __nv_bfloat162 l23 = __floats2bfloat162_rn(v.z - b23.x, v.w - b23.y);
    hi.x = *reinterpret_cast<uint32_t*>(&h01);
    hi.y = *reinterpret_cast<uint32_t*>(&h23);
    lo.x = *reinterpret_cast<uint32_t*>(&l01);
    lo.y = *reinterpret_cast<uint32_t*>(&l23);
}

// epilogue: 0=bias->f32, 1=bias+res->f32, 2=bias+gelu->bf16 split, 3=plain f32, 4=bias->bf16 split
template <int EPI>
__device__ __forceinline__ void emit_one(float x, size_t off, int col,
        const float* __restrict__ bias, const float* __restrict__ res,
        float* __restrict__ C, __nv_bfloat16* __restrict__ Chi, __nv_bfloat16* __restrict__ Clo) {
    if (EPI == 0 || EPI == 1 || EPI == 2 || EPI == 4) x += __ldg(bias + col);
    if (EPI == 2) x = 0.5f * x * (1.0f + erff(x * 0.70710678118654752440f));
    if (EPI == 1) x += res[off];
    if (EPI == 2 || EPI == 4) {
        __nv_bfloat16 h = __float2bfloat16(x);
        Chi[off] = h;
        Clo[off] = __float2bfloat16(x - __bfloat162float(h));
    } else {
        C[off] = x;
    }
}

// ================= narrow bf16 3-pass GEMM (CTA 128x128) =================
#define TB 16384
#define STAGE_BYTES (4*TB)
#define SMEM_OFF 1024
#define GEMM_SMEM (SMEM_OFF + 2*STAGE_BYTES)

__device__ __forceinline__ void copy_stage(uint32_t st,
        const __nv_bfloat16* __restrict__ Ahi, const __nv_bfloat16* __restrict__ Alo,
        const __nv_bfloat16* __restrict__ Bhi, const __nv_bfloat16* __restrict__ Blo,
        int bm, int bn, int k0, int K, int N, int tid) {
    #pragma unroll
    for (int it = 0; it < 4; it++) {
        int idx = tid + it * 256;
        int row = idx >> 3, c = idx & 7;
        uint32_t d = st + row * 128 + ((c ^ (row & 7)) << 4);
        size_t so = (size_t)(bm + row) * K + k0 + c * 8;
        cp16(d, Ahi + so, 16);
        cp16(d + TB, Alo + so, 16);
    }
    #pragma unroll
    for (int it = 0; it < 4; it++) {
        int idx = tid + it * 256;
        int row = idx >> 3, c = idx & 7;
        int n = bn + row;
        int sz = (n < N) ? 16 : 0;
        uint32_t d = st + 2 * TB + row * 128 + ((c ^ (row & 7)) << 4);
        size_t so = (size_t)n * K + k0 + c * 8;
        cp16(d, Bhi + so, sz);
        cp16(d + TB, Blo + so, sz);
    }
}

template <int EPI>
__global__ void __launch_bounds__(256, 1)
gemm_bf(const __nv_bfloat16* __restrict__ Ahi, const __nv_bfloat16* __restrict__ Alo,
        const __nv_bfloat16* __restrict__ Bhi, const __nv_bfloat16* __restrict__ Blo,
        const float* __restrict__ bias, const float* __restrict__ res,
        float* __restrict__ C, __nv_bfloat16* __restrict__ Chi, __nv_bfloat16* __restrict__ Clo,
        int M, int N, int K) {
    extern __shared__ char smem[];
    const int tid = threadIdx.x;
    const int bm = blockIdx.x * 128;
    const int bn = blockIdx.y * 128;
    const int nc = K >> 6;

    const uint32_t tiles = smem_to_u32(smem) + SMEM_OFF;
    const int lane = tid & 31;
    const int wid = tid >> 5;
    const int wm = (wid & 3) << 5;
    const int wn = (wid >> 2) << 6;
    const int mi = lane >> 3;
    const int lrow = lane & 7;

    float acc[2][8][4];
    #pragma unroll
    for (int i = 0; i < 2; i++)
        #pragma unroll
        for (int j = 0; j < 8; j++)
            #pragma unroll
            for (int t = 0; t < 4; t++) acc[i][j][t] = 0.0f;

    copy_stage(tiles, Ahi, Alo, Bhi, Blo, bm, bn, 0, K, N, tid);
    cp_commit();

    for (int c = 0; c < nc; c++) {
        if (c + 1 < nc) {
            copy_stage(tiles + ((c + 1) & 1) * STAGE_BYTES, Ahi, Alo, Bhi, Blo,
                       bm, bn, (c + 1) << 6, K, N, tid);
            cp_commit();
            cp_wait1();
        } else {
            cp_wait0();
        }
        __syncthreads();

        const uint32_t st = tiles + (c & 1) * STAGE_BYTES;
        #pragma unroll
        for (int s = 0; s < 4; s++) {
            const int cb = (s << 5) + ((mi >> 1) << 4);
            uint32_t ahi[2][4], alo[2][4], bhi[4][4], blo[4][4];
            #pragma unroll
            for (int i = 0; i < 2; i++) {
                int r = wm + (i << 4) + ((mi & 1) << 3) + lrow;
                uint32_t a = st + r * 128 + (cb ^ ((r & 7) << 4));
                LDSM4(ahi[i], a);
                LDSM4(alo[i], a + TB);
            }
            #pragma unroll
            for (int j2 = 0; j2 < 4; j2++) {
                int r = wn + (j2 << 4) + ((mi & 1) << 3) + lrow;
                uint32_t a = st + 2 * TB + r * 128 + (cb ^ ((r & 7) << 4));
                LDSM4(bhi[j2], a);
                LDSM4(blo[j2], a + TB);
            }
            #pragma unroll
            for (int i = 0; i < 2; i++)
                #pragma unroll
                for (int j2 = 0; j2 < 4; j2++) {
                    MMA16816(acc[i][2 * j2],     ahi[i], bhi[j2][0], bhi[j2][2]);
                    MMA16816(acc[i][2 * j2 + 1], ahi[i], bhi[j2][1], bhi[j2][3]);
                }
            #pragma unroll
            for (int i = 0; i < 2; i++)
                #pragma unroll
                for (int j2 = 0; j2 < 4; j2++) {
                    MMA16816(acc[i][2 * j2],     alo[i], bhi[j2][0], bhi[j2][2]);
                    MMA16816(acc[i][2 * j2 + 1], alo[i], bhi[j2][1], bhi[j2][3]);
                }
            #pragma unroll
            for (int i = 0; i < 2; i++)
                #pragma unroll
                for (int j2 = 0; j2 < 4; j2++) {
                    MMA16816(acc[i][2 * j2],     ahi[i], blo[j2][0], blo[j2][2]);
                    MMA16816(acc[i][2 * j2 + 1], ahi[i], blo[j2][1], blo[j2][3]);
                }
        }
        __syncthreads();
    }

    #pragma unroll
    for (int i = 0; i < 2; i++) {
        int row = bm + wm + (i << 4) + (lane >> 2);
        size_t base = (size_t)row * N;
        size_t base8 = base + (size_t)8 * N;
        #pragma unroll
        for (int j = 0; j < 8; j++) {
            int col = bn + wn + (j << 3) + ((lane & 3) << 1);
            if (col < N)     emit_one<EPI>(acc[i][j][0], base + col, col, bias, res, C, Chi, Clo);
            if (col + 1 < N) emit_one<EPI>(acc[i][j][1], base + col + 1, col + 1, bias, res, C, Chi, Clo);
            if (col < N)     emit_one<EPI>(acc[i][j][2], base8 + col, col, bias, res, C, Chi, Clo);
            if (col + 1 < N) emit_one<EPI>(acc[i][j][3], base8 + col + 1, col + 1, bias, res, C, Chi, Clo);
        }
    }
}

// ================= fp16 single-pass GEMM (logits) =================
// stage: [A 16K][B 16K] = 32KB, 2 stages
#define FSTAGE (2*TB)
#define GEMM_SMEM_F (SMEM_OFF + 2*FSTAGE)   // 66560

__device__ __forceinline__ void copy_stage_f(uint32_t st,
        const __half* __restrict__ A, const __half* __restrict__ B,
        int bm, int bn, int k0, int K, int N, int tid) {
    #pragma unroll
    for (int it = 0; it < 4; it++) {
        int idx = tid + it * 256;
        int row = idx >> 3, c = idx & 7;
        uint32_t d = st + row * 128 + ((c ^ (row & 7)) << 4);
        size_t so = (size_t)(bm + row) * K + k0 + c * 8;
        cp16(d, A + so, 16);
    }
    #pragma unroll
    for (int it = 0; it < 4; it++) {
        int idx = tid + it * 256;
        int row = idx >> 3, c = idx & 7;
        int n = bn + row;
        int sz = (n < N) ? 16 : 0;
        uint32_t d = st + TB + row * 128 + ((c ^ (row & 7)) << 4);
        size_t so = (size_t)n * K + k0 + c * 8;
        cp16(d, B + so, sz);
    }
}

__global__ void __launch_bounds__(256, 1)
gemm_f16(const __half* __restrict__ A, const __half* __restrict__ B,
         float* __restrict__ C, int M, int N, int K) {
    extern __shared__ char smem[];
    const int tid = threadIdx.x;
    const int bm = blockIdx.x * 128;
    const int bn = blockIdx.y * 128;
    const int nc = K >> 6;

    const uint32_t tiles = smem_to_u32(smem) + SMEM_OFF;
    const int lane = tid & 31;
    const int wid = tid >> 5;
    const int wm = (wid & 3) << 5;
    const int wn = (wid >> 2) << 6;
    const int mi = lane >> 3;
    const int lrow = lane & 7;

    float acc[2][8][4];
    #pragma unroll
    for (int i = 0; i < 2; i++)
        #pragma unroll
        for (int j = 0; j < 8; j++)
            #pragma unroll
            for (int t = 0; t < 4; t++) acc[i][j][t] = 0.0f;

    copy_stage_f(tiles, A, B, bm, bn, 0, K, N, tid);
    cp_commit();

    for (int c = 0; c < nc; c++) {
        if (c + 1 < nc) {
            copy_stage_f(tiles + ((c + 1) & 1) * FSTAGE, A, B, bm, bn, (c + 1) << 6, K, N, tid);
            cp_commit();
            cp_wait1();
        } else {
            cp_wait0();
        }
        __syncthreads();

        const uint32_t st = tiles + (c & 1) * FSTAGE;
        #pragma unroll
        for (int s = 0; s < 4; s++) {
            const int cb = (s << 5) + ((mi >> 1) << 4);
            uint32_t af[2][4], bf[4][4];
            #pragma unroll
            for (int i = 0; i < 2; i++) {
                int r = wm + (i << 4) + ((mi & 1) << 3) + lrow;
                LDSM4(af[i], st + r * 128 + (cb ^ ((r & 7) << 4)));
            }
            #pragma unroll
            for (int j2 = 0; j2 < 4; j2++) {
                int r = wn + (j2 << 4) + ((mi & 1) << 3) + lrow;
                LDSM4(bf[j2], st + TB + r * 128 + (cb ^ ((r & 7) << 4)));
            }
            #pragma unroll
            for (int i = 0; i < 2; i++)
                #pragma unroll
                for (int j2 = 0; j2 < 4; j2++) {
                    MMAF16(acc[i][2 * j2],     af[i], bf[j2][0], bf[j2][2]);
                    MMAF16(acc[i][2 * j2 + 1], af[i], bf[j2][1], bf[j2][3]);
                }
        }
        __syncthreads();
    }

    #pragma unroll
    for (int i = 0; i < 2; i++) {
        int row = bm + wm + (i << 4) + (lane >> 2);
        size_t base = (size_t)row * N;
        size_t base8 = base + (size_t)8 * N;
        #pragma unroll
        for (int j = 0; j < 8; j++) {
            int col = bn + wn + (j << 3) + ((lane & 3) << 1);
            if (col < N)     C[base + col]      = acc[i][j][0];
            if (col + 1 < N) C[base + col + 1]  = acc[i][j][1];
            if (col < N)     C[base8 + col]     = acc[i][j][2];
            if (col + 1 < N) C[base8 + col + 1] = acc[i][j][3];
        }
    }
}

// ---------------- flash attention (mma.sync, split-compensated) ----------------
#define ATT_SMEM (6*16384)
__global__ void __launch_bounds__(256, 1)
fattn_k(const __nv_bfloat16* __restrict__ qkvh, const __nv_bfloat16* __restrict__ qkvl,
        __nv_bfloat16* __restrict__ ch, __nv_bfloat16* __restrict__ cl) {
    extern __shared__ char smx[];
    const uint32_t sQ = smem_to_u32(smx);
    const uint32_t sK = sQ + 2 * 16384;
    const uint32_t sV = sQ + 4 * 16384;
    const int tid = threadIdx.x;
    const int lane = tid & 31, wid = tid >> 5;
    const int qt = blockIdx.x;
    const int bh = blockIdx.y;
    const int b = bh >> 3, h = bh & 7;
    const int tokQ = b * SEQ + qt * 128;
    const int ho = h * HEADD;
    const int mi = lane >> 3, lrow = lane & 7;
    const int wm = wid * 16;
    const int rB = ((mi & 1) << 3) + lrow;

    #pragma unroll
    for (int it = 0; it < 4; it++) {
        int idx = tid + it * 256;
        int r = idx >> 3, c = idx & 7;
        uint32_t d = sQ + r * 128 + ((c ^ (r & 7)) << 4);
        size_t so = (size_t)(tokQ + r) * QKVS + ho + c * 8;
        cp16(d, qkvh + so, 16);
        cp16(d + 16384, qkvl + so, 16);
    }
    cp_commit();
    cp_wait0();
    __syncthreads();

    uint32_t aq[4][4], aql[4][4];
    {
        int r = wm + rB;
        #pragma unroll
        for (int s = 0; s < 4; s++) {
            uint32_t addr = sQ + r * 128 + ((((s << 5) + ((mi >> 1) << 4))) ^ ((r & 7) << 4));
            LDSM4(aq[s], addr);
            LDSM4(aql[s], addr + 16384);
        }
    }

    float oacc[8][4];
    #pragma unroll
    for (int f = 0; f < 8; f++)
        #pragma unroll
        for (int t = 0; t < 4; t++) oacc[f][t] = 0.0f;
    float mr0 = -1e30f, mr1 = -1e30f, lr0 = 0.0f, lr1 = 0.0f;
    const int myr0 = wm + (lane >> 2);
    const int myr1 = myr0 + 8;

    for (int jt = 0; jt <= qt; jt++) {
        __syncthreads();
        const int tokJ = b * SEQ + jt * 128;
        #pragma unroll
        for (int it = 0; it < 4; it++) {
            int idx = tid + it * 256;
            int r = idx >> 3, c = idx & 7;
            uint32_t d = sK + r * 128 + ((c ^ (r & 7)) << 4);
            size_t so = (size_t)(tokJ + r) * QKVS + 512 + ho + c * 8;
            cp16(d, qkvh + so, 16);
            cp16(d + 16384, qkvl + so, 16);
        }
        #pragma unroll
        for (int it = 0; it < 4; it++) {
            int task = tid + it * 256;
            int j = task >> 3, c = task & 7;
            size_t so = (size_t)(tokJ + j) * QKVS + 1024 + ho + c * 8;
            uint4 v4h = *reinterpret_cast<const uint4*>(qkvh + so);
            uint4 v4l = *reinterpret_cast<const uint4*>(qkvl + so);
            const uint32_t* wh = &v4h.x;
            const uint32_t* wl = &v4l.x;
            #pragma unroll
            for (int i = 0; i < 8; i++) {
                int dd = c * 8 + i;
                uint32_t off = dd * 256 + ((((uint32_t)(j >> 3) ^ (uint32_t)(dd & 7)) << 4)) + (j & 7) * 2;
                uint16_t hv = (uint16_t)(wh[i >> 1] >> ((i & 1) * 16));
                uint16_t lv = (uint16_t)(wl[i >> 1] >> ((i & 1) * 16));
                asm volatile("st.shared.u16 [%0], %1;" :: "r"(sV + off), "h"(hv));
                asm volatile("st.shared.u16 [%0], %1;" :: "r"(sV + 16384 + off), "h"(lv));
            }
        }
        cp_commit();
        cp_wait0();
        __syncthreads();

        float facc[16][4];
        #pragma unroll
        for (int f = 0; f < 16; f++)
            #pragma unroll
            for (int t = 0; t < 4; t++) facc[f][t] = 0.0f;
        #pragma unroll
        for (int g = 0; g < 8; g++) {
            int r = g * 16 + rB;
            #pragma unroll
            for (int s = 0; s < 4; s++) {
                uint32_t kb[4], kbl[4];
                uint32_t addr = sK + r * 128 + ((((s << 5) + ((mi >> 1) << 4))) ^ ((r & 7) << 4));
                LDSM4(kb, addr);
                LDSM4(kbl, addr + 16384);
                MMA16816(facc[2 * g],     aq[s],  kb[0],  kb[2]);
                MMA16816(facc[2 * g + 1], aq[s],  kb[1],  kb[3]);
                MMA16816(facc[2 * g],     aql[s], kb[0],  kb[2]);
                MMA16816(facc[2 * g + 1], aql[s], kb[1],  kb[3]);
                MMA16816(facc[2 * g],     aq[s],  kbl[0], kbl[2]);
                MMA16816(facc[2 * g + 1], aq[s],  kbl[1], kbl[3]);
            }
        }
        const float scl = 0.125f;
        #pragma unroll
        for (int f = 0; f < 16; f++) {
            int c0 = f * 8 + 2 * (lane & 3);
            facc[f][0] *= scl; facc[f][1] *= scl;
            facc[f][2] *= scl; facc[f][3] *= scl;
            if (jt == qt) {
                if (c0     > myr0) facc[f][0] = -1e30f;
                if (c0 + 1 > myr0) facc[f][1] = -1e30f;
                if (c0     > myr1) facc[f][2] = -1e30f;
                if (c0 + 1 > myr1) facc[f][3] = -1e30f;
            }
        }
        float m0 = -1e30f, m1 = -1e30f;
        #pragma unroll
        for (int f = 0; f < 16; f++) {
            m0 = fmaxf(m0, fmaxf(facc[f][0], facc[f][1]));
            m1 = fmaxf(m1, fmaxf(facc[f][2], facc[f][3]));
        }
        m0 = fmaxf(m0, __shfl_xor_sync(0xffffffffu, m0, 1));
        m0 = fmaxf(m0, __shfl_xor_sync(0xffffffffu, m0, 2));
        m1 = fmaxf(m1, __shfl_xor_sync(0xffffffffu, m1, 1));
        m1 = fmaxf(m1, __shfl_xor_sync(0xffffffffu, m1, 2));
        float nm0 = fmaxf(mr0, m0), nm1 = fmaxf(mr1, m1);
        float al0 = __expf(mr0 - nm0), al1 = __expf(mr1 - nm1);
        mr0 = nm0; mr1 = nm1;
        #pragma unroll
        for (int f = 0; f < 8; f++) {
            oacc[f][0] *= al0; oacc[f][1] *= al0;
            oacc[f][2] *= al1; oacc[f][3] *= al1;
        }
        float s0 = 0.0f, s1 = 0.0f;
        uint32_t pah[8][4], pal[8][4];
        #pragma unroll
        for (int f = 0; f < 16; f++) {
            float p0 = __expf(facc[f][0] - nm0);
            float p1 = __expf(facc[f][1] - nm0);
            float p2 = __expf(facc[f][2] - nm1);
            float p3 = __expf(facc[f][3] - nm1);
            s0 += p0 + p1;
            s1 += p2 + p3;
            __nv_bfloat162 hp = __floats2bfloat162_rn(p0, p1);
            float2 hf = __bfloat1622float2(hp);
            __nv_bfloat162 lp = __floats2bfloat162_rn(p0 - hf.x, p1 - hf.y);
            __nv_bfloat162 hq = __floats2bfloat162_rn(p2, p3);
            float2 hg = __bfloat1622float2(hq);
            __nv_bfloat162 lq = __floats2bfloat162_rn(p2 - hg.x, p3 - hg.y);
            int ks = f >> 1, half = f & 1;
            pah[ks][2 * half]     = *reinterpret_cast<uint32_t*>(&hp);
            pah[ks][2 * half + 1] = *reinterpret_cast<uint32_t*>(&hq);
            pal[ks][2 * half]     = *reinterpret_cast<uint32_t*>(&lp);
            pal[ks][2 * half + 1] = *reinterpret_cast<uint32_t*>(&lq);
        }
        s0 += __shfl_xor_sync(0xffffffffu, s0, 1);
        s0 += __shfl_xor_sync(0xffffffffu, s0, 2);
        s1 += __shfl_xor_sync(0xffffffffu, s1, 1);
        s1 += __shfl_xor_sync(0xffffffffu, s1, 2);
        lr0 = lr0 * al0 + s0;
        lr1 = lr1 * al1 + s1;
        #pragma unroll
        for (int ks = 0; ks < 8; ks++) {
            #pragma unroll
            for (int g2 = 0; g2 < 4; g2++) {
                uint32_t vb[4], vbl[4];
                int r = g2 * 16 + rB;
                uint32_t addr = sV + r * 256 + ((((ks << 5) + ((mi >> 1) << 4))) ^ ((r & 7) << 4));
                LDSM4(vb, addr);
                LDSM4(vbl, addr + 16384);
                MMA16816(oacc[2 * g2],     pah[ks], vb[0],  vb[2]);
                MMA16816(oacc[2 * g2 + 1], pah[ks], vb[1],  vb[3]);
                MMA16816(oacc[2 * g2],     pal[ks], vb[0],  vb[2]);
                MMA16816(oacc[2 * g2 + 1], pal[ks], vb[1],  vb[3]);
                MMA16816(oacc[2 * g2],     pah[ks], vbl[0], vbl[2]);
                MMA16816(oacc[2 * g2 + 1], pah[ks], vbl[1], vbl[3]);
            }
        }
    }

    float inv0 = 1.0f / lr0, inv1 = 1.0f / lr1;
    size_t t0 = (size_t)(tokQ + myr0) * DMODEL + ho;
    size_t t1 = t0 + (size_t)8 * DMODEL;
    #pragma unroll
    for (int f = 0; f < 8; f++) {
        int dc = f * 8 + 2 * (lane & 3);
        float x0 = oacc[f][0] * inv0, x1 = oacc[f][1] * inv0;
        float x2 = oacc[f][2] * inv1, x3 = oacc[f][3] * inv1;
        __nv_bfloat162 h01 = __floats2bfloat162_rn(x0, x1);
        float2 hf = __bfloat1622float2(h01);
        __nv_bfloat162 l01 = __floats2bfloat162_rn(x0 - hf.x, x1 - hf.y);
        __nv_bfloat162 h23 = __floats2bfloat162_rn(x2, x3);
        float2 hg = __bfloat1622float2(h23);
        __nv_bfloat162 l23 = __floats2bfloat162_rn(x2 - hg.x, x3 - hg.y);
        *reinterpret_cast<uint32_t*>(ch + t0 + dc) = *reinterpret_cast<uint32_t*>(&h01);
        *reinterpret_cast<uint32_t*>(cl + t0 + dc) = *reinterpret_cast<uint32_t*>(&l01);
        *reinterpret_cast<uint32_t*>(ch + t1 + dc) = *reinterpret_cast<uint32_t*>(&h23);
        *reinterpret_cast<uint32_t*>(cl + t1 + dc) = *reinterpret_cast<uint32_t*>(&l23);
    }
}

// ---------------- weight transpose + split ----------------
__device__ __forceinline__ void transpose_split(const float* __restrict__ in,
        __nv_bfloat16* __restrict__ hi, __nv_bfloat16* __restrict__ lo, int K, int N) {
    __shared__ float t[32][33];
    int n0 = blockIdx.x << 5, k0 = blockIdx.y << 5;
    int tx = threadIdx.x, ty = threadIdx.y;
    #pragma unroll
    for (int r = 0; r < 4; r++)
        t[ty + 8 * r][tx] = in[(size_t)(k0 + ty + 8 * r) * N + n0 + tx];
    __syncthreads();
    #pragma unroll
    for (int r = 0; r < 4; r++) {
        float v = t[tx][ty + 8 * r];
        size_t o = (size_t)(n0 + ty + 8 * r) * K + k0 + tx;
        __nv_bfloat16 h = __float2bfloat16(v);
        hi[o] = h;
        lo[o] = __float2bfloat16(v - __bfloat162float(h));
    }
}
__global__ void wsplit_qkvo_k(const float* __restrict__ Wq, const float* __restrict__ Wk,
                              const float* __restrict__ Wv, const float* __restrict__ Wo,
                              __nv_bfloat16* __restrict__ wbuf) {
    int z = blockIdx.z, l = z >> 2, m = z & 3;
    const float* W = (m == 0 ? Wq : m == 1 ? Wk : m == 2 ? Wv : Wo) + (size_t)l * DDSZ;
    __nv_bfloat16* base = wbuf + (size_t)l * WL_STRIDE;
    transpose_split(W, base + (size_t)m * DDSZ, base + (size_t)(4 + m) * DDSZ, DMODEL, DMODEL);
}
__global__ void wsplit_w1_k(const float* __restrict__ W1, __nv_bfloat16* __restrict__ wbuf) {
    int l = blockIdx.z;
    __nv_bfloat16* hi = wbuf + (size_t)l * WL_STRIDE + QKVO_TOT;
    transpose_split(W1 + (size_t)l * DFSZ, hi, hi + DFSZ, DMODEL, FFDIM);
}
__global__ void wsplit_w2_k(const float* __restrict__ W2, __nv_bfloat16* __restrict__ wbuf) {
    int l = blockIdx.z;
    __nv_bfloat16* hi = wbuf + (size_t)l * WL_STRIDE + QKVO_TOT + 2 * (size_t)DFSZ;
    transpose_split(W2 + (size_t)l * DFSZ, hi, hi + DFSZ, FFDIM, DMODEL);
}
// token_emb -> fp16 (single precision copy for logits B operand)
__global__ __launch_bounds__(256) void embcvt_k(const float* __restrict__ te,
                                                __half* __restrict__ out) {
    size_t n4 = (size_t)VOCAB * DMODEL / 4;
    for (size_t i = (size_t)blockIdx.x * blockDim.x + threadIdx.x; i < n4;
         i += (size_t)gridDim.x * blockDim.x) {
        float4 v = reinterpret_cast<const float4*>(te)[i];
        __half2 a = __floats2half2_rn(v.x, v.y);
        __half2 b = __floats2half2_rn(v.z, v.w);
        uint2 o;
        o.x = *reinterpret_cast<uint32_t*>(&a);
        o.y = *reinterpret_cast<uint32_t*>(&b);
        reinterpret_cast<uint2*>(out)[i] = o;
    }
}

// ---------------- helpers ----------------
__device__ __forceinline__ int detect_i64(const void* p, int n) {
    const long long* x = (const long long*)p;
    int c = n < 32 ? n : 32;
    for (int i = 0; i < c; i++) {
        long long v = x[i];
        if (v < 0 || v >= VOCAB) return 0;
    }
    return 1;
}
__device__ __forceinline__ long long load_index(const void* p, int i, int is64) {
    return is64 ? ((const long long*)p)[i] : (long long)((const int*)p)[i];
}

// ---------------- embedding (+ folded qkv bias concat) ----------------
__global__ __launch_bounds__(256) void embed_k(const void* __restrict__ xr,
                                               const float* __restrict__ te,
                                               const float* __restrict__ pe,
                                               float* __restrict__ h,
                                               const float* __restrict__ bq,
                                               const float* __restrict__ bk,
                                               const float* __restrict__ bv,
                                               float* __restrict__ bqkv) {
    __shared__ int mode;
    if (threadIdx.x == 0) mode = detect_i64(xr, BS);
    __syncthreads();
    int pos = blockIdx.x;
    int tid = threadIdx.x;
    if (pos < NLAYER) {
        #pragma unroll
        for (int t = tid; t < DMODEL; t += 256) {
            bqkv[pos * QKVS + t]        = bq[pos * DMODEL + t];
            bqkv[pos * QKVS + 512 + t]  = bk[pos * DMODEL + t];
            bqkv[pos * QKVS + 1024 + t] = bv[pos * DMODEL + t];
        }
    }
    long long idx = load_index(xr, pos, mode);
    int s = pos & (SEQ - 1);
    const float* t = te + idx * DMODEL;
    const float* p = pe + (long long)s * DMODEL;
    float* o = h + (long long)pos * DMODEL;
    o[tid]       = t[tid]       + p[tid];
    o[tid + 256] = t[tid + 256] + p[tid + 256];
}

// ---------------- layernorm -> bf16 split (MODE 0) or fp16 single (MODE 1) ----------------
template <int MODE>
__global__ __launch_bounds__(256) void ln_k(const float* __restrict__ in,
                                            const float* __restrict__ g,
                                            const float* __restrict__ b,
                                            __nv_bfloat16* __restrict__ oh,
                                            __nv_bfloat16* __restrict__ ol,
                                            __half* __restrict__ of) {
    int row = blockIdx.x;
    int tid = threadIdx.x;
    int lane = tid & 31, wid = tid >> 5;
    const float* x = in + (long long)row * DMODEL;
    float v0 = x[tid], v1 = x[tid + 256];
    __shared__ float wr[16];
    float s = v0 + v1;
    #pragma unroll
    for (int o = 16; o; o >>= 1) s += __shfl_xor_sync(0xffffffffu, s, o);
    if (lane == 0) wr[wid] = s;
    __syncthreads();
    float mu = (wr[0] + wr[1] + wr[2] + wr[3] + wr[4] + wr[5] + wr[6] + wr[7]) * (1.0f / DMODEL);
    float d0 = v0 - mu, d1 = v1 - mu;
    float q = d0 * d0 + d1 * d1;
    #pragma unroll
    for (int o = 16; o; o >>= 1) q += __shfl_xor_sync(0xffffffffu, q, o);
    if (lane == 0) wr[8 + wid] = q;
    __syncthreads();
    float var = (wr[8] + wr[9] + wr[10] + wr[11] + wr[12] + wr[13] + wr[14] + wr[15]) * (1.0f / DMODEL);
    float rstd = rsqrtf(var + 1e-5f);
    long long base = (long long)row * DMODEL;
    float y0 = d0 * rstd * g[tid] + b[tid];
    float y1 = d1 * rstd * g[tid + 256] + b[tid + 256];
    if (MODE == 0) {
        __nv_bfloat16 h0 = __float2bfloat16(y0);
        __nv_bfloat16 h1 = __float2bfloat16(y1);
        oh[base + tid] = h0;
        ol[base + tid] = __float2bfloat16(y0 - __bfloat162float(h0));
        oh[base + tid + 256] = h1;
        ol[base + tid + 256] = __float2bfloat16(y1 - __bfloat162float(h1));
    } else {
        of[base + tid]       = __float2half_rn(y0);
        of[base + tid + 256] = __float2half_rn(y1);
    }
}

// ---------------- single-pass cross-entropy ----------------
__global__ __launch_bounds__(256) void loss_row_k(const float* __restrict__ logits,
                                                  const void* __restrict__ tr,
                                                  float* __restrict__ rowloss) {
    __shared__ int mode;
    __shared__ float rm[256], rs[256];
    int row = blockIdx.x, tid = threadIdx.x;
    if (tid == 0) mode = detect_i64(tr, BS);
    __syncthreads();
    const float* lr = logits + (long long)row * VOCAB;
    float m = -1e30f, s = 0.0f;
    for (int j = tid; j < VOCAB; j += 256) {
        float v = lr[j];
        float nm = fmaxf(m, v);
        s = s * __expf(m - nm) + __expf(v - nm);
        m = nm;
    }
    rm[tid] = m;
    rs[tid] = s;
    __syncthreads();
    #pragma unroll
    for (int st = 128; st > 0; st >>= 1) {
        if (tid < st) {
            float ma = rm[tid], mb = rm[tid + st];
            float nm = fmaxf(ma, mb);
            rs[tid] = rs[tid] * __expf(ma - nm) + rs[tid + st] * __expf(mb - nm);
            rm[tid] = nm;
        }
        __syncthreads();
    }
    if (tid == 0) {
        long long t = load_index(tr, row, mode);
        rowloss[row] = -(lr[t] - rm[0] - logf(rs[0]));
    }
}

__global__ __launch_bounds__(1024) void loss_reduce_k(const float* __restrict__ rowloss,
                                                      float* __restrict__ out) {
    __shared__ float red[1024];
    int tid = threadIdx.x;
    red[tid] = rowloss[tid] + rowloss[tid + 1024] + rowloss[tid + 2048] + rowloss[tid + 3072];
    __syncthreads();
    #pragma unroll
    for (int s = 512; s > 0; s >>= 1) {
        if (tid < s) red[tid] += red[tid + s];
        __syncthreads();
    }
    if (tid == 0) out[0] = red[0] * (1.0f / BS);
}

// ---------------- host launcher ----------------
extern "C" void kernel_launch(void* const* d_in, const int* in_sizes, int n_in,
                              void* d_out, int out_size) {
    (void)in_sizes; (void)n_in;
    const void*  x       = d_in[0];
    const void*  targets = d_in[1];
    const float* te   = (const float*)d_in[2];
    const float* pe   = (const float*)d_in[3];
    const float* ln1g = (const float*)d_in[4];
    const float* ln1b = (const float*)d_in[5];
    const float* Wq   = (const float*)d_in[6];
    const float* bq   = (const float*)d_in[7];
    const float* Wk   = (const float*)d_in[8];
    const float* bk   = (const float*)d_in[9];
    const float* Wv   = (const float*)d_in[10];
    const float* bv   = (const float*)d_in[11];
    const float* Wo   = (const float*)d_in[12];
    const float* bo   = (const float*)d_in[13];
    const float* ln2g = (const float*)d_in[14];
    const float* ln2b = (const float*)d_in[15];
    const float* W1   = (const float*)d_in[16];
    const float* b1   = (const float*)d_in[17];
    const float* W2   = (const float*)d_in[18];
    const float* b2   = (const float*)d_in[19];
    const float* lnfg = (const float*)d_in[20];
    const float* lnfb = (const float*)d_in[21];
    float* out = (float*)d_out;

    float *p_h, *p_rowloss, *p_logits, *p_bqkv;
    __nv_bfloat16 *p_xnh, *p_xnl, *p_qkvh, *p_qkvl;
    __nv_bfloat16 *p_ctxh, *p_ctxl, *p_ffh, *p_ffl, *p_wbuf;
    __half *p_xnf, *p_embf;
    cudaGetSymbolAddress((void**)&p_h, g_h);
    cudaGetSymbolAddress((void**)&p_rowloss, g_rowloss);
    cudaGetSymbolAddress((void**)&p_logits, g_logits_scratch);
    cudaGetSymbolAddress((void**)&p_bqkv, g_bqkv);
    cudaGetSymbolAddress((void**)&p_xnh, g_xnh);
    cudaGetSymbolAddress((void**)&p_xnl, g_xnl);
    cudaGetSymbolAddress((void**)&p_xnf, g_xnf);
    cudaGetSymbolAddress((void**)&p_qkvh, g_qkvh);
    cudaGetSymbolAddress((void**)&p_qkvl, g_qkvl);
    cudaGetSymbolAddress((void**)&p_ctxh, g_ctxh);
    cudaGetSymbolAddress((void**)&p_ctxl, g_ctxl);
    cudaGetSymbolAddress((void**)&p_ffh, g_ffh);
    cudaGetSymbolAddress((void**)&p_ffl, g_ffl);
    cudaGetSymbolAddress((void**)&p_wbuf, g_wbuf);
    cudaGetSymbolAddress((void**)&p_embf, g_embf);

    cudaFuncSetAttribute(gemm_bf<1>, cudaFuncAttributeMaxDynamicSharedMemorySize, GEMM_SMEM);
    cudaFuncSetAttribute(gemm_bf<2>, cudaFuncAttributeMaxDynamicSharedMemorySize, GEMM_SMEM);
    cudaFuncSetAttribute(gemm_bf<4>, cudaFuncAttributeMaxDynamicSharedMemorySize, GEMM_SMEM);
    cudaFuncSetAttribute(gemm_f16,   cudaFuncAttributeMaxDynamicSharedMemorySize, GEMM_SMEM_F);
    cudaFuncSetAttribute(fattn_k, cudaFuncAttributeMaxDynamicSharedMemorySize, ATT_SMEM);

    // launch order matters for ncu (-s 5 -c 1 captures launch #6 = first QKV GEMM)
    wsplit_qkvo_k<<<dim3(16, 16, 24), dim3(32, 8)>>>(Wq, Wk, Wv, Wo, p_wbuf);   // 1
    wsplit_w1_k<<<dim3(64, 16, 6), dim3(32, 8)>>>(W1, p_wbuf);                  // 2
    wsplit_w2_k<<<dim3(16, 64, 6), dim3(32, 8)>>>(W2, p_wbuf);                  // 3
    embed_k<<<BS, 256>>>(x, te, pe, p_h, bq, bk, bv, p_bqkv);                   // 4

    dim3 gDD(BS / 128, DMODEL / 128);
    dim3 gQKV(BS / 128, QKVS / 128);
    dim3 gDF(BS / 128, FFDIM / 128);
    dim3 gATT(SEQ / 128, BATCH * NHEAD);

    for (int l = 0; l < NLAYER; l++) {
        __nv_bfloat16* wl = p_wbuf + (size_t)l * WL_STRIDE;
        __nv_bfloat16* w1h = wl + QKVO_TOT;
        __nv_bfloat16* w2h = wl + QKVO_TOT + 2 * (size_t)DFSZ;

        ln_k<0><<<BS, 256>>>(p_h, ln1g + l * DMODEL, ln1b + l * DMODEL, p_xnh, p_xnl, nullptr);
        gemm_bf<4><<<gQKV, 256, GEMM_SMEM>>>(p_xnh, p_xnl, wl, wl + 4 * (size_t)DDSZ,
                                             p_bqkv + l * QKVS, nullptr, nullptr,
                                             p_qkvh, p_qkvl, BS, QKVS, DMODEL);
        fattn_k<<<gATT, 256, ATT_SMEM>>>(p_qkvh, p_qkvl, p_ctxh, p_ctxl);
        gemm_bf<1><<<gDD, 256, GEMM_SMEM>>>(p_ctxh, p_ctxl, wl + 3 * (size_t)DDSZ,
                                            wl + 7 * (size_t)DDSZ, bo + l * DMODEL,
                                            p_h, p_h, nullptr, nullptr, BS, DMODEL, DMODEL);
        ln_k<0><<<BS, 256>>>(p_h, ln2g + l * DMODEL, ln2b + l * DMODEL, p_xnh, p_xnl, nullptr);
        gemm_bf<2><<<gDF, 256, GEMM_SMEM>>>(p_xnh, p_xnl, w1h, w1h + DFSZ, b1 + l * FFDIM,
                                            nullptr, nullptr, p_ffh, p_ffl, BS, FFDIM, DMODEL);
        gemm_bf<1><<<gDD, 256, GEMM_SMEM>>>(p_ffh, p_ffl, w2h, w2h + DFSZ, b2 + l * DMODEL,
                                            p_h, p_h, nullptr, nullptr, BS, DMODEL, FFDIM);
    }

    ln_k<1><<<BS, 256>>>(p_h, lnfg, lnfb, nullptr, nullptr, p_xnf);
    embcvt_k<<<2048, 256>>>(te, p_embf);

    float* logits = ((long long)out_size >= NLOG) ? out : p_logits;
    dim3 gLOG(BS / 128, VPAD / 128);   // (32, 393)
    gemm_f16<<<gLOG, 256, GEMM_SMEM_F>>>(p_xnf, p_embf, logits, BS, VOCAB, DMODEL);

    loss_row_k<<<BS, 256>>>(logits, targets, p_rowloss);
    if ((long long)out_size > NLOG) {
        loss_reduce_k<<<1, 1024>>>(p_rowloss, out + NLOG);
    } else if ((long long)out_size < NLOG && out_size >= 1) {
        loss_reduce_k<<<1, 1024>>>(p_rowloss, out + (out_size - 1));
    }
}

// round 8
// speedup vs baseline: 1.9042x; 1.4647x over previous
#include <cuda_runtime.h>
#include <cuda_bf16.h>
#include <cuda_fp16.h>
#include <math.h>
#include <stdint.h>

// ---------------- model constants ----------------
#define BATCH  8
#define SEQ    512
#define DMODEL 512
#define NHEAD  8
#define HEADD  64
#define FFDIM  2048
#define NLAYER 6
#define VOCAB  50257
#define VPAD   50304                  // 393*128
#define BS     (BATCH*SEQ)
#define QKVS   1536
static const long long NLOG = (long long)BS * VOCAB;

#define DDSZ   (DMODEL*DMODEL)
#define DFSZ   (DMODEL*FFDIM)

// ---------------- device scratch ----------------
__device__ float g_h[BS * DMODEL];
__device__ float g_rowloss[BS];
__device__ float g_bqkv[NLAYER * QKVS];
__device__ float g_logits_scratch[(size_t)BS * VOCAB];
__device__ __nv_bfloat16 g_xnh[BS * DMODEL];
__device__ __nv_bfloat16 g_xnl[BS * DMODEL];
__device__ __half g_xnf[BS * DMODEL];
__device__ __nv_bfloat16 g_qkvh[BS * QKVS];
__device__ __nv_bfloat16 g_qkvl[BS * QKVS];
__device__ __half g_ctxf[BS * DMODEL];
__device__ __half g_fff[BS * FFDIM];
__device__ __nv_bfloat16 g_wqkv[(size_t)6 * DDSZ * NLAYER];   // per layer: [q k v]hi [q k v]lo
__device__ __half g_wof[(size_t)DDSZ * NLAYER];
__device__ __half g_w1f[(size_t)DFSZ * NLAYER];
__device__ __half g_w2f[(size_t)DFSZ * NLAYER];
__device__ __half g_embf[(size_t)VPAD * DMODEL];

// ================= PTX helpers =================
__device__ __forceinline__ uint32_t smem_to_u32(const void* smem_ptr) {
    uint32_t addr;
    asm("{ .reg .u64 tmp; cvta.to.shared.u64 tmp, %1; cvt.u32.u64 %0, tmp; }"
        : "=r"(addr) : "l"(smem_ptr));
    return addr;
}
__device__ __forceinline__ void cp16(uint32_t d, const void* s, int sz) {
    asm volatile("cp.async.cg.shared.global [%0], [%1], 16, %2;\n"
                 :: "r"(d), "l"(s), "r"(sz) : "memory");
}
__device__ __forceinline__ void cp_commit() {
    asm volatile("cp.async.commit_group;\n" ::: "memory");
}
__device__ __forceinline__ void cp_wait0() {
    asm volatile("cp.async.wait_group 0;\n" ::: "memory");
}
__device__ __forceinline__ void cp_wait1() {
    asm volatile("cp.async.wait_group 1;\n" ::: "memory");
}
#define LDSM4(r, addr) \
    asm volatile("ldmatrix.sync.aligned.m8n8.x4.shared.b16 {%0,%1,%2,%3}, [%4];" \
        : "=r"((r)[0]), "=r"((r)[1]), "=r"((r)[2]), "=r"((r)[3]) : "r"(addr))
#define MMA16816(c, a, b0, b1) \
    asm volatile("mma.sync.aligned.m16n8k16.row.col.f32.bf16.bf16.f32 " \
        "{%0,%1,%2,%3}, {%4,%5,%6,%7}, {%8,%9}, {%0,%1,%2,%3};" \
        : "+f"((c)[0]), "+f"((c)[1]), "+f"((c)[2]), "+f"((c)[3]) \
        : "r"((a)[0]), "r"((a)[1]), "r"((a)[2]), "r"((a)[3]), "r"(b0), "r"(b1))
#define MMAF16(c, a, b0, b1) \
    asm volatile("mma.sync.aligned.m16n8k16.row.col.f32.f16.f16.f32 " \
        "{%0,%1,%2,%3}, {%4,%5,%6,%7}, {%8,%9}, {%0,%1,%2,%3};" \
        : "+f"((c)[0]), "+f"((c)[1]), "+f"((c)[2]), "+f"((c)[3]) \
        : "r"((a)[0]), "r"((a)[1]), "r"((a)[2]), "r"((a)[3]), "r"(b0), "r"(b1))

// ================= bf16 3-pass GEMM (QKV only): bias -> bf16 split out =================
#define TB 16384
#define STAGE_BYTES (4*TB)
#define SMEM_OFF 1024
#define GEMM_SMEM (SMEM_OFF + 2*STAGE_BYTES)

__device__ __forceinline__ void copy_stage(uint32_t st,
        const __nv_bfloat16* __restrict__ Ahi, const __nv_bfloat16* __restrict__ Alo,
        const __nv_bfloat16* __restrict__ Bhi, const __nv_bfloat16* __restrict__ Blo,
        int bm, int bn, int k0, int K, int tid) {
    #pragma unroll
    for (int it = 0; it < 4; it++) {
        int idx = tid + it * 256;
        int row = idx >> 3, c = idx & 7;
        uint32_t d = st + row * 128 + ((c ^ (row & 7)) << 4);
        size_t so = (size_t)(bm + row) * K + k0 + c * 8;
        cp16(d, Ahi + so, 16);
        cp16(d + TB, Alo + so, 16);
    }
    #pragma unroll
    for (int it = 0; it < 4; it++) {
        int idx = tid + it * 256;
        int row = idx >> 3, c = idx & 7;
        uint32_t d = st + 2 * TB + row * 128 + ((c ^ (row & 7)) << 4);
        size_t so = (size_t)(bn + row) * K + k0 + c * 8;
        cp16(d, Bhi + so, 16);
        cp16(d + TB, Blo + so, 16);
    }
}

__global__ void __launch_bounds__(256, 1)
gemm_qkv(const __nv_bfloat16* __restrict__ Ahi, const __nv_bfloat16* __restrict__ Alo,
         const __nv_bfloat16* __restrict__ Bhi, const __nv_bfloat16* __restrict__ Blo,
         const float* __restrict__ bias,
         __nv_bfloat16* __restrict__ Chi, __nv_bfloat16* __restrict__ Clo,
         int N, int K) {
    extern __shared__ char smem[];
    const int tid = threadIdx.x;
    const int bm = blockIdx.x * 128;
    const int bn = blockIdx.y * 128;
    const int nc = K >> 6;

    const uint32_t tiles = smem_to_u32(smem) + SMEM_OFF;
    const int lane = tid & 31;
    const int wid = tid >> 5;
    const int wm = (wid & 3) << 5;
    const int wn = (wid >> 2) << 6;
    const int mi = lane >> 3;
    const int lrow = lane & 7;

    float acc[2][8][4];
    #pragma unroll
    for (int i = 0; i < 2; i++)
        #pragma unroll
        for (int j = 0; j < 8; j++)
            #pragma unroll
            for (int t = 0; t < 4; t++) acc[i][j][t] = 0.0f;

    copy_stage(tiles, Ahi, Alo, Bhi, Blo, bm, bn, 0, K, tid);
    cp_commit();

    for (int c = 0; c < nc; c++) {
        if (c + 1 < nc) {
            copy_stage(tiles + ((c + 1) & 1) * STAGE_BYTES, Ahi, Alo, Bhi, Blo,
                       bm, bn, (c + 1) << 6, K, tid);
            cp_commit();
            cp_wait1();
        } else {
            cp_wait0();
        }
        __syncthreads();

        const uint32_t st = tiles + (c & 1) * STAGE_BYTES;
        #pragma unroll
        for (int s = 0; s < 4; s++) {
            const int cb = (s << 5) + ((mi >> 1) << 4);
            uint32_t ahi[2][4], alo[2][4], bhi[4][4], blo[4][4];
            #pragma unroll
            for (int i = 0; i < 2; i++) {
                int r = wm + (i << 4) + ((mi & 1) << 3) + lrow;
                uint32_t a = st + r * 128 + (cb ^ ((r & 7) << 4));
                LDSM4(ahi[i], a);
                LDSM4(alo[i], a + TB);
            }
            #pragma unroll
            for (int j2 = 0; j2 < 4; j2++) {
                int r = wn + (j2 << 4) + ((mi & 1) << 3) + lrow;
                uint32_t a = st + 2 * TB + r * 128 + (cb ^ ((r & 7) << 4));
                LDSM4(bhi[j2], a);
                LDSM4(blo[j2], a + TB);
            }
            #pragma unroll
            for (int i = 0; i < 2; i++)
                #pragma unroll
                for (int j2 = 0; j2 < 4; j2++) {
                    MMA16816(acc[i][2 * j2],     ahi[i], bhi[j2][0], bhi[j2][2]);
                    MMA16816(acc[i][2 * j2 + 1], ahi[i], bhi[j2][1], bhi[j2][3]);
                }
            #pragma unroll
            for (int i = 0; i < 2; i++)
                #pragma unroll
                for (int j2 = 0; j2 < 4; j2++) {
                    MMA16816(acc[i][2 * j2],     alo[i], bhi[j2][0], bhi[j2][2]);
                    MMA16816(acc[i][2 * j2 + 1], alo[i], bhi[j2][1], bhi[j2][3]);
                }
            #pragma unroll
            for (int i = 0; i < 2; i++)
                #pragma unroll
                for (int j2 = 0; j2 < 4; j2++) {
                    MMA16816(acc[i][2 * j2],     ahi[i], blo[j2][0], blo[j2][2]);
                    MMA16816(acc[i][2 * j2 + 1], ahi[i], blo[j2][1], blo[j2][3]);
                }
        }
        __syncthreads();
    }

    #pragma unroll
    for (int i = 0; i < 2; i++) {
        int row = bm + wm + (i << 4) + (lane >> 2);
        size_t base = (size_t)row * N;
        size_t base8 = base + (size_t)8 * N;
        #pragma unroll
        for (int j = 0; j < 8; j++) {
            int col = bn + wn + (j << 3) + ((lane & 3) << 1);
            #pragma unroll
            for (int t = 0; t < 4; t++) {
                size_t off = (t < 2 ? base : base8) + col + (t & 1);
                float x = acc[i][j][t] + __ldg(bias + col + (t & 1));
                __nv_bfloat16 h = __float2bfloat16(x);
                Chi[off] = h;
                Clo[off] = __float2bfloat16(x - __bfloat162float(h));
            }
        }
    }
}

// ================= fp16 single-pass GEMM =================
// EPI: 0 = plain f32 (logits, N-guarded); 1 = bias+gelu -> fp16; 2 = bias+res -> f32
#define FSTAGE (2*TB)
#define GEMM_SMEM_F (SMEM_OFF + 2*FSTAGE)

__device__ __forceinline__ void copy_stage_f(uint32_t st,
        const __half* __restrict__ A, const __half* __restrict__ B,
        int bm, int bn, int k0, int K, int N, int tid) {
    #pragma unroll
    for (int it = 0; it < 4; it++) {
        int idx = tid + it * 256;
        int row = idx >> 3, c = idx & 7;
        uint32_t d = st + row * 128 + ((c ^ (row & 7)) << 4);
        size_t so = (size_t)(bm + row) * K + k0 + c * 8;
        cp16(d, A + so, 16);
    }
    #pragma unroll
    for (int it = 0; it < 4; it++) {
        int idx = tid + it * 256;
        int row = idx >> 3, c = idx & 7;
        int n = bn + row;
        int sz = (n < N) ? 16 : 0;
        uint32_t d = st + TB + row * 128 + ((c ^ (row & 7)) << 4);
        size_t so = (size_t)n * K + k0 + c * 8;
        cp16(d, B + so, sz);
    }
}

template <int EPI>
__global__ void __launch_bounds__(256, 1)
gemm_f16(const __half* __restrict__ A, const __half* __restrict__ B,
         const float* __restrict__ bias, const float* __restrict__ res,
         float* __restrict__ C, __half* __restrict__ Cf,
         int M, int N, int K) {
    extern __shared__ char smem[];
    const int tid = threadIdx.x;
    const int bm = blockIdx.x * 128;
    const int bn = blockIdx.y * 128;
    const int nc = K >> 6;

    const uint32_t tiles = smem_to_u32(smem) + SMEM_OFF;
    const int lane = tid & 31;
    const int wid = tid >> 5;
    const int wm = (wid & 3) << 5;
    const int wn = (wid >> 2) << 6;
    const int mi = lane >> 3;
    const int lrow = lane & 7;

    float acc[2][8][4];
    #pragma unroll
    for (int i = 0; i < 2; i++)
        #pragma unroll
        for (int j = 0; j < 8; j++)
            #pragma unroll
            for (int t = 0; t < 4; t++) acc[i][j][t] = 0.0f;

    copy_stage_f(tiles, A, B, bm, bn, 0, K, N, tid);
    cp_commit();

    for (int c = 0; c < nc; c++) {
        if (c + 1 < nc) {
            copy_stage_f(tiles + ((c + 1) & 1) * FSTAGE, A, B, bm, bn, (c + 1) << 6, K, N, tid);
            cp_commit();
            cp_wait1();
        } else {
            cp_wait0();
        }
        __syncthreads();

        const uint32_t st = tiles + (c & 1) * FSTAGE;
        #pragma unroll
        for (int s = 0; s < 4; s++) {
            const int cb = (s << 5) + ((mi >> 1) << 4);
            uint32_t af[2][4], bf[4][4];
            #pragma unroll
            for (int i = 0; i < 2; i++) {
                int r = wm + (i << 4) + ((mi & 1) << 3) + lrow;
                LDSM4(af[i], st + r * 128 + (cb ^ ((r & 7) << 4)));
            }
            #pragma unroll
            for (int j2 = 0; j2 < 4; j2++) {
                int r = wn + (j2 << 4) + ((mi & 1) << 3) + lrow;
                LDSM4(bf[j2], st + TB + r * 128 + (cb ^ ((r & 7) << 4)));
            }
            #pragma unroll
            for (int i = 0; i < 2; i++)
                #pragma unroll
                for (int j2 = 0; j2 < 4; j2++) {
                    MMAF16(acc[i][2 * j2],     af[i], bf[j2][0], bf[j2][2]);
                    MMAF16(acc[i][2 * j2 + 1], af[i], bf[j2][1], bf[j2][3]);
                }
        }
        __syncthreads();
    }

    #pragma unroll
    for (int i = 0; i < 2; i++) {
        int row = bm + wm + (i << 4) + (lane >> 2);
        size_t base = (size_t)row * N;
        size_t base8 = base + (size_t)8 * N;
        #pragma unroll
        for (int j = 0; j < 8; j++) {
            int col = bn + wn + (j << 3) + ((lane & 3) << 1);
            #pragma unroll
            for (int t = 0; t < 4; t++) {
                int cc = col + (t & 1);
                if (EPI == 0 && cc >= N) continue;
                size_t off = (t < 2 ? base : base8) + cc;
                float x = acc[i][j][t];
                if (EPI == 1 || EPI == 2) x += __ldg(bias + cc);
                if (EPI == 1) {
                    x = 0.5f * x * (1.0f + erff(x * 0.70710678118654752440f));
                    Cf[off] = __float2half_rn(x);
                } else if (EPI == 2) {
                    C[off] = x + res[off];
                } else {
                    C[off] = x;
                }
            }
        }
    }
}

// ---------------- flash attention (bf16 3-pass internals, fp16 out) ----------------
#define ATT_SMEM (6*16384)
__global__ void __launch_bounds__(256, 1)
fattn_k(const __nv_bfloat16* __restrict__ qkvh, const __nv_bfloat16* __restrict__ qkvl,
        __half* __restrict__ cf) {
    extern __shared__ char smx[];
    const uint32_t sQ = smem_to_u32(smx);
    const uint32_t sK = sQ + 2 * 16384;
    const uint32_t sV = sQ + 4 * 16384;
    const int tid = threadIdx.x;
    const int lane = tid & 31, wid = tid >> 5;
    const int qt = blockIdx.x;
    const int bh = blockIdx.y;
    const int b = bh >> 3, h = bh & 7;
    const int tokQ = b * SEQ + qt * 128;
    const int ho = h * HEADD;
    const int mi = lane >> 3, lrow = lane & 7;
    const int wm = wid * 16;
    const int rB = ((mi & 1) << 3) + lrow;

    #pragma unroll
    for (int it = 0; it < 4; it++) {
        int idx = tid + it * 256;
        int r = idx >> 3, c = idx & 7;
        uint32_t d = sQ + r * 128 + ((c ^ (r & 7)) << 4);
        size_t so = (size_t)(tokQ + r) * QKVS + ho + c * 8;
        cp16(d, qkvh + so, 16);
        cp16(d + 16384, qkvl + so, 16);
    }
    cp_commit();
    cp_wait0();
    __syncthreads();

    uint32_t aq[4][4], aql[4][4];
    {
        int r = wm + rB;
        #pragma unroll
        for (int s = 0; s < 4; s++) {
            uint32_t addr = sQ + r * 128 + ((((s << 5) + ((mi >> 1) << 4))) ^ ((r & 7) << 4));
            LDSM4(aq[s], addr);
            LDSM4(aql[s], addr + 16384);
        }
    }

    float oacc[8][4];
    #pragma unroll
    for (int f = 0; f < 8; f++)
        #pragma unroll
        for (int t = 0; t < 4; t++) oacc[f][t] = 0.0f;
    float mr0 = -1e30f, mr1 = -1e30f, lr0 = 0.0f, lr1 = 0.0f;
    const int myr0 = wm + (lane >> 2);
    const int myr1 = myr0 + 8;

    for (int jt = 0; jt <= qt; jt++) {
        __syncthreads();
        const int tokJ = b * SEQ + jt * 128;
        #pragma unroll
        for (int it = 0; it < 4; it++) {
            int idx = tid + it * 256;
            int r = idx >> 3, c = idx & 7;
            uint32_t d = sK + r * 128 + ((c ^ (r & 7)) << 4);
            size_t so = (size_t)(tokJ + r) * QKVS + 512 + ho + c * 8;
            cp16(d, qkvh + so, 16);
            cp16(d + 16384, qkvl + so, 16);
        }
        #pragma unroll
        for (int it = 0; it < 4; it++) {
            int task = tid + it * 256;
            int j = task >> 3, c = task & 7;
            size_t so = (size_t)(tokJ + j) * QKVS + 1024 + ho + c * 8;
            uint4 v4h = *reinterpret_cast<const uint4*>(qkvh + so);
            uint4 v4l = *reinterpret_cast<const uint4*>(qkvl + so);
            const uint32_t* wh = &v4h.x;
            const uint32_t* wl = &v4l.x;
            #pragma unroll
            for (int i = 0; i < 8; i++) {
                int dd = c * 8 + i;
                uint32_t off = dd * 256 + ((((uint32_t)(j >> 3) ^ (uint32_t)(dd & 7)) << 4)) + (j & 7) * 2;
                uint16_t hv = (uint16_t)(wh[i >> 1] >> ((i & 1) * 16));
                uint16_t lv = (uint16_t)(wl[i >> 1] >> ((i & 1) * 16));
                asm volatile("st.shared.u16 [%0], %1;" :: "r"(sV + off), "h"(hv));
                asm volatile("st.shared.u16 [%0], %1;" :: "r"(sV + 16384 + off), "h"(lv));
            }
        }
        cp_commit();
        cp_wait0();
        __syncthreads();

        float facc[16][4];
        #pragma unroll
        for (int f = 0; f < 16; f++)
            #pragma unroll
            for (int t = 0; t < 4; t++) facc[f][t] = 0.0f;
        #pragma unroll
        for (int g = 0; g < 8; g++) {
            int r = g * 16 + rB;
            #pragma unroll
            for (int s = 0; s < 4; s++) {
                uint32_t kb[4], kbl[4];
                uint32_t addr = sK + r * 128 + ((((s << 5) + ((mi >> 1) << 4))) ^ ((r & 7) << 4));
                LDSM4(kb, addr);
                LDSM4(kbl, addr + 16384);
                MMA16816(facc[2 * g],     aq[s],  kb[0],  kb[2]);
                MMA16816(facc[2 * g + 1], aq[s],  kb[1],  kb[3]);
                MMA16816(facc[2 * g],     aql[s], kb[0],  kb[2]);
                MMA16816(facc[2 * g + 1], aql[s], kb[1],  kb[3]);
                MMA16816(facc[2 * g],     aq[s],  kbl[0], kbl[2]);
                MMA16816(facc[2 * g + 1], aq[s],  kbl[1], kbl[3]);
            }
        }
        const float scl = 0.125f;
        #pragma unroll
        for (int f = 0; f < 16; f++) {
            int c0 = f * 8 + 2 * (lane & 3);
            facc[f][0] *= scl; facc[f][1] *= scl;
            facc[f][2] *= scl; facc[f][3] *= scl;
            if (jt == qt) {
                if (c0     > myr0) facc[f][0] = -1e30f;
                if (c0 + 1 > myr0) facc[f][1] = -1e30f;
                if (c0     > myr1) facc[f][2] = -1e30f;
                if (c0 + 1 > myr1) facc[f][3] = -1e30f;
            }
        }
        float m0 = -1e30f, m1 = -1e30f;
        #pragma unroll
        for (int f = 0; f < 16; f++) {
            m0 = fmaxf(m0, fmaxf(facc[f][0], facc[f][1]));
            m1 = fmaxf(m1, fmaxf(facc[f][2], facc[f][3]));
        }
        m0 = fmaxf(m0, __shfl_xor_sync(0xffffffffu, m0, 1));
        m0 = fmaxf(m0, __shfl_xor_sync(0xffffffffu, m0, 2));
        m1 = fmaxf(m1, __shfl_xor_sync(0xffffffffu, m1, 1));
        m1 = fmaxf(m1, __shfl_xor_sync(0xffffffffu, m1, 2));
        float nm0 = fmaxf(mr0, m0), nm1 = fmaxf(mr1, m1);
        float al0 = __expf(mr0 - nm0), al1 = __expf(mr1 - nm1);
        mr0 = nm0; mr1 = nm1;
        #pragma unroll
        for (int f = 0; f < 8; f++) {
            oacc[f][0] *= al0; oacc[f][1] *= al0;
            oacc[f][2] *= al1; oacc[f][3] *= al1;
        }
        float s0 = 0.0f, s1 = 0.0f;
        uint32_t pah[8][4], pal[8][4];
        #pragma unroll
        for (int f = 0; f < 16; f++) {
            float p0 = __expf(facc[f][0] - nm0);
            float p1 = __expf(facc[f][1] - nm0);
            float p2 = __expf(facc[f][2] - nm1);
            float p3 = __expf(facc[f][3] - nm1);
            s0 += p0 + p1;
            s1 += p2 + p3;
            __nv_bfloat162 hp = __floats2bfloat162_rn(p0, p1);
            float2 hf = __bfloat1622float2(hp);
            __nv_bfloat162 lp = __floats2bfloat162_rn(p0 - hf.x, p1 - hf.y);
            __nv_bfloat162 hq = __floats2bfloat162_rn(p2, p3);
            float2 hg = __bfloat1622float2(hq);
            __nv_bfloat162 lq = __floats2bfloat162_rn(p2 - hg.x, p3 - hg.y);
            int ks = f >> 1, half = f & 1;
            pah[ks][2 * half]     = *reinterpret_cast<uint32_t*>(&hp);
            pah[ks][2 * half + 1] = *reinterpret_cast<uint32_t*>(&hq);
            pal[ks][2 * half]     = *reinterpret_cast<uint32_t*>(&lp);
            pal[ks][2 * half + 1] = *reinterpret_cast<uint32_t*>(&lq);
        }
        s0 += __shfl_xor_sync(0xffffffffu, s0, 1);
        s0 += __shfl_xor_sync(0xffffffffu, s0, 2);
        s1 += __shfl_xor_sync(0xffffffffu, s1, 1);
        s1 += __shfl_xor_sync(0xffffffffu, s1, 2);
        lr0 = lr0 * al0 + s0;
        lr1 = lr1 * al1 + s1;
        #pragma unroll
        for (int ks = 0; ks < 8; ks++) {
            #pragma unroll
            for (int g2 = 0; g2 < 4; g2++) {
                uint32_t vb[4], vbl[4];
                int r = g2 * 16 + rB;
                uint32_t addr = sV + r * 256 + ((((ks << 5) + ((mi >> 1) << 4))) ^ ((r & 7) << 4));
                LDSM4(vb, addr);
                LDSM4(vbl, addr + 16384);
                MMA16816(oacc[2 * g2],     pah[ks], vb[0],  vb[2]);
                MMA16816(oacc[2 * g2 + 1], pah[ks], vb[1],  vb[3]);
                MMA16816(oacc[2 * g2],     pal[ks], vb[0],  vb[2]);
                MMA16816(oacc[2 * g2 + 1], pal[ks], vb[1],  vb[3]);
                MMA16816(oacc[2 * g2],     pah[ks], vbl[0], vbl[2]);
                MMA16816(oacc[2 * g2 + 1], pah[ks], vbl[1], vbl[3]);
            }
        }
    }

    float inv0 = 1.0f / lr0, inv1 = 1.0f / lr1;
    size_t t0 = (size_t)(tokQ + myr0) * DMODEL + ho;
    size_t t1 = t0 + (size_t)8 * DMODEL;
    #pragma unroll
    for (int f = 0; f < 8; f++) {
        int dc = f * 8 + 2 * (lane & 3);
        __half2 a = __floats2half2_rn(oacc[f][0] * inv0, oacc[f][1] * inv0);
        __half2 b = __floats2half2_rn(oacc[f][2] * inv1, oacc[f][3] * inv1);
        *reinterpret_cast<uint32_t*>(cf + t0 + dc) = *reinterpret_cast<uint32_t*>(&a);
        *reinterpret_cast<uint32_t*>(cf + t1 + dc) = *reinterpret_cast<uint32_t*>(&b);
    }
}

// ---------------- weight transpose kernels ----------------
__device__ __forceinline__ void transpose_split(const float* __restrict__ in,
        __nv_bfloat16* __restrict__ hi, __nv_bfloat16* __restrict__ lo, int K, int N) {
    __shared__ float t[32][33];
    int n0 = blockIdx.x << 5, k0 = blockIdx.y << 5;
    int tx = threadIdx.x, ty = threadIdx.y;
    #pragma unroll
    for (int r = 0; r < 4; r++)
        t[ty + 8 * r][tx] = in[(size_t)(k0 + ty + 8 * r) * N + n0 + tx];
    __syncthreads();
    #pragma unroll
    for (int r = 0; r < 4; r++) {
        float v = t[tx][ty + 8 * r];
        size_t o = (size_t)(n0 + ty + 8 * r) * K + k0 + tx;
        __nv_bfloat16 h = __float2bfloat16(v);
        hi[o] = h;
        lo[o] = __float2bfloat16(v - __bfloat162float(h));
    }
}
__device__ __forceinline__ void transpose_f16(const float* __restrict__ in,
        __half* __restrict__ out, int K, int N) {
    __shared__ float t[32][33];
    int n0 = blockIdx.x << 5, k0 = blockIdx.y << 5;
    int tx = threadIdx.x, ty = threadIdx.y;
    #pragma unroll
    for (int r = 0; r < 4; r++)
        t[ty + 8 * r][tx] = in[(size_t)(k0 + ty + 8 * r) * N + n0 + tx];
    __syncthreads();
    #pragma unroll
    for (int r = 0; r < 4; r++)
        out[(size_t)(n0 + ty + 8 * r) * K + k0 + tx] = __float2half_rn(t[tx][ty + 8 * r]);
}
__global__ void wsplit_qkv_k(const float* __restrict__ Wq, const float* __restrict__ Wk,
                             const float* __restrict__ Wv, __nv_bfloat16* __restrict__ wbuf) {
    int z = blockIdx.z, l = z / 3, m = z % 3;
    const float* W = (m == 0 ? Wq : m == 1 ? Wk : Wv) + (size_t)l * DDSZ;
    __nv_bfloat16* base = wbuf + (size_t)l * 6 * DDSZ;
    transpose_split(W, base + (size_t)m * DDSZ, base + (size_t)(3 + m) * DDSZ, DMODEL, DMODEL);
}
__global__ void wcvt_wo_k(const float* __restrict__ Wo, __half* __restrict__ out) {
    int l = blockIdx.z;
    transpose_f16(Wo + (size_t)l * DDSZ, out + (size_t)l * DDSZ, DMODEL, DMODEL);
}
__global__ void wcvt_w1_k(const float* __restrict__ W1, __half* __restrict__ out) {
    int l = blockIdx.z;
    transpose_f16(W1 + (size_t)l * DFSZ, out + (size_t)l * DFSZ, DMODEL, FFDIM);
}
__global__ void wcvt_w2_k(const float* __restrict__ W2, __half* __restrict__ out) {
    int l = blockIdx.z;
    transpose_f16(W2 + (size_t)l * DFSZ, out + (size_t)l * DFSZ, FFDIM, DMODEL);
}
__global__ __launch_bounds__(256) void embcvt_k(const float* __restrict__ te,
                                                __half* __restrict__ out) {
    size_t n4 = (size_t)VOCAB * DMODEL / 4;
    for (size_t i = (size_t)blockIdx.x * blockDim.x + threadIdx.x; i < n4;
         i += (size_t)gridDim.x * blockDim.x) {
        float4 v = reinterpret_cast<const float4*>(te)[i];
        __half2 a = __floats2half2_rn(v.x, v.y);
        __half2 b = __floats2half2_rn(v.z, v.w);
        uint2 o;
        o.x = *reinterpret_cast<uint32_t*>(&a);
        o.y = *reinterpret_cast<uint32_t*>(&b);
        reinterpret_cast<uint2*>(out)[i] = o;
    }
}

// ---------------- helpers ----------------
__device__ __forceinline__ int detect_i64(const void* p, int n) {
    const long long* x = (const long long*)p;
    int c = n < 32 ? n : 32;
    for (int i = 0; i < c; i++) {
        long long v = x[i];
        if (v < 0 || v >= VOCAB) return 0;
    }
    return 1;
}
__device__ __forceinline__ long long load_index(const void* p, int i, int is64) {
    return is64 ? ((const long long*)p)[i] : (long long)((const int*)p)[i];
}

// ---------------- embedding (+ folded qkv bias concat) ----------------
__global__ __launch_bounds__(256) void embed_k(const void* __restrict__ xr,
                                               const float* __restrict__ te,
                                               const float* __restrict__ pe,
                                               float* __restrict__ h,
                                               const float* __restrict__ bq,
                                               const float* __restrict__ bk,
                                               const float* __restrict__ bv,
                                               float* __restrict__ bqkv) {
    __shared__ int mode;
    if (threadIdx.x == 0) mode = detect_i64(xr, BS);
    __syncthreads();
    int pos = blockIdx.x;
    int tid = threadIdx.x;
    if (pos < NLAYER) {
        #pragma unroll
        for (int t = tid; t < DMODEL; t += 256) {
            bqkv[pos * QKVS + t]        = bq[pos * DMODEL + t];
            bqkv[pos * QKVS + 512 + t]  = bk[pos * DMODEL + t];
            bqkv[pos * QKVS + 1024 + t] = bv[pos * DMODEL + t];
        }
    }
    long long idx = load_index(xr, pos, mode);
    int s = pos & (SEQ - 1);
    const float* t = te + idx * DMODEL;
    const float* p = pe + (long long)s * DMODEL;
    float* o = h + (long long)pos * DMODEL;
    o[tid]       = t[tid]       + p[tid];
    o[tid + 256] = t[tid + 256] + p[tid + 256];
}

// ---------------- layernorm -> bf16 split (MODE 0) or fp16 single (MODE 1) ----------------
template <int MODE>
__global__ __launch_bounds__(256) void ln_k(const float* __restrict__ in,
                                            const float* __restrict__ g,
                                            const float* __restrict__ b,
                                            __nv_bfloat16* __restrict__ oh,
                                            __nv_bfloat16* __restrict__ ol,
                                            __half* __restrict__ of) {
    int row = blockIdx.x;
    int tid = threadIdx.x;
    int lane = tid & 31, wid = tid >> 5;
    const float* x = in + (long long)row * DMODEL;
    float v0 = x[tid], v1 = x[tid + 256];
    __shared__ float wr[16];
    float s = v0 + v1;
    #pragma unroll
    for (int o = 16; o; o >>= 1) s += __shfl_xor_sync(0xffffffffu, s, o);
    if (lane == 0) wr[wid] = s;
    __syncthreads();
    float mu = (wr[0] + wr[1] + wr[2] + wr[3] + wr[4] + wr[5] + wr[6] + wr[7]) * (1.0f / DMODEL);
    float d0 = v0 - mu, d1 = v1 - mu;
    float q = d0 * d0 + d1 * d1;
    #pragma unroll
    for (int o = 16; o; o >>= 1) q += __shfl_xor_sync(0xffffffffu, q, o);
    if (lane == 0) wr[8 + wid] = q;
    __syncthreads();
    float var = (wr[8] + wr[9] + wr[10] + wr[11] + wr[12] + wr[13] + wr[14] + wr[15]) * (1.0f / DMODEL);
    float rstd = rsqrtf(var + 1e-5f);
    long long base = (long long)row * DMODEL;
    float y0 = d0 * rstd * g[tid] + b[tid];
    float y1 = d1 * rstd * g[tid + 256] + b[tid + 256];
    if (MODE == 0) {
        __nv_bfloat16 h0 = __float2bfloat16(y0);
        __nv_bfloat16 h1 = __float2bfloat16(y1);
        oh[base + tid] = h0;
        ol[base + tid] = __float2bfloat16(y0 - __bfloat162float(h0));
        oh[base + tid + 256] = h1;
        ol[base + tid + 256] = __float2bfloat16(y1 - __bfloat162float(h1));
    } else {
        of[base + tid]       = __float2half_rn(y0);
        of[base + tid + 256] = __float2half_rn(y1);
    }
}

// ---------------- single-pass cross-entropy ----------------
__global__ __launch_bounds__(256) void loss_row_k(const float* __restrict__ logits,
                                                  const void* __restrict__ tr,
                                                  float* __restrict__ rowloss) {
    __shared__ int mode;
    __shared__ float rm[256], rs[256];
    int row = blockIdx.x, tid = threadIdx.x;
    if (tid == 0) mode = detect_i64(tr, BS);
    __syncthreads();
    const float* lr = logits + (long long)row * VOCAB;
    float m = -1e30f, s = 0.0f;
    for (int j = tid; j < VOCAB; j += 256) {
        float v = lr[j];
        float nm = fmaxf(m, v);
        s = s * __expf(m - nm) + __expf(v - nm);
        m = nm;
    }
    rm[tid] = m;
    rs[tid] = s;
    __syncthreads();
    #pragma unroll
    for (int st = 128; st > 0; st >>= 1) {
        if (tid < st) {
            float ma = rm[tid], mb = rm[tid + st];
            float nm = fmaxf(ma, mb);
            rs[tid] = rs[tid] * __expf(ma - nm) + rs[tid + st] * __expf(mb - nm);
            rm[tid] = nm;
        }
        __syncthreads();
    }
    if (tid == 0) {
        long long t = load_index(tr, row, mode);
        rowloss[row] = -(lr[t] - rm[0] - logf(rs[0]));
    }
}

__global__ __launch_bounds__(1024) void loss_reduce_k(const float* __restrict__ rowloss,
                                                      float* __restrict__ out) {
    __shared__ float red[1024];
    int tid = threadIdx.x;
    red[tid] = rowloss[tid] + rowloss[tid + 1024] + rowloss[tid + 2048] + rowloss[tid + 3072];
    __syncthreads();
    #pragma unroll
    for (int s = 512; s > 0; s >>= 1) {
        if (tid < s) red[tid] += red[tid + s];
        __syncthreads();
    }
    if (tid == 0) out[0] = red[0] * (1.0f / BS);
}

// ---------------- host launcher ----------------
extern "C" void kernel_launch(void* const* d_in, const int* in_sizes, int n_in,
                              void* d_out, int out_size) {
    (void)in_sizes; (void)n_in;
    const void*  x       = d_in[0];
    const void*  targets = d_in[1];
    const float* te   = (const float*)d_in[2];
    const float* pe   = (const float*)d_in[3];
    const float* ln1g = (const float*)d_in[4];
    const float* ln1b = (const float*)d_in[5];
    const float* Wq   = (const float*)d_in[6];
    const float* bq   = (const float*)d_in[7];
    const float* Wk   = (const float*)d_in[8];
    const float* bk   = (const float*)d_in[9];
    const float* Wv   = (const float*)d_in[10];
    const float* bv   = (const float*)d_in[11];
    const float* Wo   = (const float*)d_in[12];
    const float* bo   = (const float*)d_in[13];
    const float* ln2g = (const float*)d_in[14];
    const float* ln2b = (const float*)d_in[15];
    const float* W1   = (const float*)d_in[16];
    const float* b1   = (const float*)d_in[17];
    const float* W2   = (const float*)d_in[18];
    const float* b2   = (const float*)d_in[19];
    const float* lnfg = (const float*)d_in[20];
    const float* lnfb = (const float*)d_in[21];
    float* out = (float*)d_out;

    float *p_h, *p_rowloss, *p_logits, *p_bqkv;
    __nv_bfloat16 *p_xnh, *p_xnl, *p_qkvh, *p_qkvl, *p_wqkv;
    __half *p_xnf, *p_ctxf, *p_fff, *p_wof, *p_w1f, *p_w2f, *p_embf;
    cudaGetSymbolAddress((void**)&p_h, g_h);
    cudaGetSymbolAddress((void**)&p_rowloss, g_rowloss);
    cudaGetSymbolAddress((void**)&p_logits, g_logits_scratch);
    cudaGetSymbolAddress((void**)&p_bqkv, g_bqkv);
    cudaGetSymbolAddress((void**)&p_xnh, g_xnh);
    cudaGetSymbolAddress((void**)&p_xnl, g_xnl);
    cudaGetSymbolAddress((void**)&p_xnf, g_xnf);
    cudaGetSymbolAddress((void**)&p_qkvh, g_qkvh);
    cudaGetSymbolAddress((void**)&p_qkvl, g_qkvl);
    cudaGetSymbolAddress((void**)&p_ctxf, g_ctxf);
    cudaGetSymbolAddress((void**)&p_fff, g_fff);
    cudaGetSymbolAddress((void**)&p_wqkv, g_wqkv);
    cudaGetSymbolAddress((void**)&p_wof, g_wof);
    cudaGetSymbolAddress((void**)&p_w1f, g_w1f);
    cudaGetSymbolAddress((void**)&p_w2f, g_w2f);
    cudaGetSymbolAddress((void**)&p_embf, g_embf);

    cudaFuncSetAttribute(gemm_qkv,    cudaFuncAttributeMaxDynamicSharedMemorySize, GEMM_SMEM);
    cudaFuncSetAttribute(gemm_f16<0>, cudaFuncAttributeMaxDynamicSharedMemorySize, GEMM_SMEM_F);
    cudaFuncSetAttribute(gemm_f16<1>, cudaFuncAttributeMaxDynamicSharedMemorySize, GEMM_SMEM_F);
    cudaFuncSetAttribute(gemm_f16<2>, cudaFuncAttributeMaxDynamicSharedMemorySize, GEMM_SMEM_F);
    cudaFuncSetAttribute(fattn_k, cudaFuncAttributeMaxDynamicSharedMemorySize, ATT_SMEM);

    wsplit_qkv_k<<<dim3(16, 16, NLAYER * 3), dim3(32, 8)>>>(Wq, Wk, Wv, p_wqkv);
    wcvt_wo_k<<<dim3(16, 16, NLAYER), dim3(32, 8)>>>(Wo, p_wof);
    wcvt_w1_k<<<dim3(64, 16, NLAYER), dim3(32, 8)>>>(W1, p_w1f);
    wcvt_w2_k<<<dim3(16, 64, NLAYER), dim3(32, 8)>>>(W2, p_w2f);
    embcvt_k<<<2048, 256>>>(te, p_embf);
    embed_k<<<BS, 256>>>(x, te, pe, p_h, bq, bk, bv, p_bqkv);

    dim3 gDD(BS / 128, DMODEL / 128);
    dim3 gQKV(BS / 128, QKVS / 128);
    dim3 gDF(BS / 128, FFDIM / 128);
    dim3 gATT(SEQ / 128, BATCH * NHEAD);

    for (int l = 0; l < NLAYER; l++) {
        __nv_bfloat16* wqkv_l = p_wqkv + (size_t)l * 6 * DDSZ;
        __half* wof_l = p_wof + (size_t)l * DDSZ;
        __half* w1f_l = p_w1f + (size_t)l * DFSZ;
        __half* w2f_l = p_w2f + (size_t)l * DFSZ;

        ln_k<0><<<BS, 256>>>(p_h, ln1g + l * DMODEL, ln1b + l * DMODEL, p_xnh, p_xnl, nullptr);
        gemm_qkv<<<gQKV, 256, GEMM_SMEM>>>(p_xnh, p_xnl, wqkv_l, wqkv_l + 3 * (size_t)DDSZ,
                                           p_bqkv + l * QKVS, p_qkvh, p_qkvl, QKVS, DMODEL);
        fattn_k<<<gATT, 256, ATT_SMEM>>>(p_qkvh, p_qkvl, p_ctxf);
        gemm_f16<2><<<gDD, 256, GEMM_SMEM_F>>>(p_ctxf, wof_l, bo + l * DMODEL, p_h,
                                               p_h, nullptr, BS, DMODEL, DMODEL);
        ln_k<1><<<BS, 256>>>(p_h, ln2g + l * DMODEL, ln2b + l * DMODEL, nullptr, nullptr, p_xnf);
        gemm_f16<1><<<gDF, 256, GEMM_SMEM_F>>>(p_xnf, w1f_l, b1 + l * FFDIM, nullptr,
                                               nullptr, p_fff, BS, FFDIM, DMODEL);
        gemm_f16<2><<<gDD, 256, GEMM_SMEM_F>>>(p_fff, w2f_l, b2 + l * DMODEL, p_h,
                                               p_h, nullptr, BS, DMODEL, FFDIM);
    }

    ln_k<1><<<BS, 256>>>(p_h, lnfg, lnfb, nullptr, nullptr, p_xnf);

    float* logits = ((long long)out_size >= NLOG) ? out : p_logits;
    dim3 gLOG(BS / 128, VPAD / 128);
    gemm_f16<0><<<gLOG, 256, GEMM_SMEM_F>>>(p_xnf, p_embf, nullptr, nullptr,
                                            logits, nullptr, BS, VOCAB, DMODEL);

    loss_row_k<<<BS, 256>>>(logits, targets, p_rowloss);
    if ((long long)out_size > NLOG) {
        loss_reduce_k<<<1, 1024>>>(p_rowloss, out + NLOG);
    } else if ((long long)out_size < NLOG && out_size >= 1) {
        loss_reduce_k<<<1, 1024>>>(p_rowloss, out + (out_size - 1));
    }
}

// round 9
// speedup vs baseline: 2.3570x; 1.2378x over previous
#include <cuda_runtime.h>
#include <cuda_bf16.h>
#include <cuda_fp16.h>
#include <math.h>
#include <stdint.h>

// ---------------- model constants ----------------
#define BATCH  8
#define SEQ    512
#define DMODEL 512
#define NHEAD  8
#define HEADD  64
#define FFDIM  2048
#define NLAYER 6
#define VOCAB  50257
#define VPAD   50304                  // 393*128
#define BS     (BATCH*SEQ)
#define QKVS   1536
static const long long NLOG = (long long)BS * VOCAB;

#define DDSZ   (DMODEL*DMODEL)
#define DFSZ   (DMODEL*FFDIM)

// ---------------- device scratch ----------------
__device__ float g_h[BS * DMODEL];
__device__ float g_rowloss[BS];
__device__ float g_bqkv[NLAYER * QKVS];
__device__ float g_logits_scratch[(size_t)BS * VOCAB];
__device__ __half g_xnf[BS * DMODEL];
__device__ __half g_qkvf[BS * QKVS];
__device__ __half g_ctxf[BS * DMODEL];
__device__ __half g_fff[BS * FFDIM];
__device__ __half g_wqkvf[(size_t)3 * DDSZ * NLAYER];
__device__ __half g_wof[(size_t)DDSZ * NLAYER];
__device__ __half g_w1f[(size_t)DFSZ * NLAYER];
__device__ __half g_w2f[(size_t)DFSZ * NLAYER];
__device__ __half g_embf[(size_t)VPAD * DMODEL];

// ================= PTX helpers =================
__device__ __forceinline__ uint32_t smem_to_u32(const void* smem_ptr) {
    uint32_t addr;
    asm("{ .reg .u64 tmp; cvta.to.shared.u64 tmp, %1; cvt.u32.u64 %0, tmp; }"
        : "=r"(addr) : "l"(smem_ptr));
    return addr;
}
__device__ __forceinline__ void cp16(uint32_t d, const void* s, int sz) {
    asm volatile("cp.async.cg.shared.global [%0], [%1], 16, %2;\n"
                 :: "r"(d), "l"(s), "r"(sz) : "memory");
}
__device__ __forceinline__ void cp_commit() {
    asm volatile("cp.async.commit_group;\n" ::: "memory");
}
__device__ __forceinline__ void cp_wait0() {
    asm volatile("cp.async.wait_group 0;\n" ::: "memory");
}
__device__ __forceinline__ void cp_wait1() {
    asm volatile("cp.async.wait_group 1;\n" ::: "memory");
}
#define LDSM4(r, addr) \
    asm volatile("ldmatrix.sync.aligned.m8n8.x4.shared.b16 {%0,%1,%2,%3}, [%4];" \
        : "=r"((r)[0]), "=r"((r)[1]), "=r"((r)[2]), "=r"((r)[3]) : "r"(addr))
#define MMAF16(c, a, b0, b1) \
    asm volatile("mma.sync.aligned.m16n8k16.row.col.f32.f16.f16.f32 " \
        "{%0,%1,%2,%3}, {%4,%5,%6,%7}, {%8,%9}, {%0,%1,%2,%3};" \
        : "+f"((c)[0]), "+f"((c)[1]), "+f"((c)[2]), "+f"((c)[3]) \
        : "r"((a)[0]), "r"((a)[1]), "r"((a)[2]), "r"((a)[3]), "r"(b0), "r"(b1))

// ================= fp16 single-pass GEMM =================
// EPI: 0 = plain f32 (logits, N-guarded); 1 = bias+gelu -> fp16;
//      2 = bias+res -> f32; 3 = bias -> fp16 (QKV)
#define TB 16384
#define SMEM_OFF 1024
#define FSTAGE (2*TB)
#define GEMM_SMEM_F (SMEM_OFF + 2*FSTAGE)

__device__ __forceinline__ void copy_stage_f(uint32_t st,
        const __half* __restrict__ A, const __half* __restrict__ B,
        int bm, int bn, int k0, int K, int N, int tid) {
    #pragma unroll
    for (int it = 0; it < 4; it++) {
        int idx = tid + it * 256;
        int row = idx >> 3, c = idx & 7;
        uint32_t d = st + row * 128 + ((c ^ (row & 7)) << 4);
        size_t so = (size_t)(bm + row) * K + k0 + c * 8;
        cp16(d, A + so, 16);
    }
    #pragma unroll
    for (int it = 0; it < 4; it++) {
        int idx = tid + it * 256;
        int row = idx >> 3, c = idx & 7;
        int n = bn + row;
        int sz = (n < N) ? 16 : 0;
        uint32_t d = st + TB + row * 128 + ((c ^ (row & 7)) << 4);
        size_t so = (size_t)n * K + k0 + c * 8;
        cp16(d, B + so, sz);
    }
}

template <int EPI>
__global__ void __launch_bounds__(256, 1)
gemm_f16(const __half* __restrict__ A, const __half* __restrict__ B,
         const float* __restrict__ bias, const float* __restrict__ res,
         float* __restrict__ C, __half* __restrict__ Cf,
         int M, int N, int K) {
    extern __shared__ char smem[];
    const int tid = threadIdx.x;
    const int bm = blockIdx.x * 128;
    const int bn = blockIdx.y * 128;
    const int nc = K >> 6;

    const uint32_t tiles = smem_to_u32(smem) + SMEM_OFF;
    const int lane = tid & 31;
    const int wid = tid >> 5;
    const int wm = (wid & 3) << 5;
    const int wn = (wid >> 2) << 6;
    const int mi = lane >> 3;
    const int lrow = lane & 7;

    float acc[2][8][4];
    #pragma unroll
    for (int i = 0; i < 2; i++)
        #pragma unroll
        for (int j = 0; j < 8; j++)
            #pragma unroll
            for (int t = 0; t < 4; t++) acc[i][j][t] = 0.0f;

    copy_stage_f(tiles, A, B, bm, bn, 0, K, N, tid);
    cp_commit();

    for (int c = 0; c < nc; c++) {
        if (c + 1 < nc) {
            copy_stage_f(tiles + ((c + 1) & 1) * FSTAGE, A, B, bm, bn, (c + 1) << 6, K, N, tid);
            cp_commit();
            cp_wait1();
        } else {
            cp_wait0();
        }
        __syncthreads();

        const uint32_t st = tiles + (c & 1) * FSTAGE;
        #pragma unroll
        for (int s = 0; s < 4; s++) {
            const int cb = (s << 5) + ((mi >> 1) << 4);
            uint32_t af[2][4], bf[4][4];
            #pragma unroll
            for (int i = 0; i < 2; i++) {
                int r = wm + (i << 4) + ((mi & 1) << 3) + lrow;
                LDSM4(af[i], st + r * 128 + (cb ^ ((r & 7) << 4)));
            }
            #pragma unroll
            for (int j2 = 0; j2 < 4; j2++) {
                int r = wn + (j2 << 4) + ((mi & 1) << 3) + lrow;
                LDSM4(bf[j2], st + TB + r * 128 + (cb ^ ((r & 7) << 4)));
            }
            #pragma unroll
            for (int i = 0; i < 2; i++)
                #pragma unroll
                for (int j2 = 0; j2 < 4; j2++) {
                    MMAF16(acc[i][2 * j2],     af[i], bf[j2][0], bf[j2][2]);
                    MMAF16(acc[i][2 * j2 + 1], af[i], bf[j2][1], bf[j2][3]);
                }
        }
        __syncthreads();
    }

    #pragma unroll
    for (int i = 0; i < 2; i++) {
        int row = bm + wm + (i << 4) + (lane >> 2);
        size_t base = (size_t)row * N;
        size_t base8 = base + (size_t)8 * N;
        #pragma unroll
        for (int j = 0; j < 8; j++) {
            int col = bn + wn + (j << 3) + ((lane & 3) << 1);
            #pragma unroll
            for (int t = 0; t < 4; t++) {
                int cc = col + (t & 1);
                if (EPI == 0 && cc >= N) continue;
                size_t off = (t < 2 ? base : base8) + cc;
                float x = acc[i][j][t];
                if (EPI != 0) x += __ldg(bias + cc);
                if (EPI == 1) {
                    x = 0.5f * x * (1.0f + erff(x * 0.70710678118654752440f));
                    Cf[off] = __float2half_rn(x);
                } else if (EPI == 2) {
                    C[off] = x + res[off];
                } else if (EPI == 3) {
                    Cf[off] = __float2half_rn(x);
                } else {
                    C[off] = x;
                }
            }
        }
    }
}

// ---------------- flash attention (fp16 single-pass) ----------------
// smem: sQ 16K | sK 16K | sV 16K (V transposed to [d][j], 256B rows)
#define ATT_SMEM (3*16384)
__global__ void __launch_bounds__(256, 1)
fattn_k(const __half* __restrict__ qkv, __half* __restrict__ cf) {
    extern __shared__ char smx[];
    const uint32_t sQ = smem_to_u32(smx);
    const uint32_t sK = sQ + 16384;
    const uint32_t sV = sQ + 32768;
    const int tid = threadIdx.x;
    const int lane = tid & 31, wid = tid >> 5;
    const int qt = blockIdx.x;
    const int bh = blockIdx.y;
    const int b = bh >> 3, h = bh & 7;
    const int tokQ = b * SEQ + qt * 128;
    const int ho = h * HEADD;
    const int mi = lane >> 3, lrow = lane & 7;
    const int wm = wid * 16;
    const int rB = ((mi & 1) << 3) + lrow;

    // ---- load Q tile
    #pragma unroll
    for (int it = 0; it < 4; it++) {
        int idx = tid + it * 256;
        int r = idx >> 3, c = idx & 7;
        uint32_t d = sQ + r * 128 + ((c ^ (r & 7)) << 4);
        size_t so = (size_t)(tokQ + r) * QKVS + ho + c * 8;
        cp16(d, qkv + so, 16);
    }
    cp_commit();
    cp_wait0();
    __syncthreads();

    uint32_t aq[4][4];
    {
        int r = wm + rB;
        #pragma unroll
        for (int s = 0; s < 4; s++) {
            uint32_t addr = sQ + r * 128 + ((((s << 5) + ((mi >> 1) << 4))) ^ ((r & 7) << 4));
            LDSM4(aq[s], addr);
        }
    }

    float oacc[8][4];
    #pragma unroll
    for (int f = 0; f < 8; f++)
        #pragma unroll
        for (int t = 0; t < 4; t++) oacc[f][t] = 0.0f;
    float mr0 = -1e30f, mr1 = -1e30f, lr0 = 0.0f, lr1 = 0.0f;
    const int myr0 = wm + (lane >> 2);
    const int myr1 = myr0 + 8;

    for (int jt = 0; jt <= qt; jt++) {
        __syncthreads();   // prior compute done before tile overwrite
        const int tokJ = b * SEQ + jt * 128;
        // K tile
        #pragma unroll
        for (int it = 0; it < 4; it++) {
            int idx = tid + it * 256;
            int r = idx >> 3, c = idx & 7;
            uint32_t d = sK + r * 128 + ((c ^ (r & 7)) << 4);
            size_t so = (size_t)(tokJ + r) * QKVS + 512 + ho + c * 8;
            cp16(d, qkv + so, 16);
        }
        // V transpose into sV [d][j]
        #pragma unroll
        for (int it = 0; it < 4; it++) {
            int task = tid + it * 256;
            int j = task >> 3, c = task & 7;
            size_t so = (size_t)(tokJ + j) * QKVS + 1024 + ho + c * 8;
            uint4 v4 = *reinterpret_cast<const uint4*>(qkv + so);
            const uint32_t* wv = &v4.x;
            #pragma unroll
            for (int i = 0; i < 8; i++) {
                int dd = c * 8 + i;
                uint32_t off = dd * 256 + ((((uint32_t)(j >> 3) ^ (uint32_t)(dd & 7)) << 4)) + (j & 7) * 2;
                uint16_t hv = (uint16_t)(wv[i >> 1] >> ((i & 1) * 16));
                asm volatile("st.shared.u16 [%0], %1;" :: "r"(sV + off), "h"(hv));
            }
        }
        cp_commit();
        cp_wait0();
        __syncthreads();

        // ---- S = Q K^T
        float facc[16][4];
        #pragma unroll
        for (int f = 0; f < 16; f++)
            #pragma unroll
            for (int t = 0; t < 4; t++) facc[f][t] = 0.0f;
        #pragma unroll
        for (int g = 0; g < 8; g++) {
            int r = g * 16 + rB;
            #pragma unroll
            for (int s = 0; s < 4; s++) {
                uint32_t kb[4];
                uint32_t addr = sK + r * 128 + ((((s << 5) + ((mi >> 1) << 4))) ^ ((r & 7) << 4));
                LDSM4(kb, addr);
                MMAF16(facc[2 * g],     aq[s], kb[0], kb[2]);
                MMAF16(facc[2 * g + 1], aq[s], kb[1], kb[3]);
            }
        }
        const float scl = 0.125f;
        #pragma unroll
        for (int f = 0; f < 16; f++) {
            int c0 = f * 8 + 2 * (lane & 3);
            facc[f][0] *= scl; facc[f][1] *= scl;
            facc[f][2] *= scl; facc[f][3] *= scl;
            if (jt == qt) {
                if (c0     > myr0) facc[f][0] = -1e30f;
                if (c0 + 1 > myr0) facc[f][1] = -1e30f;
                if (c0     > myr1) facc[f][2] = -1e30f;
                if (c0 + 1 > myr1) facc[f][3] = -1e30f;
            }
        }
        float m0 = -1e30f, m1 = -1e30f;
        #pragma unroll
        for (int f = 0; f < 16; f++) {
            m0 = fmaxf(m0, fmaxf(facc[f][0], facc[f][1]));
            m1 = fmaxf(m1, fmaxf(facc[f][2], facc[f][3]));
        }
        m0 = fmaxf(m0, __shfl_xor_sync(0xffffffffu, m0, 1));
        m0 = fmaxf(m0, __shfl_xor_sync(0xffffffffu, m0, 2));
        m1 = fmaxf(m1, __shfl_xor_sync(0xffffffffu, m1, 1));
        m1 = fmaxf(m1, __shfl_xor_sync(0xffffffffu, m1, 2));
        float nm0 = fmaxf(mr0, m0), nm1 = fmaxf(mr1, m1);
        float al0 = __expf(mr0 - nm0), al1 = __expf(mr1 - nm1);
        mr0 = nm0; mr1 = nm1;
        #pragma unroll
        for (int f = 0; f < 8; f++) {
            oacc[f][0] *= al0; oacc[f][1] *= al0;
            oacc[f][2] *= al1; oacc[f][3] *= al1;
        }
        // P = exp(S - m) -> fp16 A-frags
        float s0 = 0.0f, s1 = 0.0f;
        uint32_t pa[8][4];
        #pragma unroll
        for (int f = 0; f < 16; f++) {
            float p0 = __expf(facc[f][0] - nm0);
            float p1 = __expf(facc[f][1] - nm0);
            float p2 = __expf(facc[f][2] - nm1);
            float p3 = __expf(facc[f][3] - nm1);
            s0 += p0 + p1;
            s1 += p2 + p3;
            __half2 hp = __floats2half2_rn(p0, p1);
            __half2 hq = __floats2half2_rn(p2, p3);
            int ks = f >> 1, half = f & 1;
            pa[ks][2 * half]     = *reinterpret_cast<uint32_t*>(&hp);
            pa[ks][2 * half + 1] = *reinterpret_cast<uint32_t*>(&hq);
        }
        s0 += __shfl_xor_sync(0xffffffffu, s0, 1);
        s0 += __shfl_xor_sync(0xffffffffu, s0, 2);
        s1 += __shfl_xor_sync(0xffffffffu, s1, 1);
        s1 += __shfl_xor_sync(0xffffffffu, s1, 2);
        lr0 = lr0 * al0 + s0;
        lr1 = lr1 * al1 + s1;
        // ---- O += P V
        #pragma unroll
        for (int ks = 0; ks < 8; ks++) {
            #pragma unroll
            for (int g2 = 0; g2 < 4; g2++) {
                uint32_t vb[4];
                int r = g2 * 16 + rB;
                uint32_t addr = sV + r * 256 + ((((ks << 5) + ((mi >> 1) << 4))) ^ ((r & 7) << 4));
                LDSM4(vb, addr);
                MMAF16(oacc[2 * g2],     pa[ks], vb[0], vb[2]);
                MMAF16(oacc[2 * g2 + 1], pa[ks], vb[1], vb[3]);
            }
        }
    }

    float inv0 = 1.0f / lr0, inv1 = 1.0f / lr1;
    size_t t0 = (size_t)(tokQ + myr0) * DMODEL + ho;
    size_t t1 = t0 + (size_t)8 * DMODEL;
    #pragma unroll
    for (int f = 0; f < 8; f++) {
        int dc = f * 8 + 2 * (lane & 3);
        __half2 a = __floats2half2_rn(oacc[f][0] * inv0, oacc[f][1] * inv0);
        __half2 b2 = __floats2half2_rn(oacc[f][2] * inv1, oacc[f][3] * inv1);
        *reinterpret_cast<uint32_t*>(cf + t0 + dc) = *reinterpret_cast<uint32_t*>(&a);
        *reinterpret_cast<uint32_t*>(cf + t1 + dc) = *reinterpret_cast<uint32_t*>(&b2);
    }
}

// ---------------- weight transpose (f32 [K,N] -> fp16 [N,K]) ----------------
__device__ __forceinline__ void transpose_f16(const float* __restrict__ in,
        __half* __restrict__ out, int K, int N) {
    __shared__ float t[32][33];
    int n0 = blockIdx.x << 5, k0 = blockIdx.y << 5;
    int tx = threadIdx.x, ty = threadIdx.y;
    #pragma unroll
    for (int r = 0; r < 4; r++)
        t[ty + 8 * r][tx] = in[(size_t)(k0 + ty + 8 * r) * N + n0 + tx];
    __syncthreads();
    #pragma unroll
    for (int r = 0; r < 4; r++)
        out[(size_t)(n0 + ty + 8 * r) * K + k0 + tx] = __float2half_rn(t[tx][ty + 8 * r]);
}
__global__ void wcvt_qkv_k(const float* __restrict__ Wq, const float* __restrict__ Wk,
                           const float* __restrict__ Wv, __half* __restrict__ out) {
    int z = blockIdx.z, l = z / 3, m = z % 3;
    const float* W = (m == 0 ? Wq : m == 1 ? Wk : Wv) + (size_t)l * DDSZ;
    transpose_f16(W, out + ((size_t)l * 3 + m) * DDSZ, DMODEL, DMODEL);
}
__global__ void wcvt_wo_k(const float* __restrict__ Wo, __half* __restrict__ out) {
    int l = blockIdx.z;
    transpose_f16(Wo + (size_t)l * DDSZ, out + (size_t)l * DDSZ, DMODEL, DMODEL);
}
__global__ void wcvt_w1_k(const float* __restrict__ W1, __half* __restrict__ out) {
    int l = blockIdx.z;
    transpose_f16(W1 + (size_t)l * DFSZ, out + (size_t)l * DFSZ, DMODEL, FFDIM);
}
__global__ void wcvt_w2_k(const float* __restrict__ W2, __half* __restrict__ out) {
    int l = blockIdx.z;
    transpose_f16(W2 + (size_t)l * DFSZ, out + (size_t)l * DFSZ, FFDIM, DMODEL);
}
__global__ __launch_bounds__(256) void embcvt_k(const float* __restrict__ te,
                                                __half* __restrict__ out) {
    size_t n4 = (size_t)VOCAB * DMODEL / 4;
    for (size_t i = (size_t)blockIdx.x * blockDim.x + threadIdx.x; i < n4;
         i += (size_t)gridDim.x * blockDim.x) {
        float4 v = reinterpret_cast<const float4*>(te)[i];
        __half2 a = __floats2half2_rn(v.x, v.y);
        __half2 b = __floats2half2_rn(v.z, v.w);
        uint2 o;
        o.x = *reinterpret_cast<uint32_t*>(&a);
        o.y = *reinterpret_cast<uint32_t*>(&b);
        reinterpret_cast<uint2*>(out)[i] = o;
    }
}

// ---------------- helpers ----------------
__device__ __forceinline__ int detect_i64(const void* p, int n) {
    const long long* x = (const long long*)p;
    int c = n < 32 ? n : 32;
    for (int i = 0; i < c; i++) {
        long long v = x[i];
        if (v < 0 || v >= VOCAB) return 0;
    }
    return 1;
}
__device__ __forceinline__ long long load_index(const void* p, int i, int is64) {
    return is64 ? ((const long long*)p)[i] : (long long)((const int*)p)[i];
}

// ---------------- embedding (+ folded qkv bias concat) ----------------
__global__ __launch_bounds__(256) void embed_k(const void* __restrict__ xr,
                                               const float* __restrict__ te,
                                               const float* __restrict__ pe,
                                               float* __restrict__ h,
                                               const float* __restrict__ bq,
                                               const float* __restrict__ bk,
                                               const float* __restrict__ bv,
                                               float* __restrict__ bqkv) {
    __shared__ int mode;
    if (threadIdx.x == 0) mode = detect_i64(xr, BS);
    __syncthreads();
    int pos = blockIdx.x;
    int tid = threadIdx.x;
    if (pos < NLAYER) {
        #pragma unroll
        for (int t = tid; t < DMODEL; t += 256) {
            bqkv[pos * QKVS + t]        = bq[pos * DMODEL + t];
            bqkv[pos * QKVS + 512 + t]  = bk[pos * DMODEL + t];
            bqkv[pos * QKVS + 1024 + t] = bv[pos * DMODEL + t];
        }
    }
    long long idx = load_index(xr, pos, mode);
    int s = pos & (SEQ - 1);
    const float* t = te + idx * DMODEL;
    const float* p = pe + (long long)s * DMODEL;
    float* o = h + (long long)pos * DMODEL;
    o[tid]       = t[tid]       + p[tid];
    o[tid + 256] = t[tid + 256] + p[tid + 256];
}

// ---------------- layernorm -> fp16 ----------------
__global__ __launch_bounds__(256) void ln_k(const float* __restrict__ in,
                                            const float* __restrict__ g,
                                            const float* __restrict__ b,
                                            __half* __restrict__ of) {
    int row = blockIdx.x;
    int tid = threadIdx.x;
    int lane = tid & 31, wid = tid >> 5;
    const float* x = in + (long long)row * DMODEL;
    float v0 = x[tid], v1 = x[tid + 256];
    __shared__ float wr[16];
    float s = v0 + v1;
    #pragma unroll
    for (int o = 16; o; o >>= 1) s += __shfl_xor_sync(0xffffffffu, s, o);
    if (lane == 0) wr[wid] = s;
    __syncthreads();
    float mu = (wr[0] + wr[1] + wr[2] + wr[3] + wr[4] + wr[5] + wr[6] + wr[7]) * (1.0f / DMODEL);
    float d0 = v0 - mu, d1 = v1 - mu;
    float q = d0 * d0 + d1 * d1;
    #pragma unroll
    for (int o = 16; o; o >>= 1) q += __shfl_xor_sync(0xffffffffu, q, o);
    if (lane == 0) wr[8 + wid] = q;
    __syncthreads();
    float var = (wr[8] + wr[9] + wr[10] + wr[11] + wr[12] + wr[13] + wr[14] + wr[15]) * (1.0f / DMODEL);
    float rstd = rsqrtf(var + 1e-5f);
    long long base = (long long)row * DMODEL;
    float y0 = d0 * rstd * g[tid] + b[tid];
    float y1 = d1 * rstd * g[tid + 256] + b[tid + 256];
    of[base + tid]       = __float2half_rn(y0);
    of[base + tid + 256] = __float2half_rn(y1);
}

// ---------------- single-pass cross-entropy ----------------
__global__ __launch_bounds__(256) void loss_row_k(const float* __restrict__ logits,
                                                  const void* __restrict__ tr,
                                                  float* __restrict__ rowloss) {
    __shared__ int mode;
    __shared__ float rm[256], rs[256];
    int row = blockIdx.x, tid = threadIdx.x;
    if (tid == 0) mode = detect_i64(tr, BS);
    __syncthreads();
    const float* lr = logits + (long long)row * VOCAB;
    float m = -1e30f, s = 0.0f;
    for (int j = tid; j < VOCAB; j += 256) {
        float v = lr[j];
        float nm = fmaxf(m, v);
        s = s * __expf(m - nm) + __expf(v - nm);
        m = nm;
    }
    rm[tid] = m;
    rs[tid] = s;
    __syncthreads();
    #pragma unroll
    for (int st = 128; st > 0; st >>= 1) {
        if (tid < st) {
            float ma = rm[tid], mb = rm[tid + st];
            float nm = fmaxf(ma, mb);
            rs[tid] = rs[tid] * __expf(ma - nm) + rs[tid + st] * __expf(mb - nm);
            rm[tid] = nm;
        }
        __syncthreads();
    }
    if (tid == 0) {
        long long t = load_index(tr, row, mode);
        rowloss[row] = -(lr[t] - rm[0] - logf(rs[0]));
    }
}

__global__ __launch_bounds__(1024) void loss_reduce_k(const float* __restrict__ rowloss,
                                                      float* __restrict__ out) {
    __shared__ float red[1024];
    int tid = threadIdx.x;
    red[tid] = rowloss[tid] + rowloss[tid + 1024] + rowloss[tid + 2048] + rowloss[tid + 3072];
    __syncthreads();
    #pragma unroll
    for (int s = 512; s > 0; s >>= 1) {
        if (tid < s) red[tid] += red[tid + s];
        __syncthreads();
    }
    if (tid == 0) out[0] = red[0] * (1.0f / BS);
}

// ---------------- host launcher ----------------
extern "C" void kernel_launch(void* const* d_in, const int* in_sizes, int n_in,
                              void* d_out, int out_size) {
    (void)in_sizes; (void)n_in;
    const void*  x       = d_in[0];
    const void*  targets = d_in[1];
    const float* te   = (const float*)d_in[2];
    const float* pe   = (const float*)d_in[3];
    const float* ln1g = (const float*)d_in[4];
    const float* ln1b = (const float*)d_in[5];
    const float* Wq   = (const float*)d_in[6];
    const float* bq   = (const float*)d_in[7];
    const float* Wk   = (const float*)d_in[8];
    const float* bk   = (const float*)d_in[9];
    const float* Wv   = (const float*)d_in[10];
    const float* bv   = (const float*)d_in[11];
    const float* Wo   = (const float*)d_in[12];
    const float* bo   = (const float*)d_in[13];
    const float* ln2g = (const float*)d_in[14];
    const float* ln2b = (const float*)d_in[15];
    const float* W1   = (const float*)d_in[16];
    const float* b1   = (const float*)d_in[17];
    const float* W2   = (const float*)d_in[18];
    const float* b2   = (const float*)d_in[19];
    const float* lnfg = (const float*)d_in[20];
    const float* lnfb = (const float*)d_in[21];
    float* out = (float*)d_out;

    float *p_h, *p_rowloss, *p_logits, *p_bqkv;
    __half *p_xnf, *p_qkvf, *p_ctxf, *p_fff, *p_wqkvf, *p_wof, *p_w1f, *p_w2f, *p_embf;
    cudaGetSymbolAddress((void**)&p_h, g_h);
    cudaGetSymbolAddress((void**)&p_rowloss, g_rowloss);
    cudaGetSymbolAddress((void**)&p_logits, g_logits_scratch);
    cudaGetSymbolAddress((void**)&p_bqkv, g_bqkv);
    cudaGetSymbolAddress((void**)&p_xnf, g_xnf);
    cudaGetSymbolAddress((void**)&p_qkvf, g_qkvf);
    cudaGetSymbolAddress((void**)&p_ctxf, g_ctxf);
    cudaGetSymbolAddress((void**)&p_fff, g_fff);
    cudaGetSymbolAddress((void**)&p_wqkvf, g_wqkvf);
    cudaGetSymbolAddress((void**)&p_wof, g_wof);
    cudaGetSymbolAddress((void**)&p_w1f, g_w1f);
    cudaGetSymbolAddress((void**)&p_w2f, g_w2f);
    cudaGetSymbolAddress((void**)&p_embf, g_embf);

    cudaFuncSetAttribute(gemm_f16<0>, cudaFuncAttributeMaxDynamicSharedMemorySize, GEMM_SMEM_F);
    cudaFuncSetAttribute(gemm_f16<1>, cudaFuncAttributeMaxDynamicSharedMemorySize, GEMM_SMEM_F);
    cudaFuncSetAttribute(gemm_f16<2>, cudaFuncAttributeMaxDynamicSharedMemorySize, GEMM_SMEM_F);
    cudaFuncSetAttribute(gemm_f16<3>, cudaFuncAttributeMaxDynamicSharedMemorySize, GEMM_SMEM_F);
    cudaFuncSetAttribute(fattn_k, cudaFuncAttributeMaxDynamicSharedMemorySize, ATT_SMEM);

    wcvt_qkv_k<<<dim3(16, 16, NLAYER * 3), dim3(32, 8)>>>(Wq, Wk, Wv, p_wqkvf);
    wcvt_wo_k<<<dim3(16, 16, NLAYER), dim3(32, 8)>>>(Wo, p_wof);
    wcvt_w1_k<<<dim3(64, 16, NLAYER), dim3(32, 8)>>>(W1, p_w1f);
    wcvt_w2_k<<<dim3(16, 64, NLAYER), dim3(32, 8)>>>(W2, p_w2f);
    embcvt_k<<<2048, 256>>>(te, p_embf);
    embed_k<<<BS, 256>>>(x, te, pe, p_h, bq, bk, bv, p_bqkv);

    dim3 gDD(BS / 128, DMODEL / 128);
    dim3 gQKV(BS / 128, QKVS / 128);
    dim3 gDF(BS / 128, FFDIM / 128);
    dim3 gATT(SEQ / 128, BATCH * NHEAD);

    for (int l = 0; l < NLAYER; l++) {
        __half* wqkv_l = p_wqkvf + (size_t)l * 3 * DDSZ;
        __half* wof_l = p_wof + (size_t)l * DDSZ;
        __half* w1f_l = p_w1f + (size_t)l * DFSZ;
        __half* w2f_l = p_w2f + (size_t)l * DFSZ;

        ln_k<<<BS, 256>>>(p_h, ln1g + l * DMODEL, ln1b + l * DMODEL, p_xnf);
        gemm_f16<3><<<gQKV, 256, GEMM_SMEM_F>>>(p_xnf, wqkv_l, p_bqkv + l * QKVS, nullptr,
                                                nullptr, p_qkvf, BS, QKVS, DMODEL);
        fattn_k<<<gATT, 256, ATT_SMEM>>>(p_qkvf, p_ctxf);
        gemm_f16<2><<<gDD, 256, GEMM_SMEM_F>>>(p_ctxf, wof_l, bo + l * DMODEL, p_h,
                                               p_h, nullptr, BS, DMODEL, DMODEL);
        ln_k<<<BS, 256>>>(p_h, ln2g + l * DMODEL, ln2b + l * DMODEL, p_xnf);
        gemm_f16<1><<<gDF, 256, GEMM_SMEM_F>>>(p_xnf, w1f_l, b1 + l * FFDIM, nullptr,
                                               nullptr, p_fff, BS, FFDIM, DMODEL);
        gemm_f16<2><<<gDD, 256, GEMM_SMEM_F>>>(p_fff, w2f_l, b2 + l * DMODEL, p_h,
                                               p_h, nullptr, BS, DMODEL, FFDIM);
    }

    ln_k<<<BS, 256>>>(p_h, lnfg, lnfb, p_xnf);

    float* logits = ((long long)out_size >= NLOG) ? out : p_logits;
    dim3 gLOG(BS / 128, VPAD / 128);
    gemm_f16<0><<<gLOG, 256, GEMM_SMEM_F>>>(p_xnf, p_embf, nullptr, nullptr,
                                            logits, nullptr, BS, VOCAB, DMODEL);

    loss_row_k<<<BS, 256>>>(logits, targets, p_rowloss);
    if ((long long)out_size > NLOG) {
        loss_reduce_k<<<1, 1024>>>(p_rowloss, out + NLOG);
    } else if ((long long)out_size < NLOG && out_size >= 1) {
        loss_reduce_k<<<1, 1024>>>(p_rowloss, out + (out_size - 1));
    }
}

// round 10
// speedup vs baseline: 2.6980x; 1.1447x over previous
#include <cuda_runtime.h>
#include <cuda_bf16.h>
#include <cuda_fp16.h>
#include <math.h>
#include <stdint.h>

// ---------------- model constants ----------------
#define BATCH  8
#define SEQ    512
#define DMODEL 512
#define NHEAD  8
#define HEADD  64
#define FFDIM  2048
#define NLAYER 6
#define VOCAB  50257
#define VPAD   50304                  // 393*128
#define NPART  786                    // 393 col-tiles * 2 warp-halves
#define BS     (BATCH*SEQ)
#define QKVS   1536
static const long long NLOG = (long long)BS * VOCAB;

#define DDSZ   (DMODEL*DMODEL)
#define DFSZ   (DMODEL*FFDIM)

// ---------------- device scratch ----------------
__device__ float g_h[BS * DMODEL];
__device__ float g_rowloss[BS];
__device__ float g_bqkv[NLAYER * QKVS];
__device__ float g_logits_scratch[(size_t)BS * VOCAB];
__device__ float2 g_part[(size_t)BS * NPART];
__device__ __half g_xnf[BS * DMODEL];
__device__ __half g_qkvf[BS * QKVS];
__device__ __half g_ctxf[BS * DMODEL];
__device__ __half g_fff[BS * FFDIM];
__device__ __half g_wqkvf[(size_t)3 * DDSZ * NLAYER];
__device__ __half g_wof[(size_t)DDSZ * NLAYER];
__device__ __half g_w1f[(size_t)DFSZ * NLAYER];
__device__ __half g_w2f[(size_t)DFSZ * NLAYER];
__device__ __half g_embf[(size_t)VPAD * DMODEL];

// ================= PTX helpers =================
__device__ __forceinline__ uint32_t smem_to_u32(const void* smem_ptr) {
    uint32_t addr;
    asm("{ .reg .u64 tmp; cvta.to.shared.u64 tmp, %1; cvt.u32.u64 %0, tmp; }"
        : "=r"(addr) : "l"(smem_ptr));
    return addr;
}
__device__ __forceinline__ void cp16(uint32_t d, const void* s, int sz) {
    asm volatile("cp.async.cg.shared.global [%0], [%1], 16, %2;\n"
                 :: "r"(d), "l"(s), "r"(sz) : "memory");
}
__device__ __forceinline__ void cp_commit() {
    asm volatile("cp.async.commit_group;\n" ::: "memory");
}
__device__ __forceinline__ void cp_wait0() {
    asm volatile("cp.async.wait_group 0;\n" ::: "memory");
}
__device__ __forceinline__ void cp_wait1() {
    asm volatile("cp.async.wait_group 1;\n" ::: "memory");
}
#define LDSM4(r, addr) \
    asm volatile("ldmatrix.sync.aligned.m8n8.x4.shared.b16 {%0,%1,%2,%3}, [%4];" \
        : "=r"((r)[0]), "=r"((r)[1]), "=r"((r)[2]), "=r"((r)[3]) : "r"(addr))
#define MMAF16(c, a, b0, b1) \
    asm volatile("mma.sync.aligned.m16n8k16.row.col.f32.f16.f16.f32 " \
        "{%0,%1,%2,%3}, {%4,%5,%6,%7}, {%8,%9}, {%0,%1,%2,%3};" \
        : "+f"((c)[0]), "+f"((c)[1]), "+f"((c)[2]), "+f"((c)[3]) \
        : "r"((a)[0]), "r"((a)[1]), "r"((a)[2]), "r"((a)[3]), "r"(b0), "r"(b1))

// ================= fp16 single-pass GEMM =================
// EPI: 0 = logits f32 + fused CE partials (N-guarded); 1 = bias+gelu -> fp16;
//      2 = bias+res -> f32; 3 = bias -> fp16 (QKV)
#define TB 16384
#define SMEM_OFF 1024
#define FSTAGE (2*TB)
#define GEMM_SMEM_F (SMEM_OFF + 2*FSTAGE)

__device__ __forceinline__ void copy_stage_f(uint32_t st,
        const __half* __restrict__ A, const __half* __restrict__ B,
        int bm, int bn, int k0, int K, int N, int tid) {
    #pragma unroll
    for (int it = 0; it < 4; it++) {
        int idx = tid + it * 256;
        int row = idx >> 3, c = idx & 7;
        uint32_t d = st + row * 128 + ((c ^ (row & 7)) << 4);
        size_t so = (size_t)(bm + row) * K + k0 + c * 8;
        cp16(d, A + so, 16);
    }
    #pragma unroll
    for (int it = 0; it < 4; it++) {
        int idx = tid + it * 256;
        int row = idx >> 3, c = idx & 7;
        int n = bn + row;
        int sz = (n < N) ? 16 : 0;
        uint32_t d = st + TB + row * 128 + ((c ^ (row & 7)) << 4);
        size_t so = (size_t)n * K + k0 + c * 8;
        cp16(d, B + so, sz);
    }
}

template <int EPI>
__global__ void __launch_bounds__(256, 2)
gemm_f16(const __half* __restrict__ A, const __half* __restrict__ B,
         const float* __restrict__ bias, const float* __restrict__ res,
         float* __restrict__ C, __half* __restrict__ Cf, float2* __restrict__ part,
         int M, int N, int K) {
    extern __shared__ char smem[];
    const int tid = threadIdx.x;
    const int bm = blockIdx.x * 128;
    const int bn = blockIdx.y * 128;
    const int nc = K >> 6;

    const uint32_t tiles = smem_to_u32(smem) + SMEM_OFF;
    const int lane = tid & 31;
    const int wid = tid >> 5;
    const int wm = (wid & 3) << 5;
    const int wn = (wid >> 2) << 6;
    const int mi = lane >> 3;
    const int lrow = lane & 7;

    float acc[2][8][4];
    #pragma unroll
    for (int i = 0; i < 2; i++)
        #pragma unroll
        for (int j = 0; j < 8; j++)
            #pragma unroll
            for (int t = 0; t < 4; t++) acc[i][j][t] = 0.0f;

    copy_stage_f(tiles, A, B, bm, bn, 0, K, N, tid);
    cp_commit();

    for (int c = 0; c < nc; c++) {
        if (c + 1 < nc) {
            copy_stage_f(tiles + ((c + 1) & 1) * FSTAGE, A, B, bm, bn, (c + 1) << 6, K, N, tid);
            cp_commit();
            cp_wait1();
        } else {
            cp_wait0();
        }
        __syncthreads();

        const uint32_t st = tiles + (c & 1) * FSTAGE;
        #pragma unroll
        for (int s = 0; s < 4; s++) {
            const int cb = (s << 5) + ((mi >> 1) << 4);
            uint32_t af[2][4], bf[4][4];
            #pragma unroll
            for (int i = 0; i < 2; i++) {
                int r = wm + (i << 4) + ((mi & 1) << 3) + lrow;
                LDSM4(af[i], st + r * 128 + (cb ^ ((r & 7) << 4)));
            }
            #pragma unroll
            for (int j2 = 0; j2 < 4; j2++) {
                int r = wn + (j2 << 4) + ((mi & 1) << 3) + lrow;
                LDSM4(bf[j2], st + TB + r * 128 + (cb ^ ((r & 7) << 4)));
            }
            #pragma unroll
            for (int i = 0; i < 2; i++)
                #pragma unroll
                for (int j2 = 0; j2 < 4; j2++) {
                    MMAF16(acc[i][2 * j2],     af[i], bf[j2][0], bf[j2][2]);
                    MMAF16(acc[i][2 * j2 + 1], af[i], bf[j2][1], bf[j2][3]);
                }
        }
        __syncthreads();
    }

    if (EPI == 0) {
        // logits store + fused per-(row, 64-col-half) softmax partials
        #pragma unroll
        for (int i = 0; i < 2; i++) {
            #pragma unroll
            for (int hr = 0; hr < 2; hr++) {
                int row = bm + wm + (i << 4) + (lane >> 2) + hr * 8;
                size_t base = (size_t)row * N;
                float pm = -1e30f, ps = 0.0f;
                #pragma unroll
                for (int j = 0; j < 8; j++) {
                    #pragma unroll
                    for (int u = 0; u < 2; u++) {
                        int cc = bn + wn + (j << 3) + ((lane & 3) << 1) + u;
                        if (cc < N) {
                            float x = acc[i][j][hr * 2 + u];
                            C[base + cc] = x;
                            float nm = fmaxf(pm, x);
                            ps = ps * __expf(pm - nm) + __expf(x - nm);
                            pm = nm;
                        }
                    }
                }
                #pragma unroll
                for (int off = 1; off <= 2; off <<= 1) {
                    float om = __shfl_xor_sync(0xffffffffu, pm, off);
                    float os = __shfl_xor_sync(0xffffffffu, ps, off);
                    float nm = fmaxf(pm, om);
                    ps = ps * __expf(pm - nm) + os * __expf(om - nm);
                    pm = nm;
                }
                if ((lane & 3) == 0)
                    part[(size_t)row * NPART + blockIdx.y * 2 + (wid >> 2)] = make_float2(pm, ps);
            }
        }
    } else {
        #pragma unroll
        for (int i = 0; i < 2; i++) {
            int row = bm + wm + (i << 4) + (lane >> 2);
            size_t base = (size_t)row * N;
            size_t base8 = base + (size_t)8 * N;
            #pragma unroll
            for (int j = 0; j < 8; j++) {
                int col = bn + wn + (j << 3) + ((lane & 3) << 1);
                #pragma unroll
                for (int t = 0; t < 4; t++) {
                    int cc = col + (t & 1);
                    size_t off = (t < 2 ? base : base8) + cc;
                    float x = acc[i][j][t] + __ldg(bias + cc);
                    if (EPI == 1) {
                        x = 0.5f * x * (1.0f + erff(x * 0.70710678118654752440f));
                        Cf[off] = __float2half_rn(x);
                    } else if (EPI == 2) {
                        C[off] = x + res[off];
                    } else {
                        Cf[off] = __float2half_rn(x);
                    }
                }
            }
        }
    }
}

// ---------------- flash attention (fp16 single-pass) ----------------
#define ATT_SMEM (3*16384)
__global__ void __launch_bounds__(256, 1)
fattn_k(const __half* __restrict__ qkv, __half* __restrict__ cf) {
    extern __shared__ char smx[];
    const uint32_t sQ = smem_to_u32(smx);
    const uint32_t sK = sQ + 16384;
    const uint32_t sV = sQ + 32768;
    const int tid = threadIdx.x;
    const int lane = tid & 31, wid = tid >> 5;
    const int qt = blockIdx.x;
    const int bh = blockIdx.y;
    const int b = bh >> 3, h = bh & 7;
    const int tokQ = b * SEQ + qt * 128;
    const int ho = h * HEADD;
    const int mi = lane >> 3, lrow = lane & 7;
    const int wm = wid * 16;
    const int rB = ((mi & 1) << 3) + lrow;

    #pragma unroll
    for (int it = 0; it < 4; it++) {
        int idx = tid + it * 256;
        int r = idx >> 3, c = idx & 7;
        uint32_t d = sQ + r * 128 + ((c ^ (r & 7)) << 4);
        size_t so = (size_t)(tokQ + r) * QKVS + ho + c * 8;
        cp16(d, qkv + so, 16);
    }
    cp_commit();
    cp_wait0();
    __syncthreads();

    uint32_t aq[4][4];
    {
        int r = wm + rB;
        #pragma unroll
        for (int s = 0; s < 4; s++) {
            uint32_t addr = sQ + r * 128 + ((((s << 5) + ((mi >> 1) << 4))) ^ ((r & 7) << 4));
            LDSM4(aq[s], addr);
        }
    }

    float oacc[8][4];
    #pragma unroll
    for (int f = 0; f < 8; f++)
        #pragma unroll
        for (int t = 0; t < 4; t++) oacc[f][t] = 0.0f;
    float mr0 = -1e30f, mr1 = -1e30f, lr0 = 0.0f, lr1 = 0.0f;
    const int myr0 = wm + (lane >> 2);
    const int myr1 = myr0 + 8;

    for (int jt = 0; jt <= qt; jt++) {
        __syncthreads();
        const int tokJ = b * SEQ + jt * 128;
        #pragma unroll
        for (int it = 0; it < 4; it++) {
            int idx = tid + it * 256;
            int r = idx >> 3, c = idx & 7;
            uint32_t d = sK + r * 128 + ((c ^ (r & 7)) << 4);
            size_t so = (size_t)(tokJ + r) * QKVS + 512 + ho + c * 8;
            cp16(d, qkv + so, 16);
        }
        #pragma unroll
        for (int it = 0; it < 4; it++) {
            int task = tid + it * 256;
            int j = task >> 3, c = task & 7;
            size_t so = (size_t)(tokJ + j) * QKVS + 1024 + ho + c * 8;
            uint4 v4 = *reinterpret_cast<const uint4*>(qkv + so);
            const uint32_t* wv = &v4.x;
            #pragma unroll
            for (int i = 0; i < 8; i++) {
                int dd = c * 8 + i;
                uint32_t off = dd * 256 + ((((uint32_t)(j >> 3) ^ (uint32_t)(dd & 7)) << 4)) + (j & 7) * 2;
                uint16_t hv = (uint16_t)(wv[i >> 1] >> ((i & 1) * 16));
                asm volatile("st.shared.u16 [%0], %1;" :: "r"(sV + off), "h"(hv));
            }
        }
        cp_commit();
        cp_wait0();
        __syncthreads();

        float facc[16][4];
        #pragma unroll
        for (int f = 0; f < 16; f++)
            #pragma unroll
            for (int t = 0; t < 4; t++) facc[f][t] = 0.0f;
        #pragma unroll
        for (int g = 0; g < 8; g++) {
            int r = g * 16 + rB;
            #pragma unroll
            for (int s = 0; s < 4; s++) {
                uint32_t kb[4];
                uint32_t addr = sK + r * 128 + ((((s << 5) + ((mi >> 1) << 4))) ^ ((r & 7) << 4));
                LDSM4(kb, addr);
                MMAF16(facc[2 * g],     aq[s], kb[0], kb[2]);
                MMAF16(facc[2 * g + 1], aq[s], kb[1], kb[3]);
            }
        }
        const float scl = 0.125f;
        #pragma unroll
        for (int f = 0; f < 16; f++) {
            int c0 = f * 8 + 2 * (lane & 3);
            facc[f][0] *= scl; facc[f][1] *= scl;
            facc[f][2] *= scl; facc[f][3] *= scl;
            if (jt == qt) {
                if (c0     > myr0) facc[f][0] = -1e30f;
                if (c0 + 1 > myr0) facc[f][1] = -1e30f;
                if (c0     > myr1) facc[f][2] = -1e30f;
                if (c0 + 1 > myr1) facc[f][3] = -1e30f;
            }
        }
        float m0 = -1e30f, m1 = -1e30f;
        #pragma unroll
        for (int f = 0; f < 16; f++) {
            m0 = fmaxf(m0, fmaxf(facc[f][0], facc[f][1]));
            m1 = fmaxf(m1, fmaxf(facc[f][2], facc[f][3]));
        }
        m0 = fmaxf(m0, __shfl_xor_sync(0xffffffffu, m0, 1));
        m0 = fmaxf(m0, __shfl_xor_sync(0xffffffffu, m0, 2));
        m1 = fmaxf(m1, __shfl_xor_sync(0xffffffffu, m1, 1));
        m1 = fmaxf(m1, __shfl_xor_sync(0xffffffffu, m1, 2));
        float nm0 = fmaxf(mr0, m0), nm1 = fmaxf(mr1, m1);
        float al0 = __expf(mr0 - nm0), al1 = __expf(mr1 - nm1);
        mr0 = nm0; mr1 = nm1;
        #pragma unroll
        for (int f = 0; f < 8; f++) {
            oacc[f][0] *= al0; oacc[f][1] *= al0;
            oacc[f][2] *= al1; oacc[f][3] *= al1;
        }
        float s0 = 0.0f, s1 = 0.0f;
        uint32_t pa[8][4];
        #pragma unroll
        for (int f = 0; f < 16; f++) {
            float p0 = __expf(facc[f][0] - nm0);
            float p1 = __expf(facc[f][1] - nm0);
            float p2 = __expf(facc[f][2] - nm1);
            float p3 = __expf(facc[f][3] - nm1);
            s0 += p0 + p1;
            s1 += p2 + p3;
            __half2 hp = __floats2half2_rn(p0, p1);
            __half2 hq = __floats2half2_rn(p2, p3);
            int ks = f >> 1, half = f & 1;
            pa[ks][2 * half]     = *reinterpret_cast<uint32_t*>(&hp);
            pa[ks][2 * half + 1] = *reinterpret_cast<uint32_t*>(&hq);
        }
        s0 += __shfl_xor_sync(0xffffffffu, s0, 1);
        s0 += __shfl_xor_sync(0xffffffffu, s0, 2);
        s1 += __shfl_xor_sync(0xffffffffu, s1, 1);
        s1 += __shfl_xor_sync(0xffffffffu, s1, 2);
        lr0 = lr0 * al0 + s0;
        lr1 = lr1 * al1 + s1;
        #pragma unroll
        for (int ks = 0; ks < 8; ks++) {
            #pragma unroll
            for (int g2 = 0; g2 < 4; g2++) {
                uint32_t vb[4];
                int r = g2 * 16 + rB;
                uint32_t addr = sV + r * 256 + ((((ks << 5) + ((mi >> 1) << 4))) ^ ((r & 7) << 4));
                LDSM4(vb, addr);
                MMAF16(oacc[2 * g2],     pa[ks], vb[0], vb[2]);
                MMAF16(oacc[2 * g2 + 1], pa[ks], vb[1], vb[3]);
            }
        }
    }

    float inv0 = 1.0f / lr0, inv1 = 1.0f / lr1;
    size_t t0 = (size_t)(tokQ + myr0) * DMODEL + ho;
    size_t t1 = t0 + (size_t)8 * DMODEL;
    #pragma unroll
    for (int f = 0; f < 8; f++) {
        int dc = f * 8 + 2 * (lane & 3);
        __half2 a = __floats2half2_rn(oacc[f][0] * inv0, oacc[f][1] * inv0);
        __half2 b2 = __floats2half2_rn(oacc[f][2] * inv1, oacc[f][3] * inv1);
        *reinterpret_cast<uint32_t*>(cf + t0 + dc) = *reinterpret_cast<uint32_t*>(&a);
        *reinterpret_cast<uint32_t*>(cf + t1 + dc) = *reinterpret_cast<uint32_t*>(&b2);
    }
}

// ---------------- weight transpose (f32 [K,N] -> fp16 [N,K]) ----------------
__device__ __forceinline__ void transpose_f16(const float* __restrict__ in,
        __half* __restrict__ out, int K, int N) {
    __shared__ float t[32][33];
    int n0 = blockIdx.x << 5, k0 = blockIdx.y << 5;
    int tx = threadIdx.x, ty = threadIdx.y;
    #pragma unroll
    for (int r = 0; r < 4; r++)
        t[ty + 8 * r][tx] = in[(size_t)(k0 + ty + 8 * r) * N + n0 + tx];
    __syncthreads();
    #pragma unroll
    for (int r = 0; r < 4; r++)
        out[(size_t)(n0 + ty + 8 * r) * K + k0 + tx] = __float2half_rn(t[tx][ty + 8 * r]);
}
__global__ void wcvt_qkvo_k(const float* __restrict__ Wq, const float* __restrict__ Wk,
                            const float* __restrict__ Wv, const float* __restrict__ Wo,
                            __half* __restrict__ oqkv, __half* __restrict__ oo) {
    int z = blockIdx.z, l = z >> 2, m = z & 3;
    const float* W = (m == 0 ? Wq : m == 1 ? Wk : m == 2 ? Wv : Wo) + (size_t)l * DDSZ;
    __half* dst = (m < 3) ? (oqkv + ((size_t)l * 3 + m) * DDSZ) : (oo + (size_t)l * DDSZ);
    transpose_f16(W, dst, DMODEL, DMODEL);
}
__global__ void wcvt_w1_k(const float* __restrict__ W1, __half* __restrict__ out) {
    int l = blockIdx.z;
    transpose_f16(W1 + (size_t)l * DFSZ, out + (size_t)l * DFSZ, DMODEL, FFDIM);
}
__global__ void wcvt_w2_k(const float* __restrict__ W2, __half* __restrict__ out) {
    int l = blockIdx.z;
    transpose_f16(W2 + (size_t)l * DFSZ, out + (size_t)l * DFSZ, FFDIM, DMODEL);
}

// ---------------- helpers ----------------
__device__ __forceinline__ int detect_i64(const void* p, int n) {
    const long long* x = (const long long*)p;
    int c = n < 32 ? n : 32;
    for (int i = 0; i < c; i++) {
        long long v = x[i];
        if (v < 0 || v >= VOCAB) return 0;
    }
    return 1;
}
__device__ __forceinline__ long long load_index(const void* p, int i, int is64) {
    return is64 ? ((const long long*)p)[i] : (long long)((const int*)p)[i];
}

// ---------------- embedding (+ qkv bias concat + emb fp16 cvt) ----------------
__global__ __launch_bounds__(256) void embed_k(const void* __restrict__ xr,
                                               const float* __restrict__ te,
                                               const float* __restrict__ pe,
                                               float* __restrict__ h,
                                               const float* __restrict__ bq,
                                               const float* __restrict__ bk,
                                               const float* __restrict__ bv,
                                               float* __restrict__ bqkv,
                                               __half* __restrict__ embf) {
    __shared__ int mode;
    if (threadIdx.x == 0) mode = detect_i64(xr, BS);
    __syncthreads();
    int pos = blockIdx.x;
    int tid = threadIdx.x;
    if (pos < NLAYER) {
        #pragma unroll
        for (int t = tid; t < DMODEL; t += 256) {
            bqkv[pos * QKVS + t]        = bq[pos * DMODEL + t];
            bqkv[pos * QKVS + 512 + t]  = bk[pos * DMODEL + t];
            bqkv[pos * QKVS + 1024 + t] = bv[pos * DMODEL + t];
        }
    }
    long long idx = load_index(xr, pos, mode);
    int s = pos & (SEQ - 1);
    const float* t = te + idx * DMODEL;
    const float* p = pe + (long long)s * DMODEL;
    float* o = h + (long long)pos * DMODEL;
    o[tid]       = t[tid]       + p[tid];
    o[tid + 256] = t[tid + 256] + p[tid + 256];
    // strided emb fp16 conversion slice
    size_t n4 = (size_t)VOCAB * DMODEL / 4;
    for (size_t i = (size_t)pos * 256 + tid; i < n4; i += (size_t)BS * 256) {
        float4 v = reinterpret_cast<const float4*>(te)[i];
        __half2 a = __floats2half2_rn(v.x, v.y);
        __half2 b = __floats2half2_rn(v.z, v.w);
        uint2 w;
        w.x = *reinterpret_cast<uint32_t*>(&a);
        w.y = *reinterpret_cast<uint32_t*>(&b);
        reinterpret_cast<uint2*>(embf)[i] = w;
    }
}

// ---------------- layernorm -> fp16 ----------------
__global__ __launch_bounds__(256) void ln_k(const float* __restrict__ in,
                                            const float* __restrict__ g,
                                            const float* __restrict__ b,
                                            __half* __restrict__ of) {
    int row = blockIdx.x;
    int tid = threadIdx.x;
    int lane = tid & 31, wid = tid >> 5;
    const float* x = in + (long long)row * DMODEL;
    float v0 = x[tid], v1 = x[tid + 256];
    __shared__ float wr[16];
    float s = v0 + v1;
    #pragma unroll
    for (int o = 16; o; o >>= 1) s += __shfl_xor_sync(0xffffffffu, s, o);
    if (lane == 0) wr[wid] = s;
    __syncthreads();
    float mu = (wr[0] + wr[1] + wr[2] + wr[3] + wr[4] + wr[5] + wr[6] + wr[7]) * (1.0f / DMODEL);
    float d0 = v0 - mu, d1 = v1 - mu;
    float q = d0 * d0 + d1 * d1;
    #pragma unroll
    for (int o = 16; o; o >>= 1) q += __shfl_xor_sync(0xffffffffu, q, o);
    if (lane == 0) wr[8 + wid] = q;
    __syncthreads();
    float var = (wr[8] + wr[9] + wr[10] + wr[11] + wr[12] + wr[13] + wr[14] + wr[15]) * (1.0f / DMODEL);
    float rstd = rsqrtf(var + 1e-5f);
    long long base = (long long)row * DMODEL;
    float y0 = d0 * rstd * g[tid] + b[tid];
    float y1 = d1 * rstd * g[tid + 256] + b[tid + 256];
    of[base + tid]       = __float2half_rn(y0);
    of[base + tid + 256] = __float2half_rn(y1);
}

// ---------------- cross-entropy from fused partials ----------------
__global__ __launch_bounds__(256) void loss_row_k(const float2* __restrict__ part,
                                                  const float* __restrict__ logits,
                                                  const void* __restrict__ tr,
                                                  float* __restrict__ rowloss) {
    __shared__ int mode;
    __shared__ float rm[256], rs[256];
    int row = blockIdx.x, tid = threadIdx.x;
    if (tid == 0) mode = detect_i64(tr, BS);
    __syncthreads();
    const float2* pr = part + (size_t)row * NPART;
    float m = -1e30f, s = 0.0f;
    for (int j = tid; j < NPART; j += 256) {
        float2 p = pr[j];
        float nm = fmaxf(m, p.x);
        s = s * __expf(m - nm) + p.y * __expf(p.x - nm);
        m = nm;
    }
    rm[tid] = m;
    rs[tid] = s;
    __syncthreads();
    #pragma unroll
    for (int st = 128; st > 0; st >>= 1) {
        if (tid < st) {
            float ma = rm[tid], mb = rm[tid + st];
            float nm = fmaxf(ma, mb);
            rs[tid] = rs[tid] * __expf(ma - nm) + rs[tid + st] * __expf(mb - nm);
            rm[tid] = nm;
        }
        __syncthreads();
    }
    if (tid == 0) {
        long long t = load_index(tr, row, mode);
        rowloss[row] = -(logits[(size_t)row * VOCAB + t] - rm[0] - logf(rs[0]));
    }
}

__global__ __launch_bounds__(1024) void loss_reduce_k(const float* __restrict__ rowloss,
                                                      float* __restrict__ out) {
    __shared__ float red[1024];
    int tid = threadIdx.x;
    red[tid] = rowloss[tid] + rowloss[tid + 1024] + rowloss[tid + 2048] + rowloss[tid + 3072];
    __syncthreads();
    #pragma unroll
    for (int s = 512; s > 0; s >>= 1) {
        if (tid < s) red[tid] += red[tid + s];
        __syncthreads();
    }
    if (tid == 0) out[0] = red[0] * (1.0f / BS);
}

// ---------------- host launcher ----------------
extern "C" void kernel_launch(void* const* d_in, const int* in_sizes, int n_in,
                              void* d_out, int out_size) {
    (void)in_sizes; (void)n_in;
    const void*  x       = d_in[0];
    const void*  targets = d_in[1];
    const float* te   = (const float*)d_in[2];
    const float* pe   = (const float*)d_in[3];
    const float* ln1g = (const float*)d_in[4];
    const float* ln1b = (const float*)d_in[5];
    const float* Wq   = (const float*)d_in[6];
    const float* bq   = (const float*)d_in[7];
    const float* Wk   = (const float*)d_in[8];
    const float* bk   = (const float*)d_in[9];
    const float* Wv   = (const float*)d_in[10];
    const float* bv   = (const float*)d_in[11];
    const float* Wo   = (const float*)d_in[12];
    const float* bo   = (const float*)d_in[13];
    const float* ln2g = (const float*)d_in[14];
    const float* ln2b = (const float*)d_in[15];
    const float* W1   = (const float*)d_in[16];
    const float* b1   = (const float*)d_in[17];
    const float* W2   = (const float*)d_in[18];
    const float* b2   = (const float*)d_in[19];
    const float* lnfg = (const float*)d_in[20];
    const float* lnfb = (const float*)d_in[21];
    float* out = (float*)d_out;

    float *p_h, *p_rowloss, *p_logits, *p_bqkv;
    float2* p_part;
    __half *p_xnf, *p_qkvf, *p_ctxf, *p_fff, *p_wqkvf, *p_wof, *p_w1f, *p_w2f, *p_embf;
    cudaGetSymbolAddress((void**)&p_h, g_h);
    cudaGetSymbolAddress((void**)&p_rowloss, g_rowloss);
    cudaGetSymbolAddress((void**)&p_logits, g_logits_scratch);
    cudaGetSymbolAddress((void**)&p_bqkv, g_bqkv);
    cudaGetSymbolAddress((void**)&p_part, g_part);
    cudaGetSymbolAddress((void**)&p_xnf, g_xnf);
    cudaGetSymbolAddress((void**)&p_qkvf, g_qkvf);
    cudaGetSymbolAddress((void**)&p_ctxf, g_ctxf);
    cudaGetSymbolAddress((void**)&p_fff, g_fff);
    cudaGetSymbolAddress((void**)&p_wqkvf, g_wqkvf);
    cudaGetSymbolAddress((void**)&p_wof, g_wof);
    cudaGetSymbolAddress((void**)&p_w1f, g_w1f);
    cudaGetSymbolAddress((void**)&p_w2f, g_w2f);
    cudaGetSymbolAddress((void**)&p_embf, g_embf);

    cudaFuncSetAttribute(gemm_f16<0>, cudaFuncAttributeMaxDynamicSharedMemorySize, GEMM_SMEM_F);
    cudaFuncSetAttribute(gemm_f16<1>, cudaFuncAttributeMaxDynamicSharedMemorySize, GEMM_SMEM_F);
    cudaFuncSetAttribute(gemm_f16<2>, cudaFuncAttributeMaxDynamicSharedMemorySize, GEMM_SMEM_F);
    cudaFuncSetAttribute(gemm_f16<3>, cudaFuncAttributeMaxDynamicSharedMemorySize, GEMM_SMEM_F);
    cudaFuncSetAttribute(fattn_k, cudaFuncAttributeMaxDynamicSharedMemorySize, ATT_SMEM);

    wcvt_qkvo_k<<<dim3(16, 16, NLAYER * 4), dim3(32, 8)>>>(Wq, Wk, Wv, Wo, p_wqkvf, p_wof);
    wcvt_w1_k<<<dim3(64, 16, NLAYER), dim3(32, 8)>>>(W1, p_w1f);
    wcvt_w2_k<<<dim3(16, 64, NLAYER), dim3(32, 8)>>>(W2, p_w2f);
    embed_k<<<BS, 256>>>(x, te, pe, p_h, bq, bk, bv, p_bqkv, p_embf);

    dim3 gDD(BS / 128, DMODEL / 128);
    dim3 gQKV(BS / 128, QKVS / 128);
    dim3 gDF(BS / 128, FFDIM / 128);
    dim3 gATT(SEQ / 128, BATCH * NHEAD);

    for (int l = 0; l < NLAYER; l++) {
        __half* wqkv_l = p_wqkvf + (size_t)l * 3 * DDSZ;
        __half* wof_l = p_wof + (size_t)l * DDSZ;
        __half* w1f_l = p_w1f + (size_t)l * DFSZ;
        __half* w2f_l = p_w2f + (size_t)l * DFSZ;

        ln_k<<<BS, 256>>>(p_h, ln1g + l * DMODEL, ln1b + l * DMODEL, p_xnf);
        gemm_f16<3><<<gQKV, 256, GEMM_SMEM_F>>>(p_xnf, wqkv_l, p_bqkv + l * QKVS, nullptr,
                                                nullptr, p_qkvf, nullptr, BS, QKVS, DMODEL);
        fattn_k<<<gATT, 256, ATT_SMEM>>>(p_qkvf, p_ctxf);
        gemm_f16<2><<<gDD, 256, GEMM_SMEM_F>>>(p_ctxf, wof_l, bo + l * DMODEL, p_h,
                                               p_h, nullptr, nullptr, BS, DMODEL, DMODEL);
        ln_k<<<BS, 256>>>(p_h, ln2g + l * DMODEL, ln2b + l * DMODEL, p_xnf);
        gemm_f16<1><<<gDF, 256, GEMM_SMEM_F>>>(p_xnf, w1f_l, b1 + l * FFDIM, nullptr,
                                               nullptr, p_fff, nullptr, BS, FFDIM, DMODEL);
        gemm_f16<2><<<gDD, 256, GEMM_SMEM_F>>>(p_fff, w2f_l, b2 + l * DMODEL, p_h,
                                               p_h, nullptr, nullptr, BS, DMODEL, FFDIM);
    }

    ln_k<<<BS, 256>>>(p_h, lnfg, lnfb, p_xnf);

    float* logits = ((long long)out_size >= NLOG) ? out : p_logits;
    dim3 gLOG(BS / 128, VPAD / 128);
    gemm_f16<0><<<gLOG, 256, GEMM_SMEM_F>>>(p_xnf, p_embf, nullptr, nullptr,
                                            logits, nullptr, p_part, BS, VOCAB, DMODEL);

    loss_row_k<<<BS, 256>>>(p_part, logits, targets, p_rowloss);
    if ((long long)out_size > NLOG) {
        loss_reduce_k<<<1, 1024>>>(p_rowloss, out + NLOG);
    } else if ((long long)out_size < NLOG && out_size >= 1) {
        loss_reduce_k<<<1, 1024>>>(p_rowloss, out + (out_size - 1));
    }
}

// round 11
// speedup vs baseline: 3.0220x; 1.1201x over previous
#include <cuda_runtime.h>
#include <cuda_bf16.h>
#include <cuda_fp16.h>
#include <math.h>
#include <stdint.h>

// ---------------- model constants ----------------
#define BATCH  8
#define SEQ    512
#define DMODEL 512
#define NHEAD  8
#define HEADD  64
#define FFDIM  2048
#define NLAYER 6
#define VOCAB  50257
#define VPAD   50304                  // 393*128
#define NPART  786
#define BS     (BATCH*SEQ)
#define QKVS   1536
static const long long NLOG = (long long)BS * VOCAB;

#define DDSZ   (DMODEL*DMODEL)
#define DFSZ   (DMODEL*FFDIM)

// ---------------- device scratch ----------------
__device__ float g_h[BS * DMODEL];
__device__ float g_rowloss[BS];
__device__ float g_bqkv[NLAYER * QKVS];
__device__ float g_logits_scratch[(size_t)BS * VOCAB];
__device__ float2 g_part[(size_t)BS * NPART];
__device__ __half g_xnf[BS * DMODEL];
__device__ __half g_qkvf[BS * QKVS];
__device__ __half g_ctxf[BS * DMODEL];
__device__ __half g_fff[BS * FFDIM];
__device__ __half g_wqkvf[(size_t)3 * DDSZ * NLAYER];
__device__ __half g_wof[(size_t)DDSZ * NLAYER];
__device__ __half g_w1f[(size_t)DFSZ * NLAYER];
__device__ __half g_w2f[(size_t)DFSZ * NLAYER];
__device__ __half g_embf[(size_t)VPAD * DMODEL];

// ================= PTX helpers =================
__device__ __forceinline__ uint32_t smem_to_u32(const void* smem_ptr) {
    uint32_t addr;
    asm("{ .reg .u64 tmp; cvta.to.shared.u64 tmp, %1; cvt.u32.u64 %0, tmp; }"
        : "=r"(addr) : "l"(smem_ptr));
    return addr;
}
__device__ __forceinline__ void cp16(uint32_t d, const void* s, int sz) {
    asm volatile("cp.async.cg.shared.global [%0], [%1], 16, %2;\n"
                 :: "r"(d), "l"(s), "r"(sz) : "memory");
}
__device__ __forceinline__ void cp_commit() {
    asm volatile("cp.async.commit_group;\n" ::: "memory");
}
__device__ __forceinline__ void cp_wait0() {
    asm volatile("cp.async.wait_group 0;\n" ::: "memory");
}
__device__ __forceinline__ void cp_wait1() {
    asm volatile("cp.async.wait_group 1;\n" ::: "memory");
}
#define LDSM4(r, addr) \
    asm volatile("ldmatrix.sync.aligned.m8n8.x4.shared.b16 {%0,%1,%2,%3}, [%4];" \
        : "=r"((r)[0]), "=r"((r)[1]), "=r"((r)[2]), "=r"((r)[3]) : "r"(addr))
#define MMAF16(c, a, b0, b1) \
    asm volatile("mma.sync.aligned.m16n8k16.row.col.f32.f16.f16.f32 " \
        "{%0,%1,%2,%3}, {%4,%5,%6,%7}, {%8,%9}, {%0,%1,%2,%3};" \
        : "+f"((c)[0]), "+f"((c)[1]), "+f"((c)[2]), "+f"((c)[3]) \
        : "r"((a)[0]), "r"((a)[1]), "r"((a)[2]), "r"((a)[3]), "r"(b0), "r"(b1))

#define TB 16384
#define SMEM_OFF 1024

// ================= M128 fp16 GEMM (logits only: EPI 0 = f32 + CE partials) =================
#define FSTAGE (2*TB)
#define GEMM_SMEM_F (SMEM_OFF + 2*FSTAGE)

__device__ __forceinline__ void copy_stage_f(uint32_t st,
        const __half* __restrict__ A, const __half* __restrict__ B,
        int bm, int bn, int k0, int K, int N, int tid) {
    #pragma unroll
    for (int it = 0; it < 4; it++) {
        int idx = tid + it * 256;
        int row = idx >> 3, c = idx & 7;
        uint32_t d = st + row * 128 + ((c ^ (row & 7)) << 4);
        size_t so = (size_t)(bm + row) * K + k0 + c * 8;
        cp16(d, A + so, 16);
    }
    #pragma unroll
    for (int it = 0; it < 4; it++) {
        int idx = tid + it * 256;
        int row = idx >> 3, c = idx & 7;
        int n = bn + row;
        int sz = (n < N) ? 16 : 0;
        uint32_t d = st + TB + row * 128 + ((c ^ (row & 7)) << 4);
        size_t so = (size_t)n * K + k0 + c * 8;
        cp16(d, B + so, sz);
    }
}

__global__ void __launch_bounds__(256, 2)
gemm_logits(const __half* __restrict__ A, const __half* __restrict__ B,
            float* __restrict__ C, float2* __restrict__ part,
            int M, int N, int K) {
    extern __shared__ char smem[];
    const int tid = threadIdx.x;
    const int bm = blockIdx.x * 128;
    const int bn = blockIdx.y * 128;
    const int nc = K >> 6;

    const uint32_t tiles = smem_to_u32(smem) + SMEM_OFF;
    const int lane = tid & 31;
    const int wid = tid >> 5;
    const int wm = (wid & 3) << 5;
    const int wn = (wid >> 2) << 6;
    const int mi = lane >> 3;
    const int lrow = lane & 7;

    float acc[2][8][4];
    #pragma unroll
    for (int i = 0; i < 2; i++)
        #pragma unroll
        for (int j = 0; j < 8; j++)
            #pragma unroll
            for (int t = 0; t < 4; t++) acc[i][j][t] = 0.0f;

    copy_stage_f(tiles, A, B, bm, bn, 0, K, N, tid);
    cp_commit();

    for (int c = 0; c < nc; c++) {
        if (c + 1 < nc) {
            copy_stage_f(tiles + ((c + 1) & 1) * FSTAGE, A, B, bm, bn, (c + 1) << 6, K, N, tid);
            cp_commit();
            cp_wait1();
        } else {
            cp_wait0();
        }
        __syncthreads();

        const uint32_t st = tiles + (c & 1) * FSTAGE;
        #pragma unroll
        for (int s = 0; s < 4; s++) {
            const int cb = (s << 5) + ((mi >> 1) << 4);
            uint32_t af[2][4], bf[4][4];
            #pragma unroll
            for (int i = 0; i < 2; i++) {
                int r = wm + (i << 4) + ((mi & 1) << 3) + lrow;
                LDSM4(af[i], st + r * 128 + (cb ^ ((r & 7) << 4)));
            }
            #pragma unroll
            for (int j2 = 0; j2 < 4; j2++) {
                int r = wn + (j2 << 4) + ((mi & 1) << 3) + lrow;
                LDSM4(bf[j2], st + TB + r * 128 + (cb ^ ((r & 7) << 4)));
            }
            #pragma unroll
            for (int i = 0; i < 2; i++)
                #pragma unroll
                for (int j2 = 0; j2 < 4; j2++) {
                    MMAF16(acc[i][2 * j2],     af[i], bf[j2][0], bf[j2][2]);
                    MMAF16(acc[i][2 * j2 + 1], af[i], bf[j2][1], bf[j2][3]);
                }
        }
        __syncthreads();
    }

    // logits store + fused per-(row, 64-col-half) softmax partials
    #pragma unroll
    for (int i = 0; i < 2; i++) {
        #pragma unroll
        for (int hr = 0; hr < 2; hr++) {
            int row = bm + wm + (i << 4) + (lane >> 2) + hr * 8;
            size_t base = (size_t)row * N;
            float pm = -1e30f, ps = 0.0f;
            #pragma unroll
            for (int j = 0; j < 8; j++) {
                #pragma unroll
                for (int u = 0; u < 2; u++) {
                    int cc = bn + wn + (j << 3) + ((lane & 3) << 1) + u;
                    if (cc < N) {
                        float x = acc[i][j][hr * 2 + u];
                        C[base + cc] = x;
                        float nm = fmaxf(pm, x);
                        ps = ps * __expf(pm - nm) + __expf(x - nm);
                        pm = nm;
                    }
                }
            }
            #pragma unroll
            for (int off = 1; off <= 2; off <<= 1) {
                float om = __shfl_xor_sync(0xffffffffu, pm, off);
                float os = __shfl_xor_sync(0xffffffffu, ps, off);
                float nm = fmaxf(pm, om);
                ps = ps * __expf(pm - nm) + os * __expf(om - nm);
                pm = nm;
            }
            if ((lane & 3) == 0)
                part[(size_t)row * NPART + blockIdx.y * 2 + (wid >> 2)] = make_float2(pm, ps);
        }
    }
}

// ================= M64 fp16 GEMM (layer GEMMs) =================
// CTA 64x128, 8 warps as 2(m) x 4(n), warp tile 32x32.
// EPI: 1 = bias+gelu -> fp16; 2 = bias+res -> f32; 3 = bias -> fp16
#define STAGE64 (8192 + TB)
#define GEMM_SMEM_64 (SMEM_OFF + 2*STAGE64)   // 50176

__device__ __forceinline__ void copy_stage_64(uint32_t st,
        const __half* __restrict__ A, const __half* __restrict__ B,
        int bm, int bn, int k0, int K, int tid) {
    #pragma unroll
    for (int it = 0; it < 2; it++) {
        int idx = tid + it * 256;
        int row = idx >> 3, c = idx & 7;
        uint32_t d = st + row * 128 + ((c ^ (row & 7)) << 4);
        size_t so = (size_t)(bm + row) * K + k0 + c * 8;
        cp16(d, A + so, 16);
    }
    #pragma unroll
    for (int it = 0; it < 4; it++) {
        int idx = tid + it * 256;
        int row = idx >> 3, c = idx & 7;
        uint32_t d = st + 8192 + row * 128 + ((c ^ (row & 7)) << 4);
        size_t so = (size_t)(bn + row) * K + k0 + c * 8;
        cp16(d, B + so, 16);
    }
}

template <int EPI>
__global__ void __launch_bounds__(256, 2)
gemm_64(const __half* __restrict__ A, const __half* __restrict__ B,
        const float* __restrict__ bias, const float* __restrict__ res,
        float* __restrict__ C, __half* __restrict__ Cf,
        int M, int N, int K) {
    extern __shared__ char smem[];
    const int tid = threadIdx.x;
    const int bm = blockIdx.x * 64;
    const int bn = blockIdx.y * 128;
    const int nc = K >> 6;

    const uint32_t tiles = smem_to_u32(smem) + SMEM_OFF;
    const int lane = tid & 31;
    const int wid = tid >> 5;
    const int wm = (wid & 1) << 5;     // 0 or 32
    const int wn = (wid >> 1) << 5;    // 0,32,64,96
    const int mi = lane >> 3;
    const int lrow = lane & 7;

    float acc[2][4][4];
    #pragma unroll
    for (int i = 0; i < 2; i++)
        #pragma unroll
        for (int j = 0; j < 4; j++)
            #pragma unroll
            for (int t = 0; t < 4; t++) acc[i][j][t] = 0.0f;

    copy_stage_64(tiles, A, B, bm, bn, 0, K, tid);
    cp_commit();

    for (int c = 0; c < nc; c++) {
        if (c + 1 < nc) {
            copy_stage_64(tiles + ((c + 1) & 1) * STAGE64, A, B, bm, bn, (c + 1) << 6, K, tid);
            cp_commit();
            cp_wait1();
        } else {
            cp_wait0();
        }
        __syncthreads();

        const uint32_t st = tiles + (c & 1) * STAGE64;
        #pragma unroll
        for (int s = 0; s < 4; s++) {
            const int cb = (s << 5) + ((mi >> 1) << 4);
            uint32_t af[2][4], bf[2][4];
            #pragma unroll
            for (int i = 0; i < 2; i++) {
                int r = wm + (i << 4) + ((mi & 1) << 3) + lrow;
                LDSM4(af[i], st + r * 128 + (cb ^ ((r & 7) << 4)));
            }
            #pragma unroll
            for (int j2 = 0; j2 < 2; j2++) {
                int r = wn + (j2 << 4) + ((mi & 1) << 3) + lrow;
                LDSM4(bf[j2], st + 8192 + r * 128 + (cb ^ ((r & 7) << 4)));
            }
            #pragma unroll
            for (int i = 0; i < 2; i++)
                #pragma unroll
                for (int j2 = 0; j2 < 2; j2++) {
                    MMAF16(acc[i][2 * j2],     af[i], bf[j2][0], bf[j2][2]);
                    MMAF16(acc[i][2 * j2 + 1], af[i], bf[j2][1], bf[j2][3]);
                }
        }
        __syncthreads();
    }

    #pragma unroll
    for (int i = 0; i < 2; i++) {
        int row = bm + wm + (i << 4) + (lane >> 2);
        size_t base = (size_t)row * N;
        size_t base8 = base + (size_t)8 * N;
        #pragma unroll
        for (int j = 0; j < 4; j++) {
            int col = bn + wn + (j << 3) + ((lane & 3) << 1);
            float b0 = __ldg(bias + col), b1 = __ldg(bias + col + 1);
            #pragma unroll
            for (int hr = 0; hr < 2; hr++) {
                size_t off = (hr == 0 ? base : base8) + col;
                float x0 = acc[i][j][hr * 2 + 0] + b0;
                float x1 = acc[i][j][hr * 2 + 1] + b1;
                if (EPI == 1) {
                    x0 = 0.5f * x0 * (1.0f + erff(x0 * 0.70710678118654752440f));
                    x1 = 0.5f * x1 * (1.0f + erff(x1 * 0.70710678118654752440f));
                    __half2 hv = __floats2half2_rn(x0, x1);
                    *reinterpret_cast<uint32_t*>(Cf + off) = *reinterpret_cast<uint32_t*>(&hv);
                } else if (EPI == 2) {
                    float2 r2 = *reinterpret_cast<const float2*>(res + off);
                    *reinterpret_cast<float2*>(C + off) = make_float2(x0 + r2.x, x1 + r2.y);
                } else {
                    __half2 hv = __floats2half2_rn(x0, x1);
                    *reinterpret_cast<uint32_t*>(Cf + off) = *reinterpret_cast<uint32_t*>(&hv);
                }
            }
        }
    }
}

// ---------------- flash attention (fp16 single-pass) ----------------
#define ATT_SMEM (3*16384)
__global__ void __launch_bounds__(256, 1)
fattn_k(const __half* __restrict__ qkv, __half* __restrict__ cf) {
    extern __shared__ char smx[];
    const uint32_t sQ = smem_to_u32(smx);
    const uint32_t sK = sQ + 16384;
    const uint32_t sV = sQ + 32768;
    const int tid = threadIdx.x;
    const int lane = tid & 31, wid = tid >> 5;
    const int qt = gridDim.y - 1 - blockIdx.y;   // big tiles scheduled first
    const int bh = blockIdx.x;
    const int b = bh >> 3, h = bh & 7;
    const int tokQ = b * SEQ + qt * 128;
    const int ho = h * HEADD;
    const int mi = lane >> 3, lrow = lane & 7;
    const int wm = wid * 16;
    const int rB = ((mi & 1) << 3) + lrow;

    #pragma unroll
    for (int it = 0; it < 4; it++) {
        int idx = tid + it * 256;
        int r = idx >> 3, c = idx & 7;
        uint32_t d = sQ + r * 128 + ((c ^ (r & 7)) << 4);
        size_t so = (size_t)(tokQ + r) * QKVS + ho + c * 8;
        cp16(d, qkv + so, 16);
    }
    cp_commit();
    cp_wait0();
    __syncthreads();

    uint32_t aq[4][4];
    {
        int r = wm + rB;
        #pragma unroll
        for (int s = 0; s < 4; s++) {
            uint32_t addr = sQ + r * 128 + ((((s << 5) + ((mi >> 1) << 4))) ^ ((r & 7) << 4));
            LDSM4(aq[s], addr);
        }
    }

    float oacc[8][4];
    #pragma unroll
    for (int f = 0; f < 8; f++)
        #pragma unroll
        for (int t = 0; t < 4; t++) oacc[f][t] = 0.0f;
    float mr0 = -1e30f, mr1 = -1e30f, lr0 = 0.0f, lr1 = 0.0f;
    const int myr0 = wm + (lane >> 2);
    const int myr1 = myr0 + 8;

    for (int jt = 0; jt <= qt; jt++) {
        __syncthreads();
        const int tokJ = b * SEQ + jt * 128;
        #pragma unroll
        for (int it = 0; it < 4; it++) {
            int idx = tid + it * 256;
            int r = idx >> 3, c = idx & 7;
            uint32_t d = sK + r * 128 + ((c ^ (r & 7)) << 4);
            size_t so = (size_t)(tokJ + r) * QKVS + 512 + ho + c * 8;
            cp16(d, qkv + so, 16);
        }
        #pragma unroll
        for (int it = 0; it < 4; it++) {
            int task = tid + it * 256;
            int j = task >> 3, c = task & 7;
            size_t so = (size_t)(tokJ + j) * QKVS + 1024 + ho + c * 8;
            uint4 v4 = *reinterpret_cast<const uint4*>(qkv + so);
            const uint32_t* wv = &v4.x;
            #pragma unroll
            for (int i = 0; i < 8; i++) {
                int dd = c * 8 + i;
                uint32_t off = dd * 256 + ((((uint32_t)(j >> 3) ^ (uint32_t)(dd & 7)) << 4)) + (j & 7) * 2;
                uint16_t hv = (uint16_t)(wv[i >> 1] >> ((i & 1) * 16));
                asm volatile("st.shared.u16 [%0], %1;" :: "r"(sV + off), "h"(hv));
            }
        }
        cp_commit();
        cp_wait0();
        __syncthreads();

        float facc[16][4];
        #pragma unroll
        for (int f = 0; f < 16; f++)
            #pragma unroll
            for (int t = 0; t < 4; t++) facc[f][t] = 0.0f;
        #pragma unroll
        for (int g = 0; g < 8; g++) {
            int r = g * 16 + rB;
            #pragma unroll
            for (int s = 0; s < 4; s++) {
                uint32_t kb[4];
                uint32_t addr = sK + r * 128 + ((((s << 5) + ((mi >> 1) << 4))) ^ ((r & 7) << 4));
                LDSM4(kb, addr);
                MMAF16(facc[2 * g],     aq[s], kb[0], kb[2]);
                MMAF16(facc[2 * g + 1], aq[s], kb[1], kb[3]);
            }
        }
        const float scl = 0.125f;
        #pragma unroll
        for (int f = 0; f < 16; f++) {
            int c0 = f * 8 + 2 * (lane & 3);
            facc[f][0] *= scl; facc[f][1] *= scl;
            facc[f][2] *= scl; facc[f][3] *= scl;
            if (jt == qt) {
                if (c0     > myr0) facc[f][0] = -1e30f;
                if (c0 + 1 > myr0) facc[f][1] = -1e30f;
                if (c0     > myr1) facc[f][2] = -1e30f;
                if (c0 + 1 > myr1) facc[f][3] = -1e30f;
            }
        }
        float m0 = -1e30f, m1 = -1e30f;
        #pragma unroll
        for (int f = 0; f < 16; f++) {
            m0 = fmaxf(m0, fmaxf(facc[f][0], facc[f][1]));
            m1 = fmaxf(m1, fmaxf(facc[f][2], facc[f][3]));
        }
        m0 = fmaxf(m0, __shfl_xor_sync(0xffffffffu, m0, 1));
        m0 = fmaxf(m0, __shfl_xor_sync(0xffffffffu, m0, 2));
        m1 = fmaxf(m1, __shfl_xor_sync(0xffffffffu, m1, 1));
        m1 = fmaxf(m1, __shfl_xor_sync(0xffffffffu, m1, 2));
        float nm0 = fmaxf(mr0, m0), nm1 = fmaxf(mr1, m1);
        float al0 = __expf(mr0 - nm0), al1 = __expf(mr1 - nm1);
        mr0 = nm0; mr1 = nm1;
        #pragma unroll
        for (int f = 0; f < 8; f++) {
            oacc[f][0] *= al0; oacc[f][1] *= al0;
            oacc[f][2] *= al1; oacc[f][3] *= al1;
        }
        float s0 = 0.0f, s1 = 0.0f;
        uint32_t pa[8][4];
        #pragma unroll
        for (int f = 0; f < 16; f++) {
            float p0 = __expf(facc[f][0] - nm0);
            float p1 = __expf(facc[f][1] - nm0);
            float p2 = __expf(facc[f][2] - nm1);
            float p3 = __expf(facc[f][3] - nm1);
            s0 += p0 + p1;
            s1 += p2 + p3;
            __half2 hp = __floats2half2_rn(p0, p1);
            __half2 hq = __floats2half2_rn(p2, p3);
            int ks = f >> 1, half = f & 1;
            pa[ks][2 * half]     = *reinterpret_cast<uint32_t*>(&hp);
            pa[ks][2 * half + 1] = *reinterpret_cast<uint32_t*>(&hq);
        }
        s0 += __shfl_xor_sync(0xffffffffu, s0, 1);
        s0 += __shfl_xor_sync(0xffffffffu, s0, 2);
        s1 += __shfl_xor_sync(0xffffffffu, s1, 1);
        s1 += __shfl_xor_sync(0xffffffffu, s1, 2);
        lr0 = lr0 * al0 + s0;
        lr1 = lr1 * al1 + s1;
        #pragma unroll
        for (int ks = 0; ks < 8; ks++) {
            #pragma unroll
            for (int g2 = 0; g2 < 4; g2++) {
                uint32_t vb[4];
                int r = g2 * 16 + rB;
                uint32_t addr = sV + r * 256 + ((((ks << 5) + ((mi >> 1) << 4))) ^ ((r & 7) << 4));
                LDSM4(vb, addr);
                MMAF16(oacc[2 * g2],     pa[ks], vb[0], vb[2]);
                MMAF16(oacc[2 * g2 + 1], pa[ks], vb[1], vb[3]);
            }
        }
    }

    float inv0 = 1.0f / lr0, inv1 = 1.0f / lr1;
    size_t t0 = (size_t)(tokQ + myr0) * DMODEL + ho;
    size_t t1 = t0 + (size_t)8 * DMODEL;
    #pragma unroll
    for (int f = 0; f < 8; f++) {
        int dc = f * 8 + 2 * (lane & 3);
        __half2 a = __floats2half2_rn(oacc[f][0] * inv0, oacc[f][1] * inv0);
        __half2 b2 = __floats2half2_rn(oacc[f][2] * inv1, oacc[f][3] * inv1);
        *reinterpret_cast<uint32_t*>(cf + t0 + dc) = *reinterpret_cast<uint32_t*>(&a);
        *reinterpret_cast<uint32_t*>(cf + t1 + dc) = *reinterpret_cast<uint32_t*>(&b2);
    }
}

// ---------------- weight transpose (f32 [K,N] -> fp16 [N,K]) ----------------
__device__ __forceinline__ void transpose_f16(const float* __restrict__ in,
        __half* __restrict__ out, int K, int N) {
    __shared__ float t[32][33];
    int n0 = blockIdx.x << 5, k0 = blockIdx.y << 5;
    int tx = threadIdx.x, ty = threadIdx.y;
    #pragma unroll
    for (int r = 0; r < 4; r++)
        t[ty + 8 * r][tx] = in[(size_t)(k0 + ty + 8 * r) * N + n0 + tx];
    __syncthreads();
    #pragma unroll
    for (int r = 0; r < 4; r++)
        out[(size_t)(n0 + ty + 8 * r) * K + k0 + tx] = __float2half_rn(t[tx][ty + 8 * r]);
}
__global__ void wcvt_qkvo_k(const float* __restrict__ Wq, const float* __restrict__ Wk,
                            const float* __restrict__ Wv, const float* __restrict__ Wo,
                            __half* __restrict__ oqkv, __half* __restrict__ oo) {
    int z = blockIdx.z, l = z >> 2, m = z & 3;
    const float* W = (m == 0 ? Wq : m == 1 ? Wk : m == 2 ? Wv : Wo) + (size_t)l * DDSZ;
    __half* dst = (m < 3) ? (oqkv + ((size_t)l * 3 + m) * DDSZ) : (oo + (size_t)l * DDSZ);
    transpose_f16(W, dst, DMODEL, DMODEL);
}
__global__ void wcvt_w1_k(const float* __restrict__ W1, __half* __restrict__ out) {
    int l = blockIdx.z;
    transpose_f16(W1 + (size_t)l * DFSZ, out + (size_t)l * DFSZ, DMODEL, FFDIM);
}
__global__ void wcvt_w2_k(const float* __restrict__ W2, __half* __restrict__ out) {
    int l = blockIdx.z;
    transpose_f16(W2 + (size_t)l * DFSZ, out + (size_t)l * DFSZ, FFDIM, DMODEL);
}

// ---------------- helpers ----------------
__device__ __forceinline__ int detect_i64(const void* p, int n) {
    const long long* x = (const long long*)p;
    int c = n < 32 ? n : 32;
    for (int i = 0; i < c; i++) {
        long long v = x[i];
        if (v < 0 || v >= VOCAB) return 0;
    }
    return 1;
}
__device__ __forceinline__ long long load_index(const void* p, int i, int is64) {
    return is64 ? ((const long long*)p)[i] : (long long)((const int*)p)[i];
}

// ---------------- embedding (+ qkv bias concat + emb fp16 cvt) ----------------
__global__ __launch_bounds__(256) void embed_k(const void* __restrict__ xr,
                                               const float* __restrict__ te,
                                               const float* __restrict__ pe,
                                               float* __restrict__ h,
                                               const float* __restrict__ bq,
                                               const float* __restrict__ bk,
                                               const float* __restrict__ bv,
                                               float* __restrict__ bqkv,
                                               __half* __restrict__ embf) {
    __shared__ int mode;
    if (threadIdx.x == 0) mode = detect_i64(xr, BS);
    __syncthreads();
    int pos = blockIdx.x;
    int tid = threadIdx.x;
    if (pos < NLAYER) {
        #pragma unroll
        for (int t = tid; t < DMODEL; t += 256) {
            bqkv[pos * QKVS + t]        = bq[pos * DMODEL + t];
            bqkv[pos * QKVS + 512 + t]  = bk[pos * DMODEL + t];
            bqkv[pos * QKVS + 1024 + t] = bv[pos * DMODEL + t];
        }
    }
    long long idx = load_index(xr, pos, mode);
    int s = pos & (SEQ - 1);
    const float* t = te + idx * DMODEL;
    const float* p = pe + (long long)s * DMODEL;
    float* o = h + (long long)pos * DMODEL;
    o[tid]       = t[tid]       + p[tid];
    o[tid + 256] = t[tid + 256] + p[tid + 256];
    size_t n4 = (size_t)VOCAB * DMODEL / 4;
    for (size_t i = (size_t)pos * 256 + tid; i < n4; i += (size_t)BS * 256) {
        float4 v = reinterpret_cast<const float4*>(te)[i];
        __half2 a = __floats2half2_rn(v.x, v.y);
        __half2 b = __floats2half2_rn(v.z, v.w);
        uint2 w;
        w.x = *reinterpret_cast<uint32_t*>(&a);
        w.y = *reinterpret_cast<uint32_t*>(&b);
        reinterpret_cast<uint2*>(embf)[i] = w;
    }
}

// ---------------- layernorm -> fp16 ----------------
__global__ __launch_bounds__(256) void ln_k(const float* __restrict__ in,
                                            const float* __restrict__ g,
                                            const float* __restrict__ b,
                                            __half* __restrict__ of) {
    int row = blockIdx.x;
    int tid = threadIdx.x;
    int lane = tid & 31, wid = tid >> 5;
    const float* x = in + (long long)row * DMODEL;
    float v0 = x[tid], v1 = x[tid + 256];
    __shared__ float wr[16];
    float s = v0 + v1;
    #pragma unroll
    for (int o = 16; o; o >>= 1) s += __shfl_xor_sync(0xffffffffu, s, o);
    if (lane == 0) wr[wid] = s;
    __syncthreads();
    float mu = (wr[0] + wr[1] + wr[2] + wr[3] + wr[4] + wr[5] + wr[6] + wr[7]) * (1.0f / DMODEL);
    float d0 = v0 - mu, d1 = v1 - mu;
    float q = d0 * d0 + d1 * d1;
    #pragma unroll
    for (int o = 16; o; o >>= 1) q += __shfl_xor_sync(0xffffffffu, q, o);
    if (lane == 0) wr[8 + wid] = q;
    __syncthreads();
    float var = (wr[8] + wr[9] + wr[10] + wr[11] + wr[12] + wr[13] + wr[14] + wr[15]) * (1.0f / DMODEL);
    float rstd = rsqrtf(var + 1e-5f);
    long long base = (long long)row * DMODEL;
    float y0 = d0 * rstd * g[tid] + b[tid];
    float y1 = d1 * rstd * g[tid + 256] + b[tid + 256];
    of[base + tid]       = __float2half_rn(y0);
    of[base + tid + 256] = __float2half_rn(y1);
}

// ---------------- cross-entropy from fused partials ----------------
__global__ __launch_bounds__(256) void loss_row_k(const float2* __restrict__ part,
                                                  const float* __restrict__ logits,
                                                  const void* __restrict__ tr,
                                                  float* __restrict__ rowloss) {
    __shared__ int mode;
    __shared__ float rm[256], rs[256];
    int row = blockIdx.x, tid = threadIdx.x;
    if (tid == 0) mode = detect_i64(tr, BS);
    __syncthreads();
    const float2* pr = part + (size_t)row * NPART;
    float m = -1e30f, s = 0.0f;
    for (int j = tid; j < NPART; j += 256) {
        float2 p = pr[j];
        float nm = fmaxf(m, p.x);
        s = s * __expf(m - nm) + p.y * __expf(p.x - nm);
        m = nm;
    }
    rm[tid] = m;
    rs[tid] = s;
    __syncthreads();
    #pragma unroll
    for (int st = 128; st > 0; st >>= 1) {
        if (tid < st) {
            float ma = rm[tid], mb = rm[tid + st];
            float nm = fmaxf(ma, mb);
            rs[tid] = rs[tid] * __expf(ma - nm) + rs[tid + st] * __expf(mb - nm);
            rm[tid] = nm;
        }
        __syncthreads();
    }
    if (tid == 0) {
        long long t = load_index(tr, row, mode);
        rowloss[row] = -(logits[(size_t)row * VOCAB + t] - rm[0] - logf(rs[0]));
    }
}

__global__ __launch_bounds__(1024) void loss_reduce_k(const float* __restrict__ rowloss,
                                                      float* __restrict__ out) {
    __shared__ float red[1024];
    int tid = threadIdx.x;
    red[tid] = rowloss[tid] + rowloss[tid + 1024] + rowloss[tid + 2048] + rowloss[tid + 3072];
    __syncthreads();
    #pragma unroll
    for (int s = 512; s > 0; s >>= 1) {
        if (tid < s) red[tid] += red[tid + s];
        __syncthreads();
    }
    if (tid == 0) out[0] = red[0] * (1.0f / BS);
}

// ---------------- host launcher ----------------
extern "C" void kernel_launch(void* const* d_in, const int* in_sizes, int n_in,
                              void* d_out, int out_size) {
    (void)in_sizes; (void)n_in;
    const void*  x       = d_in[0];
    const void*  targets = d_in[1];
    const float* te   = (const float*)d_in[2];
    const float* pe   = (const float*)d_in[3];
    const float* ln1g = (const float*)d_in[4];
    const float* ln1b = (const float*)d_in[5];
    const float* Wq   = (const float*)d_in[6];
    const float* bq   = (const float*)d_in[7];
    const float* Wk   = (const float*)d_in[8];
    const float* bk   = (const float*)d_in[9];
    const float* Wv   = (const float*)d_in[10];
    const float* bv   = (const float*)d_in[11];
    const float* Wo   = (const float*)d_in[12];
    const float* bo   = (const float*)d_in[13];
    const float* ln2g = (const float*)d_in[14];
    const float* ln2b = (const float*)d_in[15];
    const float* W1   = (const float*)d_in[16];
    const float* b1   = (const float*)d_in[17];
    const float* W2   = (const float*)d_in[18];
    const float* b2   = (const float*)d_in[19];
    const float* lnfg = (const float*)d_in[20];
    const float* lnfb = (const float*)d_in[21];
    float* out = (float*)d_out;

    float *p_h, *p_rowloss, *p_logits, *p_bqkv;
    float2* p_part;
    __half *p_xnf, *p_qkvf, *p_ctxf, *p_fff, *p_wqkvf, *p_wof, *p_w1f, *p_w2f, *p_embf;
    cudaGetSymbolAddress((void**)&p_h, g_h);
    cudaGetSymbolAddress((void**)&p_rowloss, g_rowloss);
    cudaGetSymbolAddress((void**)&p_logits, g_logits_scratch);
    cudaGetSymbolAddress((void**)&p_bqkv, g_bqkv);
    cudaGetSymbolAddress((void**)&p_part, g_part);
    cudaGetSymbolAddress((void**)&p_xnf, g_xnf);
    cudaGetSymbolAddress((void**)&p_qkvf, g_qkvf);
    cudaGetSymbolAddress((void**)&p_ctxf, g_ctxf);
    cudaGetSymbolAddress((void**)&p_fff, g_fff);
    cudaGetSymbolAddress((void**)&p_wqkvf, g_wqkvf);
    cudaGetSymbolAddress((void**)&p_wof, g_wof);
    cudaGetSymbolAddress((void**)&p_w1f, g_w1f);
    cudaGetSymbolAddress((void**)&p_w2f, g_w2f);
    cudaGetSymbolAddress((void**)&p_embf, g_embf);

    cudaFuncSetAttribute(gemm_logits, cudaFuncAttributeMaxDynamicSharedMemorySize, GEMM_SMEM_F);
    cudaFuncSetAttribute(gemm_64<1>, cudaFuncAttributeMaxDynamicSharedMemorySize, GEMM_SMEM_64);
    cudaFuncSetAttribute(gemm_64<2>, cudaFuncAttributeMaxDynamicSharedMemorySize, GEMM_SMEM_64);
    cudaFuncSetAttribute(gemm_64<3>, cudaFuncAttributeMaxDynamicSharedMemorySize, GEMM_SMEM_64);
    cudaFuncSetAttribute(fattn_k, cudaFuncAttributeMaxDynamicSharedMemorySize, ATT_SMEM);

    wcvt_qkvo_k<<<dim3(16, 16, NLAYER * 4), dim3(32, 8)>>>(Wq, Wk, Wv, Wo, p_wqkvf, p_wof);
    wcvt_w1_k<<<dim3(64, 16, NLAYER), dim3(32, 8)>>>(W1, p_w1f);
    wcvt_w2_k<<<dim3(16, 64, NLAYER), dim3(32, 8)>>>(W2, p_w2f);
    embed_k<<<BS, 256>>>(x, te, pe, p_h, bq, bk, bv, p_bqkv, p_embf);

    dim3 gDD(BS / 64, DMODEL / 128);    // (64, 4)  = 256 CTAs
    dim3 gQKV(BS / 64, QKVS / 128);     // (64, 12) = 768 CTAs
    dim3 gDF(BS / 64, FFDIM / 128);     // (64, 16) = 1024 CTAs
    dim3 gATT(BATCH * NHEAD, SEQ / 128);

    for (int l = 0; l < NLAYER; l++) {
        __half* wqkv_l = p_wqkvf + (size_t)l * 3 * DDSZ;
        __half* wof_l = p_wof + (size_t)l * DDSZ;
        __half* w1f_l = p_w1f + (size_t)l * DFSZ;
        __half* w2f_l = p_w2f + (size_t)l * DFSZ;

        ln_k<<<BS, 256>>>(p_h, ln1g + l * DMODEL, ln1b + l * DMODEL, p_xnf);
        gemm_64<3><<<gQKV, 256, GEMM_SMEM_64>>>(p_xnf, wqkv_l, p_bqkv + l * QKVS, nullptr,
                                                nullptr, p_qkvf, BS, QKVS, DMODEL);
        fattn_k<<<gATT, 256, ATT_SMEM>>>(p_qkvf, p_ctxf);
        gemm_64<2><<<gDD, 256, GEMM_SMEM_64>>>(p_ctxf, wof_l, bo + l * DMODEL, p_h,
                                               p_h, nullptr, BS, DMODEL, DMODEL);
        ln_k<<<BS, 256>>>(p_h, ln2g + l * DMODEL, ln2b + l * DMODEL, p_xnf);
        gemm_64<1><<<gDF, 256, GEMM_SMEM_64>>>(p_xnf, w1f_l, b1 + l * FFDIM, nullptr,
                                               nullptr, p_fff, BS, FFDIM, DMODEL);
        gemm_64<2><<<gDD, 256, GEMM_SMEM_64>>>(p_fff, w2f_l, b2 + l * DMODEL, p_h,
                                               p_h, nullptr, BS, DMODEL, FFDIM);
    }

    ln_k<<<BS, 256>>>(p_h, lnfg, lnfb, p_xnf);

    float* logits = ((long long)out_size >= NLOG) ? out : p_logits;
    dim3 gLOG(BS / 128, VPAD / 128);
    gemm_logits<<<gLOG, 256, GEMM_SMEM_F>>>(p_xnf, p_embf, logits, p_part, BS, VOCAB, DMODEL);

    loss_row_k<<<BS, 256>>>(p_part, logits, targets, p_rowloss);
    if ((long long)out_size > NLOG) {
        loss_reduce_k<<<1, 1024>>>(p_rowloss, out + NLOG);
    } else if ((long long)out_size < NLOG && out_size >= 1) {
        loss_reduce_k<<<1, 1024>>>(p_rowloss, out + (out_size - 1));
    }
}

// round 12
// speedup vs baseline: 3.0460x; 1.0079x over previous
#include <cuda_runtime.h>
#include <cuda_bf16.h>
#include <cuda_fp16.h>
#include <math.h>
#include <stdint.h>

// ---------------- model constants ----------------
#define BATCH  8
#define SEQ    512
#define DMODEL 512
#define NHEAD  8
#define HEADD  64
#define FFDIM  2048
#define NLAYER 6
#define VOCAB  50257
#define VPAD   50304                  // 393*128
#define NPART  786
#define BS     (BATCH*SEQ)
#define QKVS   1536
static const long long NLOG = (long long)BS * VOCAB;

#define DDSZ   (DMODEL*DMODEL)
#define DFSZ   (DMODEL*FFDIM)

// ---------------- device scratch ----------------
__device__ float g_h[BS * DMODEL];
__device__ float g_rowloss[BS];
__device__ float g_bqkv[NLAYER * QKVS];
__device__ float g_logits_scratch[(size_t)BS * VOCAB];
__device__ float2 g_part[(size_t)BS * NPART];
__device__ __half g_xnf[BS * DMODEL];
__device__ __half g_qkvf[BS * QKVS];
__device__ __half g_ctxf[BS * DMODEL];
__device__ __half g_fff[BS * FFDIM];
__device__ __half g_wqkvf[(size_t)3 * DDSZ * NLAYER];
__device__ __half g_wof[(size_t)DDSZ * NLAYER];
__device__ __half g_w1f[(size_t)DFSZ * NLAYER];
__device__ __half g_w2f[(size_t)DFSZ * NLAYER];
__device__ __half g_embf[(size_t)VPAD * DMODEL];

// ================= PTX helpers =================
__device__ __forceinline__ uint32_t smem_to_u32(const void* smem_ptr) {
    uint32_t addr;
    asm("{ .reg .u64 tmp; cvta.to.shared.u64 tmp, %1; cvt.u32.u64 %0, tmp; }"
        : "=r"(addr) : "l"(smem_ptr));
    return addr;
}
__device__ __forceinline__ void cp16(uint32_t d, const void* s, int sz) {
    asm volatile("cp.async.cg.shared.global [%0], [%1], 16, %2;\n"
                 :: "r"(d), "l"(s), "r"(sz) : "memory");
}
__device__ __forceinline__ void cp_commit() {
    asm volatile("cp.async.commit_group;\n" ::: "memory");
}
__device__ __forceinline__ void cp_wait0() {
    asm volatile("cp.async.wait_group 0;\n" ::: "memory");
}
__device__ __forceinline__ void cp_wait1() {
    asm volatile("cp.async.wait_group 1;\n" ::: "memory");
}
__device__ __forceinline__ void cp_wait2() {
    asm volatile("cp.async.wait_group 2;\n" ::: "memory");
}
#define LDSM4(r, addr) \
    asm volatile("ldmatrix.sync.aligned.m8n8.x4.shared.b16 {%0,%1,%2,%3}, [%4];" \
        : "=r"((r)[0]), "=r"((r)[1]), "=r"((r)[2]), "=r"((r)[3]) : "r"(addr))
#define MMAF16(c, a, b0, b1) \
    asm volatile("mma.sync.aligned.m16n8k16.row.col.f32.f16.f16.f32 " \
        "{%0,%1,%2,%3}, {%4,%5,%6,%7}, {%8,%9}, {%0,%1,%2,%3};" \
        : "+f"((c)[0]), "+f"((c)[1]), "+f"((c)[2]), "+f"((c)[3]) \
        : "r"((a)[0]), "r"((a)[1]), "r"((a)[2]), "r"((a)[3]), "r"(b0), "r"(b1))

#define TB 16384
#define SMEM_OFF 1024

// ================= M128 fp16 GEMM (logits: f32 out + CE partials), 3-stage =================
#define FSTAGE (2*TB)
#define GEMM_SMEM_F (SMEM_OFF + 3*FSTAGE)    // 99328

__device__ __forceinline__ void copy_stage_f(uint32_t st,
        const __half* __restrict__ A, const __half* __restrict__ B,
        int bm, int bn, int k0, int K, int N, int tid) {
    #pragma unroll
    for (int it = 0; it < 4; it++) {
        int idx = tid + it * 256;
        int row = idx >> 3, c = idx & 7;
        uint32_t d = st + row * 128 + ((c ^ (row & 7)) << 4);
        size_t so = (size_t)(bm + row) * K + k0 + c * 8;
        cp16(d, A + so, 16);
    }
    #pragma unroll
    for (int it = 0; it < 4; it++) {
        int idx = tid + it * 256;
        int row = idx >> 3, c = idx & 7;
        int n = bn + row;
        int sz = (n < N) ? 16 : 0;
        uint32_t d = st + TB + row * 128 + ((c ^ (row & 7)) << 4);
        size_t so = (size_t)n * K + k0 + c * 8;
        cp16(d, B + so, sz);
    }
}

__global__ void __launch_bounds__(256, 2)
gemm_logits(const __half* __restrict__ A, const __half* __restrict__ B,
            float* __restrict__ C, float2* __restrict__ part,
            int M, int N, int K) {
    extern __shared__ char smem[];
    const int tid = threadIdx.x;
    const int bm = blockIdx.x * 128;
    const int bn = blockIdx.y * 128;
    const int nc = K >> 6;

    const uint32_t tiles = smem_to_u32(smem) + SMEM_OFF;
    const int lane = tid & 31;
    const int wid = tid >> 5;
    const int wm = (wid & 3) << 5;
    const int wn = (wid >> 2) << 6;
    const int mi = lane >> 3;
    const int lrow = lane & 7;

    float acc[2][8][4];
    #pragma unroll
    for (int i = 0; i < 2; i++)
        #pragma unroll
        for (int j = 0; j < 8; j++)
            #pragma unroll
            for (int t = 0; t < 4; t++) acc[i][j][t] = 0.0f;

    copy_stage_f(tiles, A, B, bm, bn, 0, K, N, tid);
    cp_commit();
    if (nc > 1) {
        copy_stage_f(tiles + FSTAGE, A, B, bm, bn, 64, K, N, tid);
        cp_commit();
    }

    for (int c = 0; c < nc; c++) {
        if (c + 2 < nc) {
            copy_stage_f(tiles + ((c + 2) % 3) * FSTAGE, A, B, bm, bn, (c + 2) << 6, K, N, tid);
            cp_commit();
            cp_wait2();
        } else if (c + 1 < nc) {
            cp_wait1();
        } else {
            cp_wait0();
        }
        __syncthreads();

        const uint32_t st = tiles + (c % 3) * FSTAGE;
        #pragma unroll
        for (int s = 0; s < 4; s++) {
            const int cb = (s << 5) + ((mi >> 1) << 4);
            uint32_t af[2][4], bf[4][4];
            #pragma unroll
            for (int i = 0; i < 2; i++) {
                int r = wm + (i << 4) + ((mi & 1) << 3) + lrow;
                LDSM4(af[i], st + r * 128 + (cb ^ ((r & 7) << 4)));
            }
            #pragma unroll
            for (int j2 = 0; j2 < 4; j2++) {
                int r = wn + (j2 << 4) + ((mi & 1) << 3) + lrow;
                LDSM4(bf[j2], st + TB + r * 128 + (cb ^ ((r & 7) << 4)));
            }
            #pragma unroll
            for (int i = 0; i < 2; i++)
                #pragma unroll
                for (int j2 = 0; j2 < 4; j2++) {
                    MMAF16(acc[i][2 * j2],     af[i], bf[j2][0], bf[j2][2]);
                    MMAF16(acc[i][2 * j2 + 1], af[i], bf[j2][1], bf[j2][3]);
                }
        }
        __syncthreads();
    }

    #pragma unroll
    for (int i = 0; i < 2; i++) {
        #pragma unroll
        for (int hr = 0; hr < 2; hr++) {
            int row = bm + wm + (i << 4) + (lane >> 2) + hr * 8;
            size_t base = (size_t)row * N;
            float pm = -1e30f, ps = 0.0f;
            #pragma unroll
            for (int j = 0; j < 8; j++) {
                #pragma unroll
                for (int u = 0; u < 2; u++) {
                    int cc = bn + wn + (j << 3) + ((lane & 3) << 1) + u;
                    if (cc < N) {
                        float x = acc[i][j][hr * 2 + u];
                        C[base + cc] = x;
                        float nm = fmaxf(pm, x);
                        ps = ps * __expf(pm - nm) + __expf(x - nm);
                        pm = nm;
                    }
                }
            }
            #pragma unroll
            for (int off = 1; off <= 2; off <<= 1) {
                float om = __shfl_xor_sync(0xffffffffu, pm, off);
                float os = __shfl_xor_sync(0xffffffffu, ps, off);
                float nm = fmaxf(pm, om);
                ps = ps * __expf(pm - nm) + os * __expf(om - nm);
                pm = nm;
            }
            if ((lane & 3) == 0)
                part[(size_t)row * NPART + blockIdx.y * 2 + (wid >> 2)] = make_float2(pm, ps);
        }
    }
}

// ================= M64 fp16 GEMM (layer GEMMs), 3-stage =================
// CTA 64x128, 8 warps as 2(m) x 4(n), warp tile 32x32.
// EPI: 1 = bias+gelu -> fp16; 2 = bias+res -> f32; 3 = bias -> fp16
#define STAGE64 (8192 + TB)
#define GEMM_SMEM_64 (SMEM_OFF + 3*STAGE64)   // 74752

__device__ __forceinline__ void copy_stage_64(uint32_t st,
        const __half* __restrict__ A, const __half* __restrict__ B,
        int bm, int bn, int k0, int K, int tid) {
    #pragma unroll
    for (int it = 0; it < 2; it++) {
        int idx = tid + it * 256;
        int row = idx >> 3, c = idx & 7;
        uint32_t d = st + row * 128 + ((c ^ (row & 7)) << 4);
        size_t so = (size_t)(bm + row) * K + k0 + c * 8;
        cp16(d, A + so, 16);
    }
    #pragma unroll
    for (int it = 0; it < 4; it++) {
        int idx = tid + it * 256;
        int row = idx >> 3, c = idx & 7;
        uint32_t d = st + 8192 + row * 128 + ((c ^ (row & 7)) << 4);
        size_t so = (size_t)(bn + row) * K + k0 + c * 8;
        cp16(d, B + so, 16);
    }
}

template <int EPI>
__global__ void __launch_bounds__(256, 2)
gemm_64(const __half* __restrict__ A, const __half* __restrict__ B,
        const float* __restrict__ bias, const float* __restrict__ res,
        float* __restrict__ C, __half* __restrict__ Cf,
        int M, int N, int K) {
    extern __shared__ char smem[];
    const int tid = threadIdx.x;
    const int bm = blockIdx.x * 64;
    const int bn = blockIdx.y * 128;
    const int nc = K >> 6;

    const uint32_t tiles = smem_to_u32(smem) + SMEM_OFF;
    const int lane = tid & 31;
    const int wid = tid >> 5;
    const int wm = (wid & 1) << 5;
    const int wn = (wid >> 1) << 5;
    const int mi = lane >> 3;
    const int lrow = lane & 7;

    float acc[2][4][4];
    #pragma unroll
    for (int i = 0; i < 2; i++)
        #pragma unroll
        for (int j = 0; j < 4; j++)
            #pragma unroll
            for (int t = 0; t < 4; t++) acc[i][j][t] = 0.0f;

    copy_stage_64(tiles, A, B, bm, bn, 0, K, tid);
    cp_commit();
    if (nc > 1) {
        copy_stage_64(tiles + STAGE64, A, B, bm, bn, 64, K, tid);
        cp_commit();
    }

    for (int c = 0; c < nc; c++) {
        if (c + 2 < nc) {
            copy_stage_64(tiles + ((c + 2) % 3) * STAGE64, A, B, bm, bn, (c + 2) << 6, K, tid);
            cp_commit();
            cp_wait2();
        } else if (c + 1 < nc) {
            cp_wait1();
        } else {
            cp_wait0();
        }
        __syncthreads();

        const uint32_t st = tiles + (c % 3) * STAGE64;
        #pragma unroll
        for (int s = 0; s < 4; s++) {
            const int cb = (s << 5) + ((mi >> 1) << 4);
            uint32_t af[2][4], bf[2][4];
            #pragma unroll
            for (int i = 0; i < 2; i++) {
                int r = wm + (i << 4) + ((mi & 1) << 3) + lrow;
                LDSM4(af[i], st + r * 128 + (cb ^ ((r & 7) << 4)));
            }
            #pragma unroll
            for (int j2 = 0; j2 < 2; j2++) {
                int r = wn + (j2 << 4) + ((mi & 1) << 3) + lrow;
                LDSM4(bf[j2], st + 8192 + r * 128 + (cb ^ ((r & 7) << 4)));
            }
            #pragma unroll
            for (int i = 0; i < 2; i++)
                #pragma unroll
                for (int j2 = 0; j2 < 2; j2++) {
                    MMAF16(acc[i][2 * j2],     af[i], bf[j2][0], bf[j2][2]);
                    MMAF16(acc[i][2 * j2 + 1], af[i], bf[j2][1], bf[j2][3]);
                }
        }
        __syncthreads();
    }

    #pragma unroll
    for (int i = 0; i < 2; i++) {
        int row = bm + wm + (i << 4) + (lane >> 2);
        size_t base = (size_t)row * N;
        size_t base8 = base + (size_t)8 * N;
        #pragma unroll
        for (int j = 0; j < 4; j++) {
            int col = bn + wn + (j << 3) + ((lane & 3) << 1);
            float b0 = __ldg(bias + col), b1 = __ldg(bias + col + 1);
            #pragma unroll
            for (int hr = 0; hr < 2; hr++) {
                size_t off = (hr == 0 ? base : base8) + col;
                float x0 = acc[i][j][hr * 2 + 0] + b0;
                float x1 = acc[i][j][hr * 2 + 1] + b1;
                if (EPI == 1) {
                    x0 = 0.5f * x0 * (1.0f + erff(x0 * 0.70710678118654752440f));
                    x1 = 0.5f * x1 * (1.0f + erff(x1 * 0.70710678118654752440f));
                    __half2 hv = __floats2half2_rn(x0, x1);
                    *reinterpret_cast<uint32_t*>(Cf + off) = *reinterpret_cast<uint32_t*>(&hv);
                } else if (EPI == 2) {
                    float2 r2 = *reinterpret_cast<const float2*>(res + off);
                    *reinterpret_cast<float2*>(C + off) = make_float2(x0 + r2.x, x1 + r2.y);
                } else {
                    __half2 hv = __floats2half2_rn(x0, x1);
                    *reinterpret_cast<uint32_t*>(Cf + off) = *reinterpret_cast<uint32_t*>(&hv);
                }
            }
        }
    }
}

// ---------------- flash attention (fp16 single-pass) ----------------
#define ATT_SMEM (3*16384)
__global__ void __launch_bounds__(256, 1)
fattn_k(const __half* __restrict__ qkv, __half* __restrict__ cf) {
    extern __shared__ char smx[];
    const uint32_t sQ = smem_to_u32(smx);
    const uint32_t sK = sQ + 16384;
    const uint32_t sV = sQ + 32768;
    const int tid = threadIdx.x;
    const int lane = tid & 31, wid = tid >> 5;
    const int qt = gridDim.y - 1 - blockIdx.y;
    const int bh = blockIdx.x;
    const int b = bh >> 3, h = bh & 7;
    const int tokQ = b * SEQ + qt * 128;
    const int ho = h * HEADD;
    const int mi = lane >> 3, lrow = lane & 7;
    const int wm = wid * 16;
    const int rB = ((mi & 1) << 3) + lrow;

    #pragma unroll
    for (int it = 0; it < 4; it++) {
        int idx = tid + it * 256;
        int r = idx >> 3, c = idx & 7;
        uint32_t d = sQ + r * 128 + ((c ^ (r & 7)) << 4);
        size_t so = (size_t)(tokQ + r) * QKVS + ho + c * 8;
        cp16(d, qkv + so, 16);
    }
    cp_commit();
    cp_wait0();
    __syncthreads();

    uint32_t aq[4][4];
    {
        int r = wm + rB;
        #pragma unroll
        for (int s = 0; s < 4; s++) {
            uint32_t addr = sQ + r * 128 + ((((s << 5) + ((mi >> 1) << 4))) ^ ((r & 7) << 4));
            LDSM4(aq[s], addr);
        }
    }

    float oacc[8][4];
    #pragma unroll
    for (int f = 0; f < 8; f++)
        #pragma unroll
        for (int t = 0; t < 4; t++) oacc[f][t] = 0.0f;
    float mr0 = -1e30f, mr1 = -1e30f, lr0 = 0.0f, lr1 = 0.0f;
    const int myr0 = wm + (lane >> 2);
    const int myr1 = myr0 + 8;

    for (int jt = 0; jt <= qt; jt++) {
        __syncthreads();
        const int tokJ = b * SEQ + jt * 128;
        #pragma unroll
        for (int it = 0; it < 4; it++) {
            int idx = tid + it * 256;
            int r = idx >> 3, c = idx & 7;
            uint32_t d = sK + r * 128 + ((c ^ (r & 7)) << 4);
            size_t so = (size_t)(tokJ + r) * QKVS + 512 + ho + c * 8;
            cp16(d, qkv + so, 16);
        }
        #pragma unroll
        for (int it = 0; it < 4; it++) {
            int task = tid + it * 256;
            int j = task >> 3, c = task & 7;
            size_t so = (size_t)(tokJ + j) * QKVS + 1024 + ho + c * 8;
            uint4 v4 = *reinterpret_cast<const uint4*>(qkv + so);
            const uint32_t* wv = &v4.x;
            #pragma unroll
            for (int i = 0; i < 8; i++) {
                int dd = c * 8 + i;
                uint32_t off = dd * 256 + ((((uint32_t)(j >> 3) ^ (uint32_t)(dd & 7)) << 4)) + (j & 7) * 2;
                uint16_t hv = (uint16_t)(wv[i >> 1] >> ((i & 1) * 16));
                asm volatile("st.shared.u16 [%0], %1;" :: "r"(sV + off), "h"(hv));
            }
        }
        cp_commit();
        cp_wait0();
        __syncthreads();

        float facc[16][4];
        #pragma unroll
        for (int f = 0; f < 16; f++)
            #pragma unroll
            for (int t = 0; t < 4; t++) facc[f][t] = 0.0f;
        #pragma unroll
        for (int g = 0; g < 8; g++) {
            int r = g * 16 + rB;
            #pragma unroll
            for (int s = 0; s < 4; s++) {
                uint32_t kb[4];
                uint32_t addr = sK + r * 128 + ((((s << 5) + ((mi >> 1) << 4))) ^ ((r & 7) << 4));
                LDSM4(kb, addr);
                MMAF16(facc[2 * g],     aq[s], kb[0], kb[2]);
                MMAF16(facc[2 * g + 1], aq[s], kb[1], kb[3]);
            }
        }
        const float scl = 0.125f;
        #pragma unroll
        for (int f = 0; f < 16; f++) {
            int c0 = f * 8 + 2 * (lane & 3);
            facc[f][0] *= scl; facc[f][1] *= scl;
            facc[f][2] *= scl; facc[f][3] *= scl;
            if (jt == qt) {
                if (c0     > myr0) facc[f][0] = -1e30f;
                if (c0 + 1 > myr0) facc[f][1] = -1e30f;
                if (c0     > myr1) facc[f][2] = -1e30f;
                if (c0 + 1 > myr1) facc[f][3] = -1e30f;
            }
        }
        float m0 = -1e30f, m1 = -1e30f;
        #pragma unroll
        for (int f = 0; f < 16; f++) {
            m0 = fmaxf(m0, fmaxf(facc[f][0], facc[f][1]));
            m1 = fmaxf(m1, fmaxf(facc[f][2], facc[f][3]));
        }
        m0 = fmaxf(m0, __shfl_xor_sync(0xffffffffu, m0, 1));
        m0 = fmaxf(m0, __shfl_xor_sync(0xffffffffu, m0, 2));
        m1 = fmaxf(m1, __shfl_xor_sync(0xffffffffu, m1, 1));
        m1 = fmaxf(m1, __shfl_xor_sync(0xffffffffu, m1, 2));
        float nm0 = fmaxf(mr0, m0), nm1 = fmaxf(mr1, m1);
        float al0 = __expf(mr0 - nm0), al1 = __expf(mr1 - nm1);
        mr0 = nm0; mr1 = nm1;
        #pragma unroll
        for (int f = 0; f < 8; f++) {
            oacc[f][0] *= al0; oacc[f][1] *= al0;
            oacc[f][2] *= al1; oacc[f][3] *= al1;
        }
        float s0 = 0.0f, s1 = 0.0f;
        uint32_t pa[8][4];
        #pragma unroll
        for (int f = 0; f < 16; f++) {
            float p0 = __expf(facc[f][0] - nm0);
            float p1 = __expf(facc[f][1] - nm0);
            float p2 = __expf(facc[f][2] - nm1);
            float p3 = __expf(facc[f][3] - nm1);
            s0 += p0 + p1;
            s1 += p2 + p3;
            __half2 hp = __floats2half2_rn(p0, p1);
            __half2 hq = __floats2half2_rn(p2, p3);
            int ks = f >> 1, half = f & 1;
            pa[ks][2 * half]     = *reinterpret_cast<uint32_t*>(&hp);
            pa[ks][2 * half + 1] = *reinterpret_cast<uint32_t*>(&hq);
        }
        s0 += __shfl_xor_sync(0xffffffffu, s0, 1);
        s0 += __shfl_xor_sync(0xffffffffu, s0, 2);
        s1 += __shfl_xor_sync(0xffffffffu, s1, 1);
        s1 += __shfl_xor_sync(0xffffffffu, s1, 2);
        lr0 = lr0 * al0 + s0;
        lr1 = lr1 * al1 + s1;
        #pragma unroll
        for (int ks = 0; ks < 8; ks++) {
            #pragma unroll
            for (int g2 = 0; g2 < 4; g2++) {
                uint32_t vb[4];
                int r = g2 * 16 + rB;
                uint32_t addr = sV + r * 256 + ((((ks << 5) + ((mi >> 1) << 4))) ^ ((r & 7) << 4));
                LDSM4(vb, addr);
                MMAF16(oacc[2 * g2],     pa[ks], vb[0], vb[2]);
                MMAF16(oacc[2 * g2 + 1], pa[ks], vb[1], vb[3]);
            }
        }
    }

    float inv0 = 1.0f / lr0, inv1 = 1.0f / lr1;
    size_t t0 = (size_t)(tokQ + myr0) * DMODEL + ho;
    size_t t1 = t0 + (size_t)8 * DMODEL;
    #pragma unroll
    for (int f = 0; f < 8; f++) {
        int dc = f * 8 + 2 * (lane & 3);
        __half2 a = __floats2half2_rn(oacc[f][0] * inv0, oacc[f][1] * inv0);
        __half2 b2 = __floats2half2_rn(oacc[f][2] * inv1, oacc[f][3] * inv1);
        *reinterpret_cast<uint32_t*>(cf + t0 + dc) = *reinterpret_cast<uint32_t*>(&a);
        *reinterpret_cast<uint32_t*>(cf + t1 + dc) = *reinterpret_cast<uint32_t*>(&b2);
    }
}

// ---------------- weight transpose (f32 [K,N] -> fp16 [N,K]) ----------------
__device__ __forceinline__ void transpose_f16(const float* __restrict__ in,
        __half* __restrict__ out, int K, int N) {
    __shared__ float t[32][33];
    int n0 = blockIdx.x << 5, k0 = blockIdx.y << 5;
    int tx = threadIdx.x, ty = threadIdx.y;
    #pragma unroll
    for (int r = 0; r < 4; r++)
        t[ty + 8 * r][tx] = in[(size_t)(k0 + ty + 8 * r) * N + n0 + tx];
    __syncthreads();
    #pragma unroll
    for (int r = 0; r < 4; r++)
        out[(size_t)(n0 + ty + 8 * r) * K + k0 + tx] = __float2half_rn(t[tx][ty + 8 * r]);
}
__global__ void wcvt_qkvo_k(const float* __restrict__ Wq, const float* __restrict__ Wk,
                            const float* __restrict__ Wv, const float* __restrict__ Wo,
                            __half* __restrict__ oqkv, __half* __restrict__ oo) {
    int z = blockIdx.z, l = z >> 2, m = z & 3;
    const float* W = (m == 0 ? Wq : m == 1 ? Wk : m == 2 ? Wv : Wo) + (size_t)l * DDSZ;
    __half* dst = (m < 3) ? (oqkv + ((size_t)l * 3 + m) * DDSZ) : (oo + (size_t)l * DDSZ);
    transpose_f16(W, dst, DMODEL, DMODEL);
}
__global__ void wcvt_w1_k(const float* __restrict__ W1, __half* __restrict__ out) {
    int l = blockIdx.z;
    transpose_f16(W1 + (size_t)l * DFSZ, out + (size_t)l * DFSZ, DMODEL, FFDIM);
}
__global__ void wcvt_w2_k(const float* __restrict__ W2, __half* __restrict__ out) {
    int l = blockIdx.z;
    transpose_f16(W2 + (size_t)l * DFSZ, out + (size_t)l * DFSZ, FFDIM, DMODEL);
}

// ---------------- helpers ----------------
__device__ __forceinline__ int detect_i64(const void* p, int n) {
    const long long* x = (const long long*)p;
    int c = n < 32 ? n : 32;
    for (int i = 0; i < c; i++) {
        long long v = x[i];
        if (v < 0 || v >= VOCAB) return 0;
    }
    return 1;
}
__device__ __forceinline__ long long load_index(const void* p, int i, int is64) {
    return is64 ? ((const long long*)p)[i] : (long long)((const int*)p)[i];
}

// ---------------- embedding (+ qkv bias concat + emb fp16 cvt) ----------------
__global__ __launch_bounds__(256) void embed_k(const void* __restrict__ xr,
                                               const float* __restrict__ te,
                                               const float* __restrict__ pe,
                                               float* __restrict__ h,
                                               const float* __restrict__ bq,
                                               const float* __restrict__ bk,
                                               const float* __restrict__ bv,
                                               float* __restrict__ bqkv,
                                               __half* __restrict__ embf) {
    __shared__ int mode;
    if (threadIdx.x == 0) mode = detect_i64(xr, BS);
    __syncthreads();
    int pos = blockIdx.x;
    int tid = threadIdx.x;
    if (pos < NLAYER) {
        #pragma unroll
        for (int t = tid; t < DMODEL; t += 256) {
            bqkv[pos * QKVS + t]        = bq[pos * DMODEL + t];
            bqkv[pos * QKVS + 512 + t]  = bk[pos * DMODEL + t];
            bqkv[pos * QKVS + 1024 + t] = bv[pos * DMODEL + t];
        }
    }
    long long idx = load_index(xr, pos, mode);
    int s = pos & (SEQ - 1);
    const float* t = te + idx * DMODEL;
    const float* p = pe + (long long)s * DMODEL;
    float* o = h + (long long)pos * DMODEL;
    o[tid]       = t[tid]       + p[tid];
    o[tid + 256] = t[tid + 256] + p[tid + 256];
    size_t n4 = (size_t)VOCAB * DMODEL / 4;
    for (size_t i = (size_t)pos * 256 + tid; i < n4; i += (size_t)BS * 256) {
        float4 v = reinterpret_cast<const float4*>(te)[i];
        __half2 a = __floats2half2_rn(v.x, v.y);
        __half2 b = __floats2half2_rn(v.z, v.w);
        uint2 w;
        w.x = *reinterpret_cast<uint32_t*>(&a);
        w.y = *reinterpret_cast<uint32_t*>(&b);
        reinterpret_cast<uint2*>(embf)[i] = w;
    }
}

// ---------------- layernorm -> fp16 ----------------
__global__ __launch_bounds__(256) void ln_k(const float* __restrict__ in,
                                            const float* __restrict__ g,
                                            const float* __restrict__ b,
                                            __half* __restrict__ of) {
    int row = blockIdx.x;
    int tid = threadIdx.x;
    int lane = tid & 31, wid = tid >> 5;
    const float* x = in + (long long)row * DMODEL;
    float v0 = x[tid], v1 = x[tid + 256];
    __shared__ float wr[16];
    float s = v0 + v1;
    #pragma unroll
    for (int o = 16; o; o >>= 1) s += __shfl_xor_sync(0xffffffffu, s, o);
    if (lane == 0) wr[wid] = s;
    __syncthreads();
    float mu = (wr[0] + wr[1] + wr[2] + wr[3] + wr[4] + wr[5] + wr[6] + wr[7]) * (1.0f / DMODEL);
    float d0 = v0 - mu, d1 = v1 - mu;
    float q = d0 * d0 + d1 * d1;
    #pragma unroll
    for (int o = 16; o; o >>= 1) q += __shfl_xor_sync(0xffffffffu, q, o);
    if (lane == 0) wr[8 + wid] = q;
    __syncthreads();
    float var = (wr[8] + wr[9] + wr[10] + wr[11] + wr[12] + wr[13] + wr[14] + wr[15]) * (1.0f / DMODEL);
    float rstd = rsqrtf(var + 1e-5f);
    long long base = (long long)row * DMODEL;
    float y0 = d0 * rstd * g[tid] + b[tid];
    float y1 = d1 * rstd * g[tid + 256] + b[tid + 256];
    of[base + tid]       = __float2half_rn(y0);
    of[base + tid + 256] = __float2half_rn(y1);
}

// ---------------- cross-entropy from fused partials ----------------
__global__ __launch_bounds__(256) void loss_row_k(const float2* __restrict__ part,
                                                  const float* __restrict__ logits,
                                                  const void* __restrict__ tr,
                                                  float* __restrict__ rowloss) {
    __shared__ int mode;
    __shared__ float rm[256], rs[256];
    int row = blockIdx.x, tid = threadIdx.x;
    if (tid == 0) mode = detect_i64(tr, BS);
    __syncthreads();
    const float2* pr = part + (size_t)row * NPART;
    float m = -1e30f, s = 0.0f;
    for (int j = tid; j < NPART; j += 256) {
        float2 p = pr[j];
        float nm = fmaxf(m, p.x);
        s = s * __expf(m - nm) + p.y * __expf(p.x - nm);
        m = nm;
    }
    rm[tid] = m;
    rs[tid] = s;
    __syncthreads();
    #pragma unroll
    for (int st = 128; st > 0; st >>= 1) {
        if (tid < st) {
            float ma = rm[tid], mb = rm[tid + st];
            float nm = fmaxf(ma, mb);
            rs[tid] = rs[tid] * __expf(ma - nm) + rs[tid + st] * __expf(mb - nm);
            rm[tid] = nm;
        }
        __syncthreads();
    }
    if (tid == 0) {
        long long t = load_index(tr, row, mode);
        rowloss[row] = -(logits[(size_t)row * VOCAB + t] - rm[0] - logf(rs[0]));
    }
}

__global__ __launch_bounds__(1024) void loss_reduce_k(const float* __restrict__ rowloss,
                                                      float* __restrict__ out) {
    __shared__ float red[1024];
    int tid = threadIdx.x;
    red[tid] = rowloss[tid] + rowloss[tid + 1024] + rowloss[tid + 2048] + rowloss[tid + 3072];
    __syncthreads();
    #pragma unroll
    for (int s = 512; s > 0; s >>= 1) {
        if (tid < s) red[tid] += red[tid + s];
        __syncthreads();
    }
    if (tid == 0) out[0] = red[0] * (1.0f / BS);
}

// ---------------- host launcher ----------------
extern "C" void kernel_launch(void* const* d_in, const int* in_sizes, int n_in,
                              void* d_out, int out_size) {
    (void)in_sizes; (void)n_in;
    const void*  x       = d_in[0];
    const void*  targets = d_in[1];
    const float* te   = (const float*)d_in[2];
    const float* pe   = (const float*)d_in[3];
    const float* ln1g = (const float*)d_in[4];
    const float* ln1b = (const float*)d_in[5];
    const float* Wq   = (const float*)d_in[6];
    const float* bq   = (const float*)d_in[7];
    const float* Wk   = (const float*)d_in[8];
    const float* bk   = (const float*)d_in[9];
    const float* Wv   = (const float*)d_in[10];
    const float* bv   = (const float*)d_in[11];
    const float* Wo   = (const float*)d_in[12];
    const float* bo   = (const float*)d_in[13];
    const float* ln2g = (const float*)d_in[14];
    const float* ln2b = (const float*)d_in[15];
    const float* W1   = (const float*)d_in[16];
    const float* b1   = (const float*)d_in[17];
    const float* W2   = (const float*)d_in[18];
    const float* b2   = (const float*)d_in[19];
    const float* lnfg = (const float*)d_in[20];
    const float* lnfb = (const float*)d_in[21];
    float* out = (float*)d_out;

    float *p_h, *p_rowloss, *p_logits, *p_bqkv;
    float2* p_part;
    __half *p_xnf, *p_qkvf, *p_ctxf, *p_fff, *p_wqkvf, *p_wof, *p_w1f, *p_w2f, *p_embf;
    cudaGetSymbolAddress((void**)&p_h, g_h);
    cudaGetSymbolAddress((void**)&p_rowloss, g_rowloss);
    cudaGetSymbolAddress((void**)&p_logits, g_logits_scratch);
    cudaGetSymbolAddress((void**)&p_bqkv, g_bqkv);
    cudaGetSymbolAddress((void**)&p_part, g_part);
    cudaGetSymbolAddress((void**)&p_xnf, g_xnf);
    cudaGetSymbolAddress((void**)&p_qkvf, g_qkvf);
    cudaGetSymbolAddress((void**)&p_ctxf, g_ctxf);
    cudaGetSymbolAddress((void**)&p_fff, g_fff);
    cudaGetSymbolAddress((void**)&p_wqkvf, g_wqkvf);
    cudaGetSymbolAddress((void**)&p_wof, g_wof);
    cudaGetSymbolAddress((void**)&p_w1f, g_w1f);
    cudaGetSymbolAddress((void**)&p_w2f, g_w2f);
    cudaGetSymbolAddress((void**)&p_embf, g_embf);

    cudaFuncSetAttribute(gemm_logits, cudaFuncAttributeMaxDynamicSharedMemorySize, GEMM_SMEM_F);
    cudaFuncSetAttribute(gemm_64<1>, cudaFuncAttributeMaxDynamicSharedMemorySize, GEMM_SMEM_64);
    cudaFuncSetAttribute(gemm_64<2>, cudaFuncAttributeMaxDynamicSharedMemorySize, GEMM_SMEM_64);
    cudaFuncSetAttribute(gemm_64<3>, cudaFuncAttributeMaxDynamicSharedMemorySize, GEMM_SMEM_64);
    cudaFuncSetAttribute(fattn_k, cudaFuncAttributeMaxDynamicSharedMemorySize, ATT_SMEM);

    wcvt_qkvo_k<<<dim3(16, 16, NLAYER * 4), dim3(32, 8)>>>(Wq, Wk, Wv, Wo, p_wqkvf, p_wof);
    wcvt_w1_k<<<dim3(64, 16, NLAYER), dim3(32, 8)>>>(W1, p_w1f);
    wcvt_w2_k<<<dim3(16, 64, NLAYER), dim3(32, 8)>>>(W2, p_w2f);
    embed_k<<<BS, 256>>>(x, te, pe, p_h, bq, bk, bv, p_bqkv, p_embf);

    dim3 gDD(BS / 64, DMODEL / 128);
    dim3 gQKV(BS / 64, QKVS / 128);
    dim3 gDF(BS / 64, FFDIM / 128);
    dim3 gATT(BATCH * NHEAD, SEQ / 128);

    for (int l = 0; l < NLAYER; l++) {
        __half* wqkv_l = p_wqkvf + (size_t)l * 3 * DDSZ;
        __half* wof_l = p_wof + (size_t)l * DDSZ;
        __half* w1f_l = p_w1f + (size_t)l * DFSZ;
        __half* w2f_l = p_w2f + (size_t)l * DFSZ;

        ln_k<<<BS, 256>>>(p_h, ln1g + l * DMODEL, ln1b + l * DMODEL, p_xnf);
        gemm_64<3><<<gQKV, 256, GEMM_SMEM_64>>>(p_xnf, wqkv_l, p_bqkv + l * QKVS, nullptr,
                                                nullptr, p_qkvf, BS, QKVS, DMODEL);
        fattn_k<<<gATT, 256, ATT_SMEM>>>(p_qkvf, p_ctxf);
        gemm_64<2><<<gDD, 256, GEMM_SMEM_64>>>(p_ctxf, wof_l, bo + l * DMODEL, p_h,
                                               p_h, nullptr, BS, DMODEL, DMODEL);
        ln_k<<<BS, 256>>>(p_h, ln2g + l * DMODEL, ln2b + l * DMODEL, p_xnf);
        gemm_64<1><<<gDF, 256, GEMM_SMEM_64>>>(p_xnf, w1f_l, b1 + l * FFDIM, nullptr,
                                               nullptr, p_fff, BS, FFDIM, DMODEL);
        gemm_64<2><<<gDD, 256, GEMM_SMEM_64>>>(p_fff, w2f_l, b2 + l * DMODEL, p_h,
                                               p_h, nullptr, BS, DMODEL, FFDIM);
    }

    ln_k<<<BS, 256>>>(p_h, lnfg, lnfb, p_xnf);

    float* logits = ((long long)out_size >= NLOG) ? out : p_logits;
    dim3 gLOG(BS / 128, VPAD / 128);
    gemm_logits<<<gLOG, 256, GEMM_SMEM_F>>>(p_xnf, p_embf, logits, p_part, BS, VOCAB, DMODEL);

    loss_row_k<<<BS, 256>>>(p_part, logits, targets, p_rowloss);
    if ((long long)out_size > NLOG) {
        loss_reduce_k<<<1, 1024>>>(p_rowloss, out + NLOG);
    } else if ((long long)out_size < NLOG && out_size >= 1) {
        loss_reduce_k<<<1, 1024>>>(p_rowloss, out + (out_size - 1));
    }
}

// round 13
// speedup vs baseline: 3.1268x; 1.0265x over previous
#include <cuda_runtime.h>
#include <cuda_bf16.h>
#include <cuda_fp16.h>
#include <math.h>
#include <stdint.h>

// ---------------- model constants ----------------
#define BATCH  8
#define SEQ    512
#define DMODEL 512
#define NHEAD  8
#define HEADD  64
#define FFDIM  2048
#define NLAYER 6
#define VOCAB  50257
#define VPAD   50304                  // 393*128
#define NPART  786
#define BS     (BATCH*SEQ)
#define QKVS   1536
static const long long NLOG = (long long)BS * VOCAB;

#define DDSZ   (DMODEL*DMODEL)
#define DFSZ   (DMODEL*FFDIM)

// ---------------- device scratch ----------------
__device__ float g_h[BS * DMODEL];
__device__ float g_rowloss[BS];
__device__ float g_bqkv[NLAYER * QKVS];
__device__ float g_logits_scratch[(size_t)BS * VOCAB];
__device__ float2 g_part[(size_t)BS * NPART];
__device__ __half g_xnf[BS * DMODEL];
__device__ __half g_qkvf[BS * QKVS];
__device__ __half g_ctxf[BS * DMODEL];
__device__ __half g_fff[BS * FFDIM];
__device__ __half g_wqkvf[(size_t)3 * DDSZ * NLAYER];
__device__ __half g_wof[(size_t)DDSZ * NLAYER];
__device__ __half g_w1f[(size_t)DFSZ * NLAYER];
__device__ __half g_w2f[(size_t)DFSZ * NLAYER];
__device__ __half g_embf[(size_t)VPAD * DMODEL];

// ================= PTX helpers =================
__device__ __forceinline__ uint32_t smem_to_u32(const void* smem_ptr) {
    uint32_t addr;
    asm("{ .reg .u64 tmp; cvta.to.shared.u64 tmp, %1; cvt.u32.u64 %0, tmp; }"
        : "=r"(addr) : "l"(smem_ptr));
    return addr;
}
__device__ __forceinline__ void cp16(uint32_t d, const void* s, int sz) {
    asm volatile("cp.async.cg.shared.global [%0], [%1], 16, %2;\n"
                 :: "r"(d), "l"(s), "r"(sz) : "memory");
}
__device__ __forceinline__ void cp_commit() {
    asm volatile("cp.async.commit_group;\n" ::: "memory");
}
__device__ __forceinline__ void cp_wait0() {
    asm volatile("cp.async.wait_group 0;\n" ::: "memory");
}
__device__ __forceinline__ void cp_wait1() {
    asm volatile("cp.async.wait_group 1;\n" ::: "memory");
}
__device__ __forceinline__ void cp_wait2() {
    asm volatile("cp.async.wait_group 2;\n" ::: "memory");
}
#define LDSM4(r, addr) \
    asm volatile("ldmatrix.sync.aligned.m8n8.x4.shared.b16 {%0,%1,%2,%3}, [%4];" \
        : "=r"((r)[0]), "=r"((r)[1]), "=r"((r)[2]), "=r"((r)[3]) : "r"(addr))
#define MMAF16(c, a, b0, b1) \
    asm volatile("mma.sync.aligned.m16n8k16.row.col.f32.f16.f16.f32 " \
        "{%0,%1,%2,%3}, {%4,%5,%6,%7}, {%8,%9}, {%0,%1,%2,%3};" \
        : "+f"((c)[0]), "+f"((c)[1]), "+f"((c)[2]), "+f"((c)[3]) \
        : "r"((a)[0]), "r"((a)[1]), "r"((a)[2]), "r"((a)[3]), "r"(b0), "r"(b1))

#define TB 16384
#define SMEM_OFF 1024

// ================= M128 fp16 GEMM (logits: f32 out + CE partials), 3-stage =================
#define FSTAGE (2*TB)
#define GEMM_SMEM_F (SMEM_OFF + 3*FSTAGE)    // 99328

__device__ __forceinline__ void copy_stage_f(uint32_t st,
        const __half* __restrict__ A, const __half* __restrict__ B,
        int bm, int bn, int k0, int K, int N, int tid) {
    #pragma unroll
    for (int it = 0; it < 4; it++) {
        int idx = tid + it * 256;
        int row = idx >> 3, c = idx & 7;
        uint32_t d = st + row * 128 + ((c ^ (row & 7)) << 4);
        size_t so = (size_t)(bm + row) * K + k0 + c * 8;
        cp16(d, A + so, 16);
    }
    #pragma unroll
    for (int it = 0; it < 4; it++) {
        int idx = tid + it * 256;
        int row = idx >> 3, c = idx & 7;
        int n = bn + row;
        int sz = (n < N) ? 16 : 0;
        uint32_t d = st + TB + row * 128 + ((c ^ (row & 7)) << 4);
        size_t so = (size_t)n * K + k0 + c * 8;
        cp16(d, B + so, sz);
    }
}

__global__ void __launch_bounds__(256, 2)
gemm_logits(const __half* __restrict__ A, const __half* __restrict__ B,
            float* __restrict__ C, float2* __restrict__ part,
            int M, int N, int K) {
    extern __shared__ char smem[];
    const int tid = threadIdx.x;
    const int bm = blockIdx.x * 128;
    const int bn = blockIdx.y * 128;
    const int nc = K >> 6;

    const uint32_t tiles = smem_to_u32(smem) + SMEM_OFF;
    const int lane = tid & 31;
    const int wid = tid >> 5;
    const int wm = (wid & 3) << 5;
    const int wn = (wid >> 2) << 6;
    const int mi = lane >> 3;
    const int lrow = lane & 7;

    float acc[2][8][4];
    #pragma unroll
    for (int i = 0; i < 2; i++)
        #pragma unroll
        for (int j = 0; j < 8; j++)
            #pragma unroll
            for (int t = 0; t < 4; t++) acc[i][j][t] = 0.0f;

    copy_stage_f(tiles, A, B, bm, bn, 0, K, N, tid);
    cp_commit();
    if (nc > 1) {
        copy_stage_f(tiles + FSTAGE, A, B, bm, bn, 64, K, N, tid);
        cp_commit();
    }

    for (int c = 0; c < nc; c++) {
        if (c + 2 < nc) {
            copy_stage_f(tiles + ((c + 2) % 3) * FSTAGE, A, B, bm, bn, (c + 2) << 6, K, N, tid);
            cp_commit();
            cp_wait2();
        } else if (c + 1 < nc) {
            cp_wait1();
        } else {
            cp_wait0();
        }
        __syncthreads();

        const uint32_t st = tiles + (c % 3) * FSTAGE;
        #pragma unroll
        for (int s = 0; s < 4; s++) {
            const int cb = (s << 5) + ((mi >> 1) << 4);
            uint32_t af[2][4], bf[4][4];
            #pragma unroll
            for (int i = 0; i < 2; i++) {
                int r = wm + (i << 4) + ((mi & 1) << 3) + lrow;
                LDSM4(af[i], st + r * 128 + (cb ^ ((r & 7) << 4)));
            }
            #pragma unroll
            for (int j2 = 0; j2 < 4; j2++) {
                int r = wn + (j2 << 4) + ((mi & 1) << 3) + lrow;
                LDSM4(bf[j2], st + TB + r * 128 + (cb ^ ((r & 7) << 4)));
            }
            #pragma unroll
            for (int i = 0; i < 2; i++)
                #pragma unroll
                for (int j2 = 0; j2 < 4; j2++) {
                    MMAF16(acc[i][2 * j2],     af[i], bf[j2][0], bf[j2][2]);
                    MMAF16(acc[i][2 * j2 + 1], af[i], bf[j2][1], bf[j2][3]);
                }
        }
        __syncthreads();
    }

    #pragma unroll
    for (int i = 0; i < 2; i++) {
        #pragma unroll
        for (int hr = 0; hr < 2; hr++) {
            int row = bm + wm + (i << 4) + (lane >> 2) + hr * 8;
            size_t base = (size_t)row * N;
            float pm = -1e30f, ps = 0.0f;
            #pragma unroll
            for (int j = 0; j < 8; j++) {
                #pragma unroll
                for (int u = 0; u < 2; u++) {
                    int cc = bn + wn + (j << 3) + ((lane & 3) << 1) + u;
                    if (cc < N) {
                        float x = acc[i][j][hr * 2 + u];
                        C[base + cc] = x;
                        float nm = fmaxf(pm, x);
                        ps = ps * __expf(pm - nm) + __expf(x - nm);
                        pm = nm;
                    }
                }
            }
            #pragma unroll
            for (int off = 1; off <= 2; off <<= 1) {
                float om = __shfl_xor_sync(0xffffffffu, pm, off);
                float os = __shfl_xor_sync(0xffffffffu, ps, off);
                float nm = fmaxf(pm, om);
                ps = ps * __expf(pm - nm) + os * __expf(om - nm);
                pm = nm;
            }
            if ((lane & 3) == 0)
                part[(size_t)row * NPART + blockIdx.y * 2 + (wid >> 2)] = make_float2(pm, ps);
        }
    }
}

// ================= M64 fp16 GEMM (layer GEMMs), 3-stage, occ 3 =================
#define STAGE64 (8192 + TB)
#define GEMM_SMEM_64 (SMEM_OFF + 3*STAGE64)   // 74752

__device__ __forceinline__ void copy_stage_64(uint32_t st,
        const __half* __restrict__ A, const __half* __restrict__ B,
        int bm, int bn, int k0, int K, int tid) {
    #pragma unroll
    for (int it = 0; it < 2; it++) {
        int idx = tid + it * 256;
        int row = idx >> 3, c = idx & 7;
        uint32_t d = st + row * 128 + ((c ^ (row & 7)) << 4);
        size_t so = (size_t)(bm + row) * K + k0 + c * 8;
        cp16(d, A + so, 16);
    }
    #pragma unroll
    for (int it = 0; it < 4; it++) {
        int idx = tid + it * 256;
        int row = idx >> 3, c = idx & 7;
        uint32_t d = st + 8192 + row * 128 + ((c ^ (row & 7)) << 4);
        size_t so = (size_t)(bn + row) * K + k0 + c * 8;
        cp16(d, B + so, 16);
    }
}

template <int EPI>
__global__ void __launch_bounds__(256, 3)
gemm_64(const __half* __restrict__ A, const __half* __restrict__ B,
        const float* __restrict__ bias, const float* __restrict__ res,
        float* __restrict__ C, __half* __restrict__ Cf,
        int M, int N, int K) {
    extern __shared__ char smem[];
    const int tid = threadIdx.x;
    const int bm = blockIdx.x * 64;
    const int bn = blockIdx.y * 128;
    const int nc = K >> 6;

    const uint32_t tiles = smem_to_u32(smem) + SMEM_OFF;
    const int lane = tid & 31;
    const int wid = tid >> 5;
    const int wm = (wid & 1) << 5;
    const int wn = (wid >> 1) << 5;
    const int mi = lane >> 3;
    const int lrow = lane & 7;

    float acc[2][4][4];
    #pragma unroll
    for (int i = 0; i < 2; i++)
        #pragma unroll
        for (int j = 0; j < 4; j++)
            #pragma unroll
            for (int t = 0; t < 4; t++) acc[i][j][t] = 0.0f;

    copy_stage_64(tiles, A, B, bm, bn, 0, K, tid);
    cp_commit();
    if (nc > 1) {
        copy_stage_64(tiles + STAGE64, A, B, bm, bn, 64, K, tid);
        cp_commit();
    }

    for (int c = 0; c < nc; c++) {
        if (c + 2 < nc) {
            copy_stage_64(tiles + ((c + 2) % 3) * STAGE64, A, B, bm, bn, (c + 2) << 6, K, tid);
            cp_commit();
            cp_wait2();
        } else if (c + 1 < nc) {
            cp_wait1();
        } else {
            cp_wait0();
        }
        __syncthreads();

        const uint32_t st = tiles + (c % 3) * STAGE64;
        #pragma unroll
        for (int s = 0; s < 4; s++) {
            const int cb = (s << 5) + ((mi >> 1) << 4);
            uint32_t af[2][4], bf[2][4];
            #pragma unroll
            for (int i = 0; i < 2; i++) {
                int r = wm + (i << 4) + ((mi & 1) << 3) + lrow;
                LDSM4(af[i], st + r * 128 + (cb ^ ((r & 7) << 4)));
            }
            #pragma unroll
            for (int j2 = 0; j2 < 2; j2++) {
                int r = wn + (j2 << 4) + ((mi & 1) << 3) + lrow;
                LDSM4(bf[j2], st + 8192 + r * 128 + (cb ^ ((r & 7) << 4)));
            }
            #pragma unroll
            for (int i = 0; i < 2; i++)
                #pragma unroll
                for (int j2 = 0; j2 < 2; j2++) {
                    MMAF16(acc[i][2 * j2],     af[i], bf[j2][0], bf[j2][2]);
                    MMAF16(acc[i][2 * j2 + 1], af[i], bf[j2][1], bf[j2][3]);
                }
        }
        __syncthreads();
    }

    #pragma unroll
    for (int i = 0; i < 2; i++) {
        int row = bm + wm + (i << 4) + (lane >> 2);
        size_t base = (size_t)row * N;
        size_t base8 = base + (size_t)8 * N;
        #pragma unroll
        for (int j = 0; j < 4; j++) {
            int col = bn + wn + (j << 3) + ((lane & 3) << 1);
            float b0 = __ldg(bias + col), b1 = __ldg(bias + col + 1);
            #pragma unroll
            for (int hr = 0; hr < 2; hr++) {
                size_t off = (hr == 0 ? base : base8) + col;
                float x0 = acc[i][j][hr * 2 + 0] + b0;
                float x1 = acc[i][j][hr * 2 + 1] + b1;
                if (EPI == 1) {
                    x0 = 0.5f * x0 * (1.0f + erff(x0 * 0.70710678118654752440f));
                    x1 = 0.5f * x1 * (1.0f + erff(x1 * 0.70710678118654752440f));
                    __half2 hv = __floats2half2_rn(x0, x1);
                    *reinterpret_cast<uint32_t*>(Cf + off) = *reinterpret_cast<uint32_t*>(&hv);
                } else if (EPI == 2) {
                    float2 r2 = *reinterpret_cast<const float2*>(res + off);
                    *reinterpret_cast<float2*>(C + off) = make_float2(x0 + r2.x, x1 + r2.y);
                } else {
                    __half2 hv = __floats2half2_rn(x0, x1);
                    *reinterpret_cast<uint32_t*>(Cf + off) = *reinterpret_cast<uint32_t*>(&hv);
                }
            }
        }
    }
}

// ---------------- flash attention (fp16 single-pass) ----------------
#define ATT_SMEM (3*16384)
__global__ void __launch_bounds__(256, 1)
fattn_k(const __half* __restrict__ qkv, __half* __restrict__ cf) {
    extern __shared__ char smx[];
    const uint32_t sQ = smem_to_u32(smx);
    const uint32_t sK = sQ + 16384;
    const uint32_t sV = sQ + 32768;
    const int tid = threadIdx.x;
    const int lane = tid & 31, wid = tid >> 5;
    const int qt = gridDim.y - 1 - blockIdx.y;
    const int bh = blockIdx.x;
    const int b = bh >> 3, h = bh & 7;
    const int tokQ = b * SEQ + qt * 128;
    const int ho = h * HEADD;
    const int mi = lane >> 3, lrow = lane & 7;
    const int wm = wid * 16;
    const int rB = ((mi & 1) << 3) + lrow;

    #pragma unroll
    for (int it = 0; it < 4; it++) {
        int idx = tid + it * 256;
        int r = idx >> 3, c = idx & 7;
        uint32_t d = sQ + r * 128 + ((c ^ (r & 7)) << 4);
        size_t so = (size_t)(tokQ + r) * QKVS + ho + c * 8;
        cp16(d, qkv + so, 16);
    }
    cp_commit();
    cp_wait0();
    __syncthreads();

    uint32_t aq[4][4];
    {
        int r = wm + rB;
        #pragma unroll
        for (int s = 0; s < 4; s++) {
            uint32_t addr = sQ + r * 128 + ((((s << 5) + ((mi >> 1) << 4))) ^ ((r & 7) << 4));
            LDSM4(aq[s], addr);
        }
    }

    float oacc[8][4];
    #pragma unroll
    for (int f = 0; f < 8; f++)
        #pragma unroll
        for (int t = 0; t < 4; t++) oacc[f][t] = 0.0f;
    float mr0 = -1e30f, mr1 = -1e30f, lr0 = 0.0f, lr1 = 0.0f;
    const int myr0 = wm + (lane >> 2);
    const int myr1 = myr0 + 8;

    for (int jt = 0; jt <= qt; jt++) {
        __syncthreads();
        const int tokJ = b * SEQ + jt * 128;
        #pragma unroll
        for (int it = 0; it < 4; it++) {
            int idx = tid + it * 256;
            int r = idx >> 3, c = idx & 7;
            uint32_t d = sK + r * 128 + ((c ^ (r & 7)) << 4);
            size_t so = (size_t)(tokJ + r) * QKVS + 512 + ho + c * 8;
            cp16(d, qkv + so, 16);
        }
        #pragma unroll
        for (int it = 0; it < 4; it++) {
            int task = tid + it * 256;
            int j = task >> 3, c = task & 7;
            size_t so = (size_t)(tokJ + j) * QKVS + 1024 + ho + c * 8;
            uint4 v4 = *reinterpret_cast<const uint4*>(qkv + so);
            const uint32_t* wv = &v4.x;
            #pragma unroll
            for (int i = 0; i < 8; i++) {
                int dd = c * 8 + i;
                uint32_t off = dd * 256 + ((((uint32_t)(j >> 3) ^ (uint32_t)(dd & 7)) << 4)) + (j & 7) * 2;
                uint16_t hv = (uint16_t)(wv[i >> 1] >> ((i & 1) * 16));
                asm volatile("st.shared.u16 [%0], %1;" :: "r"(sV + off), "h"(hv));
            }
        }
        cp_commit();
        cp_wait0();
        __syncthreads();

        float facc[16][4];
        #pragma unroll
        for (int f = 0; f < 16; f++)
            #pragma unroll
            for (int t = 0; t < 4; t++) facc[f][t] = 0.0f;
        #pragma unroll
        for (int g = 0; g < 8; g++) {
            int r = g * 16 + rB;
            #pragma unroll
            for (int s = 0; s < 4; s++) {
                uint32_t kb[4];
                uint32_t addr = sK + r * 128 + ((((s << 5) + ((mi >> 1) << 4))) ^ ((r & 7) << 4));
                LDSM4(kb, addr);
                MMAF16(facc[2 * g],     aq[s], kb[0], kb[2]);
                MMAF16(facc[2 * g + 1], aq[s], kb[1], kb[3]);
            }
        }
        const float scl = 0.125f;
        #pragma unroll
        for (int f = 0; f < 16; f++) {
            int c0 = f * 8 + 2 * (lane & 3);
            facc[f][0] *= scl; facc[f][1] *= scl;
            facc[f][2] *= scl; facc[f][3] *= scl;
            if (jt == qt) {
                if (c0     > myr0) facc[f][0] = -1e30f;
                if (c0 + 1 > myr0) facc[f][1] = -1e30f;
                if (c0     > myr1) facc[f][2] = -1e30f;
                if (c0 + 1 > myr1) facc[f][3] = -1e30f;
            }
        }
        float m0 = -1e30f, m1 = -1e30f;
        #pragma unroll
        for (int f = 0; f < 16; f++) {
            m0 = fmaxf(m0, fmaxf(facc[f][0], facc[f][1]));
            m1 = fmaxf(m1, fmaxf(facc[f][2], facc[f][3]));
        }
        m0 = fmaxf(m0, __shfl_xor_sync(0xffffffffu, m0, 1));
        m0 = fmaxf(m0, __shfl_xor_sync(0xffffffffu, m0, 2));
        m1 = fmaxf(m1, __shfl_xor_sync(0xffffffffu, m1, 1));
        m1 = fmaxf(m1, __shfl_xor_sync(0xffffffffu, m1, 2));
        float nm0 = fmaxf(mr0, m0), nm1 = fmaxf(mr1, m1);
        float al0 = __expf(mr0 - nm0), al1 = __expf(mr1 - nm1);
        mr0 = nm0; mr1 = nm1;
        #pragma unroll
        for (int f = 0; f < 8; f++) {
            oacc[f][0] *= al0; oacc[f][1] *= al0;
            oacc[f][2] *= al1; oacc[f][3] *= al1;
        }
        float s0 = 0.0f, s1 = 0.0f;
        uint32_t pa[8][4];
        #pragma unroll
        for (int f = 0; f < 16; f++) {
            float p0 = __expf(facc[f][0] - nm0);
            float p1 = __expf(facc[f][1] - nm0);
            float p2 = __expf(facc[f][2] - nm1);
            float p3 = __expf(facc[f][3] - nm1);
            s0 += p0 + p1;
            s1 += p2 + p3;
            __half2 hp = __floats2half2_rn(p0, p1);
            __half2 hq = __floats2half2_rn(p2, p3);
            int ks = f >> 1, half = f & 1;
            pa[ks][2 * half]     = *reinterpret_cast<uint32_t*>(&hp);
            pa[ks][2 * half + 1] = *reinterpret_cast<uint32_t*>(&hq);
        }
        s0 += __shfl_xor_sync(0xffffffffu, s0, 1);
        s0 += __shfl_xor_sync(0xffffffffu, s0, 2);
        s1 += __shfl_xor_sync(0xffffffffu, s1, 1);
        s1 += __shfl_xor_sync(0xffffffffu, s1, 2);
        lr0 = lr0 * al0 + s0;
        lr1 = lr1 * al1 + s1;
        #pragma unroll
        for (int ks = 0; ks < 8; ks++) {
            #pragma unroll
            for (int g2 = 0; g2 < 4; g2++) {
                uint32_t vb[4];
                int r = g2 * 16 + rB;
                uint32_t addr = sV + r * 256 + ((((ks << 5) + ((mi >> 1) << 4))) ^ ((r & 7) << 4));
                LDSM4(vb, addr);
                MMAF16(oacc[2 * g2],     pa[ks], vb[0], vb[2]);
                MMAF16(oacc[2 * g2 + 1], pa[ks], vb[1], vb[3]);
            }
        }
    }

    float inv0 = 1.0f / lr0, inv1 = 1.0f / lr1;
    size_t t0 = (size_t)(tokQ + myr0) * DMODEL + ho;
    size_t t1 = t0 + (size_t)8 * DMODEL;
    #pragma unroll
    for (int f = 0; f < 8; f++) {
        int dc = f * 8 + 2 * (lane & 3);
        __half2 a = __floats2half2_rn(oacc[f][0] * inv0, oacc[f][1] * inv0);
        __half2 b2 = __floats2half2_rn(oacc[f][2] * inv1, oacc[f][3] * inv1);
        *reinterpret_cast<uint32_t*>(cf + t0 + dc) = *reinterpret_cast<uint32_t*>(&a);
        *reinterpret_cast<uint32_t*>(cf + t1 + dc) = *reinterpret_cast<uint32_t*>(&b2);
    }
}

// ---------------- weight transpose (f32 [K,N] -> fp16 [N,K]) ----------------
__device__ __forceinline__ void transpose_f16(const float* __restrict__ in,
        __half* __restrict__ out, int K, int N) {
    __shared__ float t[32][33];
    int n0 = blockIdx.x << 5, k0 = blockIdx.y << 5;
    int tx = threadIdx.x, ty = threadIdx.y;
    #pragma unroll
    for (int r = 0; r < 4; r++)
        t[ty + 8 * r][tx] = in[(size_t)(k0 + ty + 8 * r) * N + n0 + tx];
    __syncthreads();
    #pragma unroll
    for (int r = 0; r < 4; r++)
        out[(size_t)(n0 + ty + 8 * r) * K + k0 + tx] = __float2half_rn(t[tx][ty + 8 * r]);
}
__global__ void wcvt_qkvo_k(const float* __restrict__ Wq, const float* __restrict__ Wk,
                            const float* __restrict__ Wv, const float* __restrict__ Wo,
                            __half* __restrict__ oqkv, __half* __restrict__ oo) {
    int z = blockIdx.z, l = z >> 2, m = z & 3;
    const float* W = (m == 0 ? Wq : m == 1 ? Wk : m == 2 ? Wv : Wo) + (size_t)l * DDSZ;
    __half* dst = (m < 3) ? (oqkv + ((size_t)l * 3 + m) * DDSZ) : (oo + (size_t)l * DDSZ);
    transpose_f16(W, dst, DMODEL, DMODEL);
}
__global__ void wcvt_w1_k(const float* __restrict__ W1, __half* __restrict__ out) {
    int l = blockIdx.z;
    transpose_f16(W1 + (size_t)l * DFSZ, out + (size_t)l * DFSZ, DMODEL, FFDIM);
}
__global__ void wcvt_w2_k(const float* __restrict__ W2, __half* __restrict__ out) {
    int l = blockIdx.z;
    transpose_f16(W2 + (size_t)l * DFSZ, out + (size_t)l * DFSZ, FFDIM, DMODEL);
}

// ---------------- helpers ----------------
__device__ __forceinline__ int detect_i64(const void* p, int n) {
    const long long* x = (const long long*)p;
    int c = n < 32 ? n : 32;
    for (int i = 0; i < c; i++) {
        long long v = x[i];
        if (v < 0 || v >= VOCAB) return 0;
    }
    return 1;
}
__device__ __forceinline__ long long load_index(const void* p, int i, int is64) {
    return is64 ? ((const long long*)p)[i] : (long long)((const int*)p)[i];
}

// ---------------- embedding (+ qkv bias concat + emb fp16 cvt) ----------------
__global__ __launch_bounds__(256) void embed_k(const void* __restrict__ xr,
                                               const float* __restrict__ te,
                                               const float* __restrict__ pe,
                                               float* __restrict__ h,
                                               const float* __restrict__ bq,
                                               const float* __restrict__ bk,
                                               const float* __restrict__ bv,
                                               float* __restrict__ bqkv,
                                               __half* __restrict__ embf) {
    __shared__ int mode;
    if (threadIdx.x == 0) mode = detect_i64(xr, BS);
    __syncthreads();
    int pos = blockIdx.x;
    int tid = threadIdx.x;
    if (pos < NLAYER) {
        #pragma unroll
        for (int t = tid; t < DMODEL; t += 256) {
            bqkv[pos * QKVS + t]        = bq[pos * DMODEL + t];
            bqkv[pos * QKVS + 512 + t]  = bk[pos * DMODEL + t];
            bqkv[pos * QKVS + 1024 + t] = bv[pos * DMODEL + t];
        }
    }
    long long idx = load_index(xr, pos, mode);
    int s = pos & (SEQ - 1);
    const float* t = te + idx * DMODEL;
    const float* p = pe + (long long)s * DMODEL;
    float* o = h + (long long)pos * DMODEL;
    o[tid]       = t[tid]       + p[tid];
    o[tid + 256] = t[tid + 256] + p[tid + 256];
    size_t n4 = (size_t)VOCAB * DMODEL / 4;
    for (size_t i = (size_t)pos * 256 + tid; i < n4; i += (size_t)BS * 256) {
        float4 v = reinterpret_cast<const float4*>(te)[i];
        __half2 a = __floats2half2_rn(v.x, v.y);
        __half2 b = __floats2half2_rn(v.z, v.w);
        uint2 w;
        w.x = *reinterpret_cast<uint32_t*>(&a);
        w.y = *reinterpret_cast<uint32_t*>(&b);
        reinterpret_cast<uint2*>(embf)[i] = w;
    }
}

// ---------------- layernorm: one warp per row (512 elems, 16/lane) ----------------
__global__ __launch_bounds__(256) void ln_k(const float* __restrict__ in,
                                            const float* __restrict__ g,
                                            const float* __restrict__ b,
                                            __half* __restrict__ of) {
    int lane = threadIdx.x & 31, wid = threadIdx.x >> 5;
    int row = blockIdx.x * 8 + wid;
    const float* x = in + (long long)row * DMODEL;
    float4 v[4];
    #pragma unroll
    for (int i = 0; i < 4; i++)
        v[i] = *reinterpret_cast<const float4*>(x + lane * 4 + i * 128);
    float s = 0.0f;
    #pragma unroll
    for (int i = 0; i < 4; i++) s += v[i].x + v[i].y + v[i].z + v[i].w;
    #pragma unroll
    for (int o = 16; o; o >>= 1) s += __shfl_xor_sync(0xffffffffu, s, o);
    float mu = s * (1.0f / DMODEL);
    float q = 0.0f;
    #pragma unroll
    for (int i = 0; i < 4; i++) {
        float d0 = v[i].x - mu, d1 = v[i].y - mu, d2 = v[i].z - mu, d3 = v[i].w - mu;
        q += d0 * d0 + d1 * d1 + d2 * d2 + d3 * d3;
    }
    #pragma unroll
    for (int o = 16; o; o >>= 1) q += __shfl_xor_sync(0xffffffffu, q, o);
    float rstd = rsqrtf(q * (1.0f / DMODEL) + 1e-5f);
    __half* orow = of + (long long)row * DMODEL;
    #pragma unroll
    for (int i = 0; i < 4; i++) {
        int c = lane * 4 + i * 128;
        float4 gg = *reinterpret_cast<const float4*>(g + c);
        float4 bb = *reinterpret_cast<const float4*>(b + c);
        float y0 = (v[i].x - mu) * rstd * gg.x + bb.x;
        float y1 = (v[i].y - mu) * rstd * gg.y + bb.y;
        float y2 = (v[i].z - mu) * rstd * gg.z + bb.z;
        float y3 = (v[i].w - mu) * rstd * gg.w + bb.w;
        __half2 h01 = __floats2half2_rn(y0, y1);
        __half2 h23 = __floats2half2_rn(y2, y3);
        uint2 w;
        w.x = *reinterpret_cast<uint32_t*>(&h01);
        w.y = *reinterpret_cast<uint32_t*>(&h23);
        *reinterpret_cast<uint2*>(orow + c) = w;
    }
}

// ---------------- cross-entropy from fused partials: one warp per row ----------------
__global__ __launch_bounds__(256) void loss_row_k(const float2* __restrict__ part,
                                                  const float* __restrict__ logits,
                                                  const void* __restrict__ tr,
                                                  float* __restrict__ rowloss) {
    __shared__ int mode;
    if (threadIdx.x == 0) mode = detect_i64(tr, BS);
    __syncthreads();
    int lane = threadIdx.x & 31, wid = threadIdx.x >> 5;
    int row = blockIdx.x * 8 + wid;
    const float2* pr = part + (size_t)row * NPART;
    float m = -1e30f, s = 0.0f;
    for (int j = lane; j < NPART; j += 32) {
        float2 p = pr[j];
        float nm = fmaxf(m, p.x);
        s = s * __expf(m - nm) + p.y * __expf(p.x - nm);
        m = nm;
    }
    #pragma unroll
    for (int o = 16; o; o >>= 1) {
        float om = __shfl_xor_sync(0xffffffffu, m, o);
        float os = __shfl_xor_sync(0xffffffffu, s, o);
        float nm = fmaxf(m, om);
        s = s * __expf(m - nm) + os * __expf(om - nm);
        m = nm;
    }
    if (lane == 0) {
        long long t = load_index(tr, row, mode);
        rowloss[row] = -(logits[(size_t)row * VOCAB + t] - m - logf(s));
    }
}

__global__ __launch_bounds__(1024) void loss_reduce_k(const float* __restrict__ rowloss,
                                                      float* __restrict__ out) {
    __shared__ float red[1024];
    int tid = threadIdx.x;
    red[tid] = rowloss[tid] + rowloss[tid + 1024] + rowloss[tid + 2048] + rowloss[tid + 3072];
    __syncthreads();
    #pragma unroll
    for (int s = 512; s > 0; s >>= 1) {
        if (tid < s) red[tid] += red[tid + s];
        __syncthreads();
    }
    if (tid == 0) out[0] = red[0] * (1.0f / BS);
}

// ---------------- host launcher ----------------
extern "C" void kernel_launch(void* const* d_in, const int* in_sizes, int n_in,
                              void* d_out, int out_size) {
    (void)in_sizes; (void)n_in;
    const void*  x       = d_in[0];
    const void*  targets = d_in[1];
    const float* te   = (const float*)d_in[2];
    const float* pe   = (const float*)d_in[3];
    const float* ln1g = (const float*)d_in[4];
    const float* ln1b = (const float*)d_in[5];
    const float* Wq   = (const float*)d_in[6];
    const float* bq   = (const float*)d_in[7];
    const float* Wk   = (const float*)d_in[8];
    const float* bk   = (const float*)d_in[9];
    const float* Wv   = (const float*)d_in[10];
    const float* bv   = (const float*)d_in[11];
    const float* Wo   = (const float*)d_in[12];
    const float* bo   = (const float*)d_in[13];
    const float* ln2g = (const float*)d_in[14];
    const float* ln2b = (const float*)d_in[15];
    const float* W1   = (const float*)d_in[16];
    const float* b1   = (const float*)d_in[17];
    const float* W2   = (const float*)d_in[18];
    const float* b2   = (const float*)d_in[19];
    const float* lnfg = (const float*)d_in[20];
    const float* lnfb = (const float*)d_in[21];
    float* out = (float*)d_out;

    float *p_h, *p_rowloss, *p_logits, *p_bqkv;
    float2* p_part;
    __half *p_xnf, *p_qkvf, *p_ctxf, *p_fff, *p_wqkvf, *p_wof, *p_w1f, *p_w2f, *p_embf;
    cudaGetSymbolAddress((void**)&p_h, g_h);
    cudaGetSymbolAddress((void**)&p_rowloss, g_rowloss);
    cudaGetSymbolAddress((void**)&p_logits, g_logits_scratch);
    cudaGetSymbolAddress((void**)&p_bqkv, g_bqkv);
    cudaGetSymbolAddress((void**)&p_part, g_part);
    cudaGetSymbolAddress((void**)&p_xnf, g_xnf);
    cudaGetSymbolAddress((void**)&p_qkvf, g_qkvf);
    cudaGetSymbolAddress((void**)&p_ctxf, g_ctxf);
    cudaGetSymbolAddress((void**)&p_fff, g_fff);
    cudaGetSymbolAddress((void**)&p_wqkvf, g_wqkvf);
    cudaGetSymbolAddress((void**)&p_wof, g_wof);
    cudaGetSymbolAddress((void**)&p_w1f, g_w1f);
    cudaGetSymbolAddress((void**)&p_w2f, g_w2f);
    cudaGetSymbolAddress((void**)&p_embf, g_embf);

    cudaFuncSetAttribute(gemm_logits, cudaFuncAttributeMaxDynamicSharedMemorySize, GEMM_SMEM_F);
    cudaFuncSetAttribute(gemm_64<1>, cudaFuncAttributeMaxDynamicSharedMemorySize, GEMM_SMEM_64);
    cudaFuncSetAttribute(gemm_64<2>, cudaFuncAttributeMaxDynamicSharedMemorySize, GEMM_SMEM_64);
    cudaFuncSetAttribute(gemm_64<3>, cudaFuncAttributeMaxDynamicSharedMemorySize, GEMM_SMEM_64);
    cudaFuncSetAttribute(fattn_k, cudaFuncAttributeMaxDynamicSharedMemorySize, ATT_SMEM);

    wcvt_qkvo_k<<<dim3(16, 16, NLAYER * 4), dim3(32, 8)>>>(Wq, Wk, Wv, Wo, p_wqkvf, p_wof);
    wcvt_w1_k<<<dim3(64, 16, NLAYER), dim3(32, 8)>>>(W1, p_w1f);
    wcvt_w2_k<<<dim3(16, 64, NLAYER), dim3(32, 8)>>>(W2, p_w2f);
    embed_k<<<BS, 256>>>(x, te, pe, p_h, bq, bk, bv, p_bqkv, p_embf);

    dim3 gDD(BS / 64, DMODEL / 128);
    dim3 gQKV(BS / 64, QKVS / 128);
    dim3 gDF(BS / 64, FFDIM / 128);
    dim3 gATT(BATCH * NHEAD, SEQ / 128);

    for (int l = 0; l < NLAYER; l++) {
        __half* wqkv_l = p_wqkvf + (size_t)l * 3 * DDSZ;
        __half* wof_l = p_wof + (size_t)l * DDSZ;
        __half* w1f_l = p_w1f + (size_t)l * DFSZ;
        __half* w2f_l = p_w2f + (size_t)l * DFSZ;

        ln_k<<<BS / 8, 256>>>(p_h, ln1g + l * DMODEL, ln1b + l * DMODEL, p_xnf);
        gemm_64<3><<<gQKV, 256, GEMM_SMEM_64>>>(p_xnf, wqkv_l, p_bqkv + l * QKVS, nullptr,
                                                nullptr, p_qkvf, BS, QKVS, DMODEL);
        fattn_k<<<gATT, 256, ATT_SMEM>>>(p_qkvf, p_ctxf);
        gemm_64<2><<<gDD, 256, GEMM_SMEM_64>>>(p_ctxf, wof_l, bo + l * DMODEL, p_h,
                                               p_h, nullptr, BS, DMODEL, DMODEL);
        ln_k<<<BS / 8, 256>>>(p_h, ln2g + l * DMODEL, ln2b + l * DMODEL, p_xnf);
        gemm_64<1><<<gDF, 256, GEMM_SMEM_64>>>(p_xnf, w1f_l, b1 + l * FFDIM, nullptr,
                                               nullptr, p_fff, BS, FFDIM, DMODEL);
        gemm_64<2><<<gDD, 256, GEMM_SMEM_64>>>(p_fff, w2f_l, b2 + l * DMODEL, p_h,
                                               p_h, nullptr, BS, DMODEL, FFDIM);
    }

    ln_k<<<BS / 8, 256>>>(p_h, lnfg, lnfb, p_xnf);

    float* logits = ((long long)out_size >= NLOG) ? out : p_logits;
    dim3 gLOG(BS / 128, VPAD / 128);
    gemm_logits<<<gLOG, 256, GEMM_SMEM_F>>>(p_xnf, p_embf, logits, p_part, BS, VOCAB, DMODEL);

    loss_row_k<<<BS / 8, 256>>>(p_part, logits, targets, p_rowloss);
    if ((long long)out_size > NLOG) {
        loss_reduce_k<<<1, 1024>>>(p_rowloss, out + NLOG);
    } else if ((long long)out_size < NLOG && out_size >= 1) {
        loss_reduce_k<<<1, 1024>>>(p_rowloss, out + (out_size - 1));
    }
}

// round 14
// speedup vs baseline: 3.2125x; 1.0274x over previous
#include <cuda_runtime.h>
#include <cuda_bf16.h>
#include <cuda_fp16.h>
#include <math.h>
#include <stdint.h>

// ---------------- model constants ----------------
#define BATCH  8
#define SEQ    512
#define DMODEL 512
#define NHEAD  8
#define HEADD  64
#define FFDIM  2048
#define NLAYER 6
#define VOCAB  50257
#define VPAD   50304                  // 393*128
#define NPART  786
#define BS     (BATCH*SEQ)
#define QKVS   1536
static const long long NLOG = (long long)BS * VOCAB;

#define DDSZ   (DMODEL*DMODEL)
#define DFSZ   (DMODEL*FFDIM)

// ---------------- device scratch ----------------
__device__ float g_h[BS * DMODEL];
__device__ float g_rowloss[BS];
__device__ float g_bqkv[NLAYER * QKVS];
__device__ float g_logits_scratch[(size_t)BS * VOCAB];
__device__ float2 g_part[(size_t)BS * NPART];
__device__ __half g_xnf[BS * DMODEL];
__device__ __half g_qkvf[BS * QKVS];
__device__ __half g_ctxf[BS * DMODEL];
__device__ __half g_fff[BS * FFDIM];
__device__ __half g_wqkvf[(size_t)3 * DDSZ * NLAYER];
__device__ __half g_wof[(size_t)DDSZ * NLAYER];
__device__ __half g_w1f[(size_t)DFSZ * NLAYER];
__device__ __half g_w2f[(size_t)DFSZ * NLAYER];
__device__ __half g_embf[(size_t)VPAD * DMODEL];

// ================= PTX helpers =================
__device__ __forceinline__ uint32_t smem_to_u32(const void* smem_ptr) {
    uint32_t addr;
    asm("{ .reg .u64 tmp; cvta.to.shared.u64 tmp, %1; cvt.u32.u64 %0, tmp; }"
        : "=r"(addr) : "l"(smem_ptr));
    return addr;
}
__device__ __forceinline__ void cp16(uint32_t d, const void* s, int sz) {
    asm volatile("cp.async.cg.shared.global [%0], [%1], 16, %2;\n"
                 :: "r"(d), "l"(s), "r"(sz) : "memory");
}
__device__ __forceinline__ void cp_commit() {
    asm volatile("cp.async.commit_group;\n" ::: "memory");
}
__device__ __forceinline__ void cp_wait0() {
    asm volatile("cp.async.wait_group 0;\n" ::: "memory");
}
__device__ __forceinline__ void cp_wait1() {
    asm volatile("cp.async.wait_group 1;\n" ::: "memory");
}
__device__ __forceinline__ void cp_wait2() {
    asm volatile("cp.async.wait_group 2;\n" ::: "memory");
}
#define LDSM4(r, addr) \
    asm volatile("ldmatrix.sync.aligned.m8n8.x4.shared.b16 {%0,%1,%2,%3}, [%4];" \
        : "=r"((r)[0]), "=r"((r)[1]), "=r"((r)[2]), "=r"((r)[3]) : "r"(addr))
#define LDSM4T(r, addr) \
    asm volatile("ldmatrix.sync.aligned.m8n8.x4.trans.shared.b16 {%0,%1,%2,%3}, [%4];" \
        : "=r"((r)[0]), "=r"((r)[1]), "=r"((r)[2]), "=r"((r)[3]) : "r"(addr))
#define MMAF16(c, a, b0, b1) \
    asm volatile("mma.sync.aligned.m16n8k16.row.col.f32.f16.f16.f32 " \
        "{%0,%1,%2,%3}, {%4,%5,%6,%7}, {%8,%9}, {%0,%1,%2,%3};" \
        : "+f"((c)[0]), "+f"((c)[1]), "+f"((c)[2]), "+f"((c)[3]) \
        : "r"((a)[0]), "r"((a)[1]), "r"((a)[2]), "r"((a)[3]), "r"(b0), "r"(b1))

#define TB 16384
#define SMEM_OFF 1024

// ================= M128 fp16 GEMM (logits: f32 out + CE partials), 3-stage =================
#define FSTAGE (2*TB)
#define GEMM_SMEM_F (SMEM_OFF + 3*FSTAGE)

__device__ __forceinline__ void copy_stage_f(uint32_t st,
        const __half* __restrict__ A, const __half* __restrict__ B,
        int bm, int bn, int k0, int K, int N, int tid) {
    #pragma unroll
    for (int it = 0; it < 4; it++) {
        int idx = tid + it * 256;
        int row = idx >> 3, c = idx & 7;
        uint32_t d = st + row * 128 + ((c ^ (row & 7)) << 4);
        size_t so = (size_t)(bm + row) * K + k0 + c * 8;
        cp16(d, A + so, 16);
    }
    #pragma unroll
    for (int it = 0; it < 4; it++) {
        int idx = tid + it * 256;
        int row = idx >> 3, c = idx & 7;
        int n = bn + row;
        int sz = (n < N) ? 16 : 0;
        uint32_t d = st + TB + row * 128 + ((c ^ (row & 7)) << 4);
        size_t so = (size_t)n * K + k0 + c * 8;
        cp16(d, B + so, sz);
    }
}

__global__ void __launch_bounds__(256, 2)
gemm_logits(const __half* __restrict__ A, const __half* __restrict__ B,
            float* __restrict__ C, float2* __restrict__ part,
            int M, int N, int K) {
    extern __shared__ char smem[];
    const int tid = threadIdx.x;
    const int bm = blockIdx.x * 128;
    const int bn = blockIdx.y * 128;
    const int nc = K >> 6;

    const uint32_t tiles = smem_to_u32(smem) + SMEM_OFF;
    const int lane = tid & 31;
    const int wid = tid >> 5;
    const int wm = (wid & 3) << 5;
    const int wn = (wid >> 2) << 6;
    const int mi = lane >> 3;
    const int lrow = lane & 7;

    float acc[2][8][4];
    #pragma unroll
    for (int i = 0; i < 2; i++)
        #pragma unroll
        for (int j = 0; j < 8; j++)
            #pragma unroll
            for (int t = 0; t < 4; t++) acc[i][j][t] = 0.0f;

    copy_stage_f(tiles, A, B, bm, bn, 0, K, N, tid);
    cp_commit();
    if (nc > 1) {
        copy_stage_f(tiles + FSTAGE, A, B, bm, bn, 64, K, N, tid);
        cp_commit();
    }

    for (int c = 0; c < nc; c++) {
        if (c + 2 < nc) {
            copy_stage_f(tiles + ((c + 2) % 3) * FSTAGE, A, B, bm, bn, (c + 2) << 6, K, N, tid);
            cp_commit();
            cp_wait2();
        } else if (c + 1 < nc) {
            cp_wait1();
        } else {
            cp_wait0();
        }
        __syncthreads();

        const uint32_t st = tiles + (c % 3) * FSTAGE;
        #pragma unroll
        for (int s = 0; s < 4; s++) {
            const int cb = (s << 5) + ((mi >> 1) << 4);
            uint32_t af[2][4], bf[4][4];
            #pragma unroll
            for (int i = 0; i < 2; i++) {
                int r = wm + (i << 4) + ((mi & 1) << 3) + lrow;
                LDSM4(af[i], st + r * 128 + (cb ^ ((r & 7) << 4)));
            }
            #pragma unroll
            for (int j2 = 0; j2 < 4; j2++) {
                int r = wn + (j2 << 4) + ((mi & 1) << 3) + lrow;
                LDSM4(bf[j2], st + TB + r * 128 + (cb ^ ((r & 7) << 4)));
            }
            #pragma unroll
            for (int i = 0; i < 2; i++)
                #pragma unroll
                for (int j2 = 0; j2 < 4; j2++) {
                    MMAF16(acc[i][2 * j2],     af[i], bf[j2][0], bf[j2][2]);
                    MMAF16(acc[i][2 * j2 + 1], af[i], bf[j2][1], bf[j2][3]);
                }
        }
        __syncthreads();
    }

    #pragma unroll
    for (int i = 0; i < 2; i++) {
        #pragma unroll
        for (int hr = 0; hr < 2; hr++) {
            int row = bm + wm + (i << 4) + (lane >> 2) + hr * 8;
            size_t base = (size_t)row * N;
            float pm = -1e30f, ps = 0.0f;
            #pragma unroll
            for (int j = 0; j < 8; j++) {
                #pragma unroll
                for (int u = 0; u < 2; u++) {
                    int cc = bn + wn + (j << 3) + ((lane & 3) << 1) + u;
                    if (cc < N) {
                        float x = acc[i][j][hr * 2 + u];
                        C[base + cc] = x;
                        float nm = fmaxf(pm, x);
                        ps = ps * __expf(pm - nm) + __expf(x - nm);
                        pm = nm;
                    }
                }
            }
            #pragma unroll
            for (int off = 1; off <= 2; off <<= 1) {
                float om = __shfl_xor_sync(0xffffffffu, pm, off);
                float os = __shfl_xor_sync(0xffffffffu, ps, off);
                float nm = fmaxf(pm, om);
                ps = ps * __expf(pm - nm) + os * __expf(om - nm);
                pm = nm;
            }
            if ((lane & 3) == 0)
                part[(size_t)row * NPART + blockIdx.y * 2 + (wid >> 2)] = make_float2(pm, ps);
        }
    }
}

// ================= M64 fp16 GEMM (layer GEMMs), 3-stage, occ 3 =================
#define STAGE64 (8192 + TB)
#define GEMM_SMEM_64 (SMEM_OFF + 3*STAGE64)

__device__ __forceinline__ void copy_stage_64(uint32_t st,
        const __half* __restrict__ A, const __half* __restrict__ B,
        int bm, int bn, int k0, int K, int tid) {
    #pragma unroll
    for (int it = 0; it < 2; it++) {
        int idx = tid + it * 256;
        int row = idx >> 3, c = idx & 7;
        uint32_t d = st + row * 128 + ((c ^ (row & 7)) << 4);
        size_t so = (size_t)(bm + row) * K + k0 + c * 8;
        cp16(d, A + so, 16);
    }
    #pragma unroll
    for (int it = 0; it < 4; it++) {
        int idx = tid + it * 256;
        int row = idx >> 3, c = idx & 7;
        uint32_t d = st + 8192 + row * 128 + ((c ^ (row & 7)) << 4);
        size_t so = (size_t)(bn + row) * K + k0 + c * 8;
        cp16(d, B + so, 16);
    }
}

template <int EPI>
__global__ void __launch_bounds__(256, 3)
gemm_64(const __half* __restrict__ A, const __half* __restrict__ B,
        const float* __restrict__ bias, const float* __restrict__ res,
        float* __restrict__ C, __half* __restrict__ Cf,
        int M, int N, int K) {
    extern __shared__ char smem[];
    const int tid = threadIdx.x;
    const int bm = blockIdx.x * 64;
    const int bn = blockIdx.y * 128;
    const int nc = K >> 6;

    const uint32_t tiles = smem_to_u32(smem) + SMEM_OFF;
    const int lane = tid & 31;
    const int wid = tid >> 5;
    const int wm = (wid & 1) << 5;
    const int wn = (wid >> 1) << 5;
    const int mi = lane >> 3;
    const int lrow = lane & 7;

    float acc[2][4][4];
    #pragma unroll
    for (int i = 0; i < 2; i++)
        #pragma unroll
        for (int j = 0; j < 4; j++)
            #pragma unroll
            for (int t = 0; t < 4; t++) acc[i][j][t] = 0.0f;

    copy_stage_64(tiles, A, B, bm, bn, 0, K, tid);
    cp_commit();
    if (nc > 1) {
        copy_stage_64(tiles + STAGE64, A, B, bm, bn, 64, K, tid);
        cp_commit();
    }

    for (int c = 0; c < nc; c++) {
        if (c + 2 < nc) {
            copy_stage_64(tiles + ((c + 2) % 3) * STAGE64, A, B, bm, bn, (c + 2) << 6, K, tid);
            cp_commit();
            cp_wait2();
        } else if (c + 1 < nc) {
            cp_wait1();
        } else {
            cp_wait0();
        }
        __syncthreads();

        const uint32_t st = tiles + (c % 3) * STAGE64;
        #pragma unroll
        for (int s = 0; s < 4; s++) {
            const int cb = (s << 5) + ((mi >> 1) << 4);
            uint32_t af[2][4], bf[2][4];
            #pragma unroll
            for (int i = 0; i < 2; i++) {
                int r = wm + (i << 4) + ((mi & 1) << 3) + lrow;
                LDSM4(af[i], st + r * 128 + (cb ^ ((r & 7) << 4)));
            }
            #pragma unroll
            for (int j2 = 0; j2 < 2; j2++) {
                int r = wn + (j2 << 4) + ((mi & 1) << 3) + lrow;
                LDSM4(bf[j2], st + 8192 + r * 128 + (cb ^ ((r & 7) << 4)));
            }
            #pragma unroll
            for (int i = 0; i < 2; i++)
                #pragma unroll
                for (int j2 = 0; j2 < 2; j2++) {
                    MMAF16(acc[i][2 * j2],     af[i], bf[j2][0], bf[j2][2]);
                    MMAF16(acc[i][2 * j2 + 1], af[i], bf[j2][1], bf[j2][3]);
                }
        }
        __syncthreads();
    }

    #pragma unroll
    for (int i = 0; i < 2; i++) {
        int row = bm + wm + (i << 4) + (lane >> 2);
        size_t base = (size_t)row * N;
        size_t base8 = base + (size_t)8 * N;
        #pragma unroll
        for (int j = 0; j < 4; j++) {
            int col = bn + wn + (j << 3) + ((lane & 3) << 1);
            float b0 = __ldg(bias + col), b1 = __ldg(bias + col + 1);
            #pragma unroll
            for (int hr = 0; hr < 2; hr++) {
                size_t off = (hr == 0 ? base : base8) + col;
                float x0 = acc[i][j][hr * 2 + 0] + b0;
                float x1 = acc[i][j][hr * 2 + 1] + b1;
                if (EPI == 1) {
                    x0 = 0.5f * x0 * (1.0f + erff(x0 * 0.70710678118654752440f));
                    x1 = 0.5f * x1 * (1.0f + erff(x1 * 0.70710678118654752440f));
                    __half2 hv = __floats2half2_rn(x0, x1);
                    *reinterpret_cast<uint32_t*>(Cf + off) = *reinterpret_cast<uint32_t*>(&hv);
                } else if (EPI == 2) {
                    float2 r2 = *reinterpret_cast<const float2*>(res + off);
                    *reinterpret_cast<float2*>(C + off) = make_float2(x0 + r2.x, x1 + r2.y);
                } else {
                    __half2 hv = __floats2half2_rn(x0, x1);
                    *reinterpret_cast<uint32_t*>(Cf + off) = *reinterpret_cast<uint32_t*>(&hv);
                }
            }
        }
    }
}

// ---------------- flash attention (fp16, trans-LDSM V, double-buffered KV) ----------------
// smem: sQ 16K | KV stage0 (K 16K + V 16K) | KV stage1 (K 16K + V 16K) = 80KB
#define ATT_SMEM (5*16384)
__global__ void __launch_bounds__(256, 1)
fattn_k(const __half* __restrict__ qkv, __half* __restrict__ cf) {
    extern __shared__ char smx[];
    const uint32_t sQ = smem_to_u32(smx);
    const uint32_t sKV0 = sQ + 16384;
    const int tid = threadIdx.x;
    const int lane = tid & 31, wid = tid >> 5;
    const int qt = gridDim.y - 1 - blockIdx.y;
    const int bh = blockIdx.x;
    const int b = bh >> 3, h = bh & 7;
    const int tokQ = b * SEQ + qt * 128;
    const int ho = h * HEADD;
    const int mi = lane >> 3, lrow = lane & 7;
    const int wm = wid * 16;
    const int rB = ((mi & 1) << 3) + lrow;

    // ---- load Q tile (own cp group)
    #pragma unroll
    for (int it = 0; it < 4; it++) {
        int idx = tid + it * 256;
        int r = idx >> 3, c = idx & 7;
        uint32_t d = sQ + r * 128 + ((c ^ (r & 7)) << 4);
        size_t so = (size_t)(tokQ + r) * QKVS + ho + c * 8;
        cp16(d, qkv + so, 16);
    }
    cp_commit();
    cp_wait0();
    __syncthreads();

    uint32_t aq[4][4];
    {
        int r = wm + rB;
        #pragma unroll
        for (int s = 0; s < 4; s++) {
            uint32_t addr = sQ + r * 128 + ((((s << 5) + ((mi >> 1) << 4))) ^ ((r & 7) << 4));
            LDSM4(aq[s], addr);
        }
    }

    // KV tile loader: K rows [j][64d] and V rows [j][64d], both swizzled like GEMM tiles
    auto load_kv = [&](uint32_t stKV, int jt) {
        const int tokJ = b * SEQ + jt * 128;
        #pragma unroll
        for (int it = 0; it < 4; it++) {
            int idx = tid + it * 256;
            int r = idx >> 3, c = idx & 7;
            uint32_t off = r * 128 + ((c ^ (r & 7)) << 4);
            size_t rowb = (size_t)(tokJ + r) * QKVS + ho + c * 8;
            cp16(stKV + off, qkv + rowb + 512, 16);           // K
            cp16(stKV + 16384 + off, qkv + rowb + 1024, 16);  // V
        }
    };

    // preload KV tile 0
    load_kv(sKV0, 0);
    cp_commit();

    float oacc[8][4];
    #pragma unroll
    for (int f = 0; f < 8; f++)
        #pragma unroll
        for (int t = 0; t < 4; t++) oacc[f][t] = 0.0f;
    float mr0 = -1e30f, mr1 = -1e30f, lr0 = 0.0f, lr1 = 0.0f;
    const int myr0 = wm + (lane >> 2);
    const int myr1 = myr0 + 8;

    for (int jt = 0; jt <= qt; jt++) {
        const uint32_t sK = sKV0 + (jt & 1) * 32768;
        const uint32_t sV = sK + 16384;
        if (jt + 1 <= qt) {
            load_kv(sKV0 + ((jt + 1) & 1) * 32768, jt + 1);
            cp_commit();
            cp_wait1();
        } else {
            cp_wait0();
        }
        __syncthreads();

        // ---- S = Q K^T
        float facc[16][4];
        #pragma unroll
        for (int f = 0; f < 16; f++)
            #pragma unroll
            for (int t = 0; t < 4; t++) facc[f][t] = 0.0f;
        #pragma unroll
        for (int g = 0; g < 8; g++) {
            int r = g * 16 + rB;
            #pragma unroll
            for (int s = 0; s < 4; s++) {
                uint32_t kb[4];
                uint32_t addr = sK + r * 128 + ((((s << 5) + ((mi >> 1) << 4))) ^ ((r & 7) << 4));
                LDSM4(kb, addr);
                MMAF16(facc[2 * g],     aq[s], kb[0], kb[2]);
                MMAF16(facc[2 * g + 1], aq[s], kb[1], kb[3]);
            }
        }
        const float scl = 0.125f;
        #pragma unroll
        for (int f = 0; f < 16; f++) {
            int c0 = f * 8 + 2 * (lane & 3);
            facc[f][0] *= scl; facc[f][1] *= scl;
            facc[f][2] *= scl; facc[f][3] *= scl;
            if (jt == qt) {
                if (c0     > myr0) facc[f][0] = -1e30f;
                if (c0 + 1 > myr0) facc[f][1] = -1e30f;
                if (c0     > myr1) facc[f][2] = -1e30f;
                if (c0 + 1 > myr1) facc[f][3] = -1e30f;
            }
        }
        float m0 = -1e30f, m1 = -1e30f;
        #pragma unroll
        for (int f = 0; f < 16; f++) {
            m0 = fmaxf(m0, fmaxf(facc[f][0], facc[f][1]));
            m1 = fmaxf(m1, fmaxf(facc[f][2], facc[f][3]));
        }
        m0 = fmaxf(m0, __shfl_xor_sync(0xffffffffu, m0, 1));
        m0 = fmaxf(m0, __shfl_xor_sync(0xffffffffu, m0, 2));
        m1 = fmaxf(m1, __shfl_xor_sync(0xffffffffu, m1, 1));
        m1 = fmaxf(m1, __shfl_xor_sync(0xffffffffu, m1, 2));
        float nm0 = fmaxf(mr0, m0), nm1 = fmaxf(mr1, m1);
        float al0 = __expf(mr0 - nm0), al1 = __expf(mr1 - nm1);
        mr0 = nm0; mr1 = nm1;
        #pragma unroll
        for (int f = 0; f < 8; f++) {
            oacc[f][0] *= al0; oacc[f][1] *= al0;
            oacc[f][2] *= al1; oacc[f][3] *= al1;
        }
        float s0 = 0.0f, s1 = 0.0f;
        uint32_t pa[8][4];
        #pragma unroll
        for (int f = 0; f < 16; f++) {
            float p0 = __expf(facc[f][0] - nm0);
            float p1 = __expf(facc[f][1] - nm0);
            float p2 = __expf(facc[f][2] - nm1);
            float p3 = __expf(facc[f][3] - nm1);
            s0 += p0 + p1;
            s1 += p2 + p3;
            __half2 hp = __floats2half2_rn(p0, p1);
            __half2 hq = __floats2half2_rn(p2, p3);
            int ks = f >> 1, half = f & 1;
            pa[ks][2 * half]     = *reinterpret_cast<uint32_t*>(&hp);
            pa[ks][2 * half + 1] = *reinterpret_cast<uint32_t*>(&hq);
        }
        s0 += __shfl_xor_sync(0xffffffffu, s0, 1);
        s0 += __shfl_xor_sync(0xffffffffu, s0, 2);
        s1 += __shfl_xor_sync(0xffffffffu, s1, 1);
        s1 += __shfl_xor_sync(0xffffffffu, s1, 2);
        lr0 = lr0 * al0 + s0;
        lr1 = lr1 * al1 + s1;
        // ---- O += P V, B-frags via ldmatrix.trans on [j][d] tile
        // lanes 0-7: rows j0-7 (d low), 8-15: j8-15 (d low), 16-23: j0-7 (d high), 24-31: j8-15 (d high)
        const int trow_off = ((lane >> 3) & 1) * 8 + (lane & 7);
        const int tg_hi = (lane >> 4) & 1;
        #pragma unroll
        for (int ks = 0; ks < 8; ks++) {
            int r = ks * 16 + trow_off;
            #pragma unroll
            for (int g2 = 0; g2 < 4; g2++) {
                uint32_t vb[4];
                int gg = g2 * 2 + tg_hi;
                uint32_t addr = sV + r * 128 + (((uint32_t)(gg ^ (r & 7))) << 4);
                LDSM4T(vb, addr);
                MMAF16(oacc[2 * g2],     pa[ks], vb[0], vb[1]);
                MMAF16(oacc[2 * g2 + 1], pa[ks], vb[2], vb[3]);
            }
        }
        __syncthreads();   // compute on this buffer done before it is refilled (jt+2)
    }

    float inv0 = 1.0f / lr0, inv1 = 1.0f / lr1;
    size_t t0 = (size_t)(tokQ + myr0) * DMODEL + ho;
    size_t t1 = t0 + (size_t)8 * DMODEL;
    #pragma unroll
    for (int f = 0; f < 8; f++) {
        int dc = f * 8 + 2 * (lane & 3);
        __half2 a = __floats2half2_rn(oacc[f][0] * inv0, oacc[f][1] * inv0);
        __half2 b2 = __floats2half2_rn(oacc[f][2] * inv1, oacc[f][3] * inv1);
        *reinterpret_cast<uint32_t*>(cf + t0 + dc) = *reinterpret_cast<uint32_t*>(&a);
        *reinterpret_cast<uint32_t*>(cf + t1 + dc) = *reinterpret_cast<uint32_t*>(&b2);
    }
}

// ---------------- weight transpose (f32 [K,N] -> fp16 [N,K]) ----------------
__device__ __forceinline__ void transpose_f16(const float* __restrict__ in,
        __half* __restrict__ out, int K, int N) {
    __shared__ float t[32][33];
    int n0 = blockIdx.x << 5, k0 = blockIdx.y << 5;
    int tx = threadIdx.x, ty = threadIdx.y;
    #pragma unroll
    for (int r = 0; r < 4; r++)
        t[ty + 8 * r][tx] = in[(size_t)(k0 + ty + 8 * r) * N + n0 + tx];
    __syncthreads();
    #pragma unroll
    for (int r = 0; r < 4; r++)
        out[(size_t)(n0 + ty + 8 * r) * K + k0 + tx] = __float2half_rn(t[tx][ty + 8 * r]);
}
__global__ void wcvt_qkvo_k(const float* __restrict__ Wq, const float* __restrict__ Wk,
                            const float* __restrict__ Wv, const float* __restrict__ Wo,
                            __half* __restrict__ oqkv, __half* __restrict__ oo) {
    int z = blockIdx.z, l = z >> 2, m = z & 3;
    const float* W = (m == 0 ? Wq : m == 1 ? Wk : m == 2 ? Wv : Wo) + (size_t)l * DDSZ;
    __half* dst = (m < 3) ? (oqkv + ((size_t)l * 3 + m) * DDSZ) : (oo + (size_t)l * DDSZ);
    transpose_f16(W, dst, DMODEL, DMODEL);
}
__global__ void wcvt_w1_k(const float* __restrict__ W1, __half* __restrict__ out) {
    int l = blockIdx.z;
    transpose_f16(W1 + (size_t)l * DFSZ, out + (size_t)l * DFSZ, DMODEL, FFDIM);
}
__global__ void wcvt_w2_k(const float* __restrict__ W2, __half* __restrict__ out) {
    int l = blockIdx.z;
    transpose_f16(W2 + (size_t)l * DFSZ, out + (size_t)l * DFSZ, FFDIM, DMODEL);
}

// ---------------- helpers ----------------
__device__ __forceinline__ int detect_i64(const void* p, int n) {
    const long long* x = (const long long*)p;
    int c = n < 32 ? n : 32;
    for (int i = 0; i < c; i++) {
        long long v = x[i];
        if (v < 0 || v >= VOCAB) return 0;
    }
    return 1;
}
__device__ __forceinline__ long long load_index(const void* p, int i, int is64) {
    return is64 ? ((const long long*)p)[i] : (long long)((const int*)p)[i];
}

// ---------------- embedding (+ qkv bias concat + emb fp16 cvt) ----------------
__global__ __launch_bounds__(256) void embed_k(const void* __restrict__ xr,
                                               const float* __restrict__ te,
                                               const float* __restrict__ pe,
                                               float* __restrict__ h,
                                               const float* __restrict__ bq,
                                               const float* __restrict__ bk,
                                               const float* __restrict__ bv,
                                               float* __restrict__ bqkv,
                                               __half* __restrict__ embf) {
    __shared__ int mode;
    if (threadIdx.x == 0) mode = detect_i64(xr, BS);
    __syncthreads();
    int pos = blockIdx.x;
    int tid = threadIdx.x;
    if (pos < NLAYER) {
        #pragma unroll
        for (int t = tid; t < DMODEL; t += 256) {
            bqkv[pos * QKVS + t]        = bq[pos * DMODEL + t];
            bqkv[pos * QKVS + 512 + t]  = bk[pos * DMODEL + t];
            bqkv[pos * QKVS + 1024 + t] = bv[pos * DMODEL + t];
        }
    }
    long long idx = load_index(xr, pos, mode);
    int s = pos & (SEQ - 1);
    const float* t = te + idx * DMODEL;
    const float* p = pe + (long long)s * DMODEL;
    float* o = h + (long long)pos * DMODEL;
    o[tid]       = t[tid]       + p[tid];
    o[tid + 256] = t[tid + 256] + p[tid + 256];
    size_t n4 = (size_t)VOCAB * DMODEL / 4;
    for (size_t i = (size_t)pos * 256 + tid; i < n4; i += (size_t)BS * 256) {
        float4 v = reinterpret_cast<const float4*>(te)[i];
        __half2 a = __floats2half2_rn(v.x, v.y);
        __half2 b = __floats2half2_rn(v.z, v.w);
        uint2 w;
        w.x = *reinterpret_cast<uint32_t*>(&a);
        w.y = *reinterpret_cast<uint32_t*>(&b);
        reinterpret_cast<uint2*>(embf)[i] = w;
    }
}

// ---------------- layernorm: one warp per row ----------------
__global__ __launch_bounds__(256) void ln_k(const float* __restrict__ in,
                                            const float* __restrict__ g,
                                            const float* __restrict__ b,
                                            __half* __restrict__ of) {
    int lane = threadIdx.x & 31, wid = threadIdx.x >> 5;
    int row = blockIdx.x * 8 + wid;
    const float* x = in + (long long)row * DMODEL;
    float4 v[4];
    #pragma unroll
    for (int i = 0; i < 4; i++)
        v[i] = *reinterpret_cast<const float4*>(x + lane * 4 + i * 128);
    float s = 0.0f;
    #pragma unroll
    for (int i = 0; i < 4; i++) s += v[i].x + v[i].y + v[i].z + v[i].w;
    #pragma unroll
    for (int o = 16; o; o >>= 1) s += __shfl_xor_sync(0xffffffffu, s, o);
    float mu = s * (1.0f / DMODEL);
    float q = 0.0f;
    #pragma unroll
    for (int i = 0; i < 4; i++) {
        float d0 = v[i].x - mu, d1 = v[i].y - mu, d2 = v[i].z - mu, d3 = v[i].w - mu;
        q += d0 * d0 + d1 * d1 + d2 * d2 + d3 * d3;
    }
    #pragma unroll
    for (int o = 16; o; o >>= 1) q += __shfl_xor_sync(0xffffffffu, q, o);
    float rstd = rsqrtf(q * (1.0f / DMODEL) + 1e-5f);
    __half* orow = of + (long long)row * DMODEL;
    #pragma unroll
    for (int i = 0; i < 4; i++) {
        int c = lane * 4 + i * 128;
        float4 gg = *reinterpret_cast<const float4*>(g + c);
        float4 bb = *reinterpret_cast<const float4*>(b + c);
        float y0 = (v[i].x - mu) * rstd * gg.x + bb.x;
        float y1 = (v[i].y - mu) * rstd * gg.y + bb.y;
        float y2 = (v[i].z - mu) * rstd * gg.z + bb.z;
        float y3 = (v[i].w - mu) * rstd * gg.w + bb.w;
        __half2 h01 = __floats2half2_rn(y0, y1);
        __half2 h23 = __floats2half2_rn(y2, y3);
        uint2 w;
        w.x = *reinterpret_cast<uint32_t*>(&h01);
        w.y = *reinterpret_cast<uint32_t*>(&h23);
        *reinterpret_cast<uint2*>(orow + c) = w;
    }
}

// ---------------- cross-entropy from fused partials: one warp per row ----------------
__global__ __launch_bounds__(256) void loss_row_k(const float2* __restrict__ part,
                                                  const float* __restrict__ logits,
                                                  const void* __restrict__ tr,
                                                  float* __restrict__ rowloss) {
    __shared__ int mode;
    if (threadIdx.x == 0) mode = detect_i64(tr, BS);
    __syncthreads();
    int lane = threadIdx.x & 31, wid = threadIdx.x >> 5;
    int row = blockIdx.x * 8 + wid;
    const float2* pr = part + (size_t)row * NPART;
    float m = -1e30f, s = 0.0f;
    for (int j = lane; j < NPART; j += 32) {
        float2 p = pr[j];
        float nm = fmaxf(m, p.x);
        s = s * __expf(m - nm) + p.y * __expf(p.x - nm);
        m = nm;
    }
    #pragma unroll
    for (int o = 16; o; o >>= 1) {
        float om = __shfl_xor_sync(0xffffffffu, m, o);
        float os = __shfl_xor_sync(0xffffffffu, s, o);
        float nm = fmaxf(m, om);
        s = s * __expf(m - nm) + os * __expf(om - nm);
        m = nm;
    }
    if (lane == 0) {
        long long t = load_index(tr, row, mode);
        rowloss[row] = -(logits[(size_t)row * VOCAB + t] - m - logf(s));
    }
}

__global__ __launch_bounds__(1024) void loss_reduce_k(const float* __restrict__ rowloss,
                                                      float* __restrict__ out) {
    __shared__ float red[1024];
    int tid = threadIdx.x;
    red[tid] = rowloss[tid] + rowloss[tid + 1024] + rowloss[tid + 2048] + rowloss[tid + 3072];
    __syncthreads();
    #pragma unroll
    for (int s = 512; s > 0; s >>= 1) {
        if (tid < s) red[tid] += red[tid + s];
        __syncthreads();
    }
    if (tid == 0) out[0] = red[0] * (1.0f / BS);
}

// ---------------- host launcher ----------------
extern "C" void kernel_launch(void* const* d_in, const int* in_sizes, int n_in,
                              void* d_out, int out_size) {
    (void)in_sizes; (void)n_in;
    const void*  x       = d_in[0];
    const void*  targets = d_in[1];
    const float* te   = (const float*)d_in[2];
    const float* pe   = (const float*)d_in[3];
    const float* ln1g = (const float*)d_in[4];
    const float* ln1b = (const float*)d_in[5];
    const float* Wq   = (const float*)d_in[6];
    const float* bq   = (const float*)d_in[7];
    const float* Wk   = (const float*)d_in[8];
    const float* bk   = (const float*)d_in[9];
    const float* Wv   = (const float*)d_in[10];
    const float* bv   = (const float*)d_in[11];
    const float* Wo   = (const float*)d_in[12];
    const float* bo   = (const float*)d_in[13];
    const float* ln2g = (const float*)d_in[14];
    const float* ln2b = (const float*)d_in[15];
    const float* W1   = (const float*)d_in[16];
    const float* b1   = (const float*)d_in[17];
    const float* W2   = (const float*)d_in[18];
    const float* b2   = (const float*)d_in[19];
    const float* lnfg = (const float*)d_in[20];
    const float* lnfb = (const float*)d_in[21];
    float* out = (float*)d_out;

    float *p_h, *p_rowloss, *p_logits, *p_bqkv;
    float2* p_part;
    __half *p_xnf, *p_qkvf, *p_ctxf, *p_fff, *p_wqkvf, *p_wof, *p_w1f, *p_w2f, *p_embf;
    cudaGetSymbolAddress((void**)&p_h, g_h);
    cudaGetSymbolAddress((void**)&p_rowloss, g_rowloss);
    cudaGetSymbolAddress((void**)&p_logits, g_logits_scratch);
    cudaGetSymbolAddress((void**)&p_bqkv, g_bqkv);
    cudaGetSymbolAddress((void**)&p_part, g_part);
    cudaGetSymbolAddress((void**)&p_xnf, g_xnf);
    cudaGetSymbolAddress((void**)&p_qkvf, g_qkvf);
    cudaGetSymbolAddress((void**)&p_ctxf, g_ctxf);
    cudaGetSymbolAddress((void**)&p_fff, g_fff);
    cudaGetSymbolAddress((void**)&p_wqkvf, g_wqkvf);
    cudaGetSymbolAddress((void**)&p_wof, g_wof);
    cudaGetSymbolAddress((void**)&p_w1f, g_w1f);
    cudaGetSymbolAddress((void**)&p_w2f, g_w2f);
    cudaGetSymbolAddress((void**)&p_embf, g_embf);

    cudaFuncSetAttribute(gemm_logits, cudaFuncAttributeMaxDynamicSharedMemorySize, GEMM_SMEM_F);
    cudaFuncSetAttribute(gemm_64<1>, cudaFuncAttributeMaxDynamicSharedMemorySize, GEMM_SMEM_64);
    cudaFuncSetAttribute(gemm_64<2>, cudaFuncAttributeMaxDynamicSharedMemorySize, GEMM_SMEM_64);
    cudaFuncSetAttribute(gemm_64<3>, cudaFuncAttributeMaxDynamicSharedMemorySize, GEMM_SMEM_64);
    cudaFuncSetAttribute(fattn_k, cudaFuncAttributeMaxDynamicSharedMemorySize, ATT_SMEM);

    wcvt_qkvo_k<<<dim3(16, 16, NLAYER * 4), dim3(32, 8)>>>(Wq, Wk, Wv, Wo, p_wqkvf, p_wof);
    wcvt_w1_k<<<dim3(64, 16, NLAYER), dim3(32, 8)>>>(W1, p_w1f);
    wcvt_w2_k<<<dim3(16, 64, NLAYER), dim3(32, 8)>>>(W2, p_w2f);
    embed_k<<<BS, 256>>>(x, te, pe, p_h, bq, bk, bv, p_bqkv, p_embf);

    dim3 gDD(BS / 64, DMODEL / 128);
    dim3 gQKV(BS / 64, QKVS / 128);
    dim3 gDF(BS / 64, FFDIM / 128);
    dim3 gATT(BATCH * NHEAD, SEQ / 128);

    for (int l = 0; l < NLAYER; l++) {
        __half* wqkv_l = p_wqkvf + (size_t)l * 3 * DDSZ;
        __half* wof_l = p_wof + (size_t)l * DDSZ;
        __half* w1f_l = p_w1f + (size_t)l * DFSZ;
        __half* w2f_l = p_w2f + (size_t)l * DFSZ;

        ln_k<<<BS / 8, 256>>>(p_h, ln1g + l * DMODEL, ln1b + l * DMODEL, p_xnf);
        gemm_64<3><<<gQKV, 256, GEMM_SMEM_64>>>(p_xnf, wqkv_l, p_bqkv + l * QKVS, nullptr,
                                                nullptr, p_qkvf, BS, QKVS, DMODEL);
        fattn_k<<<gATT, 256, ATT_SMEM>>>(p_qkvf, p_ctxf);
        gemm_64<2><<<gDD, 256, GEMM_SMEM_64>>>(p_ctxf, wof_l, bo + l * DMODEL, p_h,
                                               p_h, nullptr, BS, DMODEL, DMODEL);
        ln_k<<<BS / 8, 256>>>(p_h, ln2g + l * DMODEL, ln2b + l * DMODEL, p_xnf);
        gemm_64<1><<<gDF, 256, GEMM_SMEM_64>>>(p_xnf, w1f_l, b1 + l * FFDIM, nullptr,
                                               nullptr, p_fff, BS, FFDIM, DMODEL);
        gemm_64<2><<<gDD, 256, GEMM_SMEM_64>>>(p_fff, w2f_l, b2 + l * DMODEL, p_h,
                                               p_h, nullptr, BS, DMODEL, FFDIM);
    }

    ln_k<<<BS / 8, 256>>>(p_h, lnfg, lnfb, p_xnf);

    float* logits = ((long long)out_size >= NLOG) ? out : p_logits;
    dim3 gLOG(BS / 128, VPAD / 128);
    gemm_logits<<<gLOG, 256, GEMM_SMEM_F>>>(p_xnf, p_embf, logits, p_part, BS, VOCAB, DMODEL);

    loss_row_k<<<BS / 8, 256>>>(p_part, logits, targets, p_rowloss);
    if ((long long)out_size > NLOG) {
        loss_reduce_k<<<1, 1024>>>(p_rowloss, out + NLOG);
    } else if ((long long)out_size < NLOG && out_size >= 1) {
        loss_reduce_k<<<1, 1024>>>(p_rowloss, out + (out_size - 1));
    }
}